// round 10
// baseline (speedup 1.0000x reference)
#include <cuda_runtime.h>
#include <cuda_bf16.h>
#include <math.h>

// Problem: V=32000, H=512, TS=TT=48, B=64, PAD=0
// Output: logits (48,64,32000) f32

#define NTB (48*64)            // 3072 time-batch rows
#define NBLK 96                // persistent grid size (<=148 SMs -> all resident)

// ---------------- scratch (static device globals; no allocation) -------------
__device__ __align__(256) float g_src_emb[NTB*512];
__device__ __align__(256) float g_tgt_emb[NTB*512];
__device__ __align__(256) float g_xp0[NTB*1536];
__device__ __align__(256) float g_l0 [NTB*1024];
__device__ __align__(256) float g_xp1[NTB*1536];
__device__ __align__(256) float g_henc[NTB*1024];
__device__ __align__(256) float g_hw [NTB*512];
__device__ __align__(256) float g_xpx[NTB*1536];
__device__ __align__(256) float g_hts[NTB*512];
__device__ __align__(256) float g_uc0[1536*512];
__device__ __align__(256) float g_uc1[1536*512];
__device__ __align__(256) float g_dw [3072*512];   // [WihH(1536); dUr;dUz;dUn]
__device__ __align__(256) float g_wat[512*1024];   // Wa transposed (n,k)
__device__ __align__(256) float g_est[128*512];    // enc state: rows0-63 fwd, 64-127 bwd
__device__ __align__(256) float g_dst[128*512];    // dec state: rows0-63 ht, 64-127 h
__device__ __align__(256) float g_hfhb[64*1024];
__device__ __align__(256) float g_P [128*1536];    // encoder per-step U-projections
__device__ __align__(256) float g_G [128*1536];    // decoder: rows0-63 ht@WihH^T, 64-127 h@Ucat^T
__device__ __align__(256) float g_cc[64*1536];     // [h | ctx]
__device__ __align__(256) float g_cp[6*64*512];    // split-K partials for combine
__device__ unsigned g_barc[4];                     // grid-barrier counters

// ---------------- helpers ----------------------------------------------------
__device__ __forceinline__ unsigned long long fma2(unsigned long long a,
                                                   unsigned long long b,
                                                   unsigned long long c){
  unsigned long long d;
  asm("fma.rn.f32x2 %0, %1, %2, %3;" : "=l"(d) : "l"(a), "l"(b), "l"(c));
  return d;
}
__device__ __forceinline__ unsigned long long pack2(float x, float y){
  unsigned long long d;
  asm("mov.b64 %0, {%1, %2};" : "=l"(d) : "f"(x), "f"(y));
  return d;
}
__device__ __forceinline__ float2 unpack2(unsigned long long v){
  float2 r;
  asm("mov.b64 {%0, %1}, %2;" : "=f"(r.x), "=f"(r.y) : "l"(v));
  return r;
}
__device__ __forceinline__ float sigmf(float x){ return 1.f/(1.f+__expf(-x)); }

// grid barrier: release fence -> arrive -> spin -> acquire fence (CCTL.IVALL
// from gpu-scope membar invalidates this SM's L1D so post-barrier loads are fresh)
__device__ __forceinline__ void gbar(unsigned* cnt, unsigned target){
  __syncthreads();
  if (threadIdx.x == 0){
    __threadfence();
    atomicAdd(cnt, 1u);
    volatile unsigned* vc = (volatile unsigned*)cnt;
    while (*vc < target) {}
    __threadfence();
  }
  __syncthreads();
}

// ---------------- 64x32 tile GEMM (f32x2 FFMA), used inside persistent scans -
// C[cm0+0..63][cn0..cn0+31] = A[m0+0..63][kstart..kstart+K) @ W[wrow0..+31][...]^T
__device__ __forceinline__ void tile64x32(
    float (*As)[68], float (*Bs)[36],
    const float* __restrict__ A, int lda, int m0,
    const float* __restrict__ W, int ldw, int wrow0,
    int kstart, int K,
    float* __restrict__ C, int ldc, int cm0, int cn0)
{
  int t = threadIdx.x;
  int ar = t & 63, ak = (t >> 6) << 2;
  int wr = t & 31, wk = ((t & 127) >> 5) << 2;
  const float* Ap = A + (size_t)(m0 + ar)*lda + kstart + ak;
  const float* Wp = W + (size_t)(wrow0 + wr)*ldw + kstart + wk;
  int cm = (t >> 4) << 2, cn = (t & 15) << 1;
  unsigned long long a00=0ull, a01=0ull, a10=0ull, a11=0ull;
  for (int k0 = 0; k0 < K; k0 += 16){
    float4 av = *(const float4*)(Ap + k0);
    float4 wv = make_float4(0.f,0.f,0.f,0.f);
    if (t < 128) wv = *(const float4*)(Wp + k0);
    __syncthreads();
    As[ak+0][ar]=av.x; As[ak+1][ar]=av.y; As[ak+2][ar]=av.z; As[ak+3][ar]=av.w;
    if (t < 128){ Bs[wk+0][wr]=wv.x; Bs[wk+1][wr]=wv.y; Bs[wk+2][wr]=wv.z; Bs[wk+3][wr]=wv.w; }
    __syncthreads();
#pragma unroll
    for (int kk = 0; kk < 16; kk++){
      float4 af = *(const float4*)&As[kk][cm];
      float2 bf = *(const float2*)&Bs[kk][cn];
      unsigned long long ap0 = pack2(af.x, af.y);
      unsigned long long ap1 = pack2(af.z, af.w);
      unsigned long long b0  = pack2(bf.x, bf.x);
      unsigned long long b1  = pack2(bf.y, bf.y);
      a00 = fma2(ap0, b0, a00); a10 = fma2(ap1, b0, a10);
      a01 = fma2(ap0, b1, a01); a11 = fma2(ap1, b1, a11);
    }
  }
  float2 v;
  v = unpack2(a00); C[(size_t)(cm0+cm+0)*ldc + cn0+cn]   = v.x; C[(size_t)(cm0+cm+1)*ldc + cn0+cn]   = v.y;
  v = unpack2(a10); C[(size_t)(cm0+cm+2)*ldc + cn0+cn]   = v.x; C[(size_t)(cm0+cm+3)*ldc + cn0+cn]   = v.y;
  v = unpack2(a01); C[(size_t)(cm0+cm+0)*ldc + cn0+cn+1] = v.x; C[(size_t)(cm0+cm+1)*ldc + cn0+cn+1] = v.y;
  v = unpack2(a11); C[(size_t)(cm0+cm+2)*ldc + cn0+cn+1] = v.x; C[(size_t)(cm0+cm+3)*ldc + cn0+cn+1] = v.y;
}

// ---------------- embedding gather -------------------------------------------
__global__ void k_gather(const int* __restrict__ src, const int* __restrict__ tgt,
                         const float* __restrict__ emb,
                         float* __restrict__ se, float* __restrict__ te){
  int idx = blockIdx.x;                 // 0..6143
  int is_src = idx < NTB;
  int i = is_src ? idx : idx - NTB;
  int token = is_src ? src[i] : tgt[i];
  const float4* erow = (const float4*)(emb + (size_t)token*512);
  float4* orow = (float4*)((is_src ? se : te) + (size_t)i*512);
  orow[threadIdx.x] = erow[threadIdx.x];
}

// ---------------- weight prep (+ barrier counter reset) ----------------------
__global__ void k_prep(const float* e0Ur, const float* e0Uz, const float* e0Un,
                       const float* e1Ur, const float* e1Uz, const float* e1Un,
                       const float* dUr, const float* dUz, const float* dUn,
                       const float* dWih, const float* Wa,
                       float* uc0, float* uc1, float* dw, float* wat){
  if (blockIdx.x == 0 && threadIdx.x < 4) g_barc[threadIdx.x] = 0u;
  const int n1 = 1536*512;
  const int n2 = 3072*512;
  const int n3 = 512*1024;
  int total = 2*n1 + n2 + n3;
  for (int i = blockIdx.x*blockDim.x + threadIdx.x; i < total;
       i += gridDim.x*blockDim.x){
    if (i < n1){
      int g = i / 262144, r = i % 262144;
      uc0[i] = g==0 ? e0Ur[r] : (g==1 ? e0Uz[r] : e0Un[r]);
    } else if (i < 2*n1){
      int j = i - n1; int g = j / 262144, r = j % 262144;
      uc1[j] = g==0 ? e1Ur[r] : (g==1 ? e1Uz[r] : e1Un[r]);
    } else if (i < 2*n1 + n2){
      int j = i - 2*n1; int row = j >> 9, k = j & 511;
      float v;
      if      (row < 1536) v = dWih[(size_t)row*1024 + 512 + k];
      else if (row < 2048) v = dUr[(row-1536)*512 + k];
      else if (row < 2560) v = dUz[(row-2048)*512 + k];
      else                 v = dUn[(row-2560)*512 + k];
      dw[j] = v;
    } else {
      int j = i - 2*n1 - n2; int nn = j >> 10, k = j & 1023;
      wat[j] = Wa[(size_t)k*512 + nn];
    }
  }
}

// ---------------- big GEMM: C(MxN) = act(scale*A@W^T + bias) -----------------
__global__ __launch_bounds__(256) void k_gemm_big(
    const float* __restrict__ A, int lda,
    const float* __restrict__ W, int ldw,
    const float* __restrict__ bias,
    float* __restrict__ C, int ldc,
    int K, float scale, int act)
{
  __shared__ __align__(16) float As[16][136];
  __shared__ __align__(16) float Bs[16][136];
  int t = threadIdx.x;
  int m0 = blockIdx.y * 128, n0 = blockIdx.x * 128;
  int ar = t >> 1, ak = (t & 1) * 8;
  const float* Ap = A + (size_t)(m0 + ar)*lda + ak;
  const float* Wp = W + (size_t)(n0 + ar)*ldw + ak;
  int tx = t & 15, ty = t >> 4;
  int cm = ty * 8, cn = tx * 8;
  unsigned long long acc[8][4];
#pragma unroll
  for (int i=0;i<8;i++)
#pragma unroll
    for (int j=0;j<4;j++) acc[i][j] = 0ull;

  for (int k0 = 0; k0 < K; k0 += 16){
    float4 a0 = *(const float4*)(Ap + k0);
    float4 a1 = *(const float4*)(Ap + k0 + 4);
    float4 w0 = *(const float4*)(Wp + k0);
    float4 w1 = *(const float4*)(Wp + k0 + 4);
    __syncthreads();
    As[ak+0][ar]=a0.x; As[ak+1][ar]=a0.y; As[ak+2][ar]=a0.z; As[ak+3][ar]=a0.w;
    As[ak+4][ar]=a1.x; As[ak+5][ar]=a1.y; As[ak+6][ar]=a1.z; As[ak+7][ar]=a1.w;
    Bs[ak+0][ar]=w0.x; Bs[ak+1][ar]=w0.y; Bs[ak+2][ar]=w0.z; Bs[ak+3][ar]=w0.w;
    Bs[ak+4][ar]=w1.x; Bs[ak+5][ar]=w1.y; Bs[ak+6][ar]=w1.z; Bs[ak+7][ar]=w1.w;
    __syncthreads();
#pragma unroll
    for (int kk=0; kk<16; kk++){
      float4 af0 = *(const float4*)&As[kk][cm];
      float4 af1 = *(const float4*)&As[kk][cm+4];
      float4 bf0 = *(const float4*)&Bs[kk][cn];
      float4 bf1 = *(const float4*)&Bs[kk][cn+4];
      unsigned long long bp0 = pack2(bf0.x, bf0.y);
      unsigned long long bp1 = pack2(bf0.z, bf0.w);
      unsigned long long bp2 = pack2(bf1.x, bf1.y);
      unsigned long long bp3 = pack2(bf1.z, bf1.w);
      float am[8] = {af0.x,af0.y,af0.z,af0.w,af1.x,af1.y,af1.z,af1.w};
#pragma unroll
      for (int i=0;i<8;i++){
        unsigned long long ap = pack2(am[i], am[i]);
        acc[i][0] = fma2(ap, bp0, acc[i][0]);
        acc[i][1] = fma2(ap, bp1, acc[i][1]);
        acc[i][2] = fma2(ap, bp2, acc[i][2]);
        acc[i][3] = fma2(ap, bp3, acc[i][3]);
      }
    }
  }
#pragma unroll
  for (int i=0;i<8;i++){
    float* crow = C + (size_t)(m0+cm+i)*ldc + n0 + cn;
#pragma unroll
    for (int j=0;j<4;j++){
      float2 v = unpack2(acc[i][j]);
      float x0 = v.x*scale, x1 = v.y*scale;
      if (bias){ x0 += bias[n0+cn+2*j]; x1 += bias[n0+cn+2*j+1]; }
      if (act){ x0 = tanhf(x0); x1 = tanhf(x1); }
      *(float2*)(crow + 2*j) = make_float2(x0, x1);
    }
  }
}

// ---------------- small standalone GEMM (decoder h0 init only) ---------------
__global__ __launch_bounds__(256) void k_gemm_small(
    const float* __restrict__ A, int lda,
    const float* __restrict__ W, int ldw,
    const float* __restrict__ bias,
    float* __restrict__ C, int ldc, int K, int act)
{
  __shared__ __align__(16) float As[16][68];
  __shared__ __align__(16) float Bs[16][36];
  int t = threadIdx.x;
  int n0 = blockIdx.x * 32;
  int ar = t & 63, ak = (t >> 6) << 2;
  int wr = t & 31, wk = ((t & 127) >> 5) << 2;
  const float* Ap = A + (size_t)ar*lda + ak;
  const float* Wp = W + (size_t)(n0 + wr)*ldw + wk;
  int tx = t & 15, ty = t >> 4;
  int cm = ty * 4, cn = tx * 2;
  float acc[4][2] = {{0.f,0.f},{0.f,0.f},{0.f,0.f},{0.f,0.f}};
  for (int k0 = 0; k0 < K; k0 += 16){
    float4 av = *(const float4*)(Ap + k0);
    float4 wv = make_float4(0.f,0.f,0.f,0.f);
    if (t < 128) wv = *(const float4*)(Wp + k0);
    __syncthreads();
    As[ak+0][ar]=av.x; As[ak+1][ar]=av.y; As[ak+2][ar]=av.z; As[ak+3][ar]=av.w;
    if (t < 128){ Bs[wk+0][wr]=wv.x; Bs[wk+1][wr]=wv.y; Bs[wk+2][wr]=wv.z; Bs[wk+3][wr]=wv.w; }
    __syncthreads();
#pragma unroll
    for (int kk=0; kk<16; kk++){
      float4 af = *(const float4*)&As[kk][cm];
      float2 bf = *(const float2*)&Bs[kk][cn];
      acc[0][0] += af.x*bf.x; acc[0][1] += af.x*bf.y;
      acc[1][0] += af.y*bf.x; acc[1][1] += af.y*bf.y;
      acc[2][0] += af.z*bf.x; acc[2][1] += af.z*bf.y;
      acc[3][0] += af.w*bf.x; acc[3][1] += af.w*bf.y;
    }
  }
#pragma unroll
  for (int i=0;i<4;i++)
#pragma unroll
    for (int j=0;j<2;j++){
      float v = acc[i][j];
      if (bias) v += bias[n0+cn+j];
      if (act) v = tanhf(v);
      C[(size_t)(cm+i)*ldc + n0 + cn + j] = v;
    }
}

// ---------------- hf|hb concat -----------------------------------------------
__global__ void k_hfhb(const float* __restrict__ est, float* __restrict__ hfhb){
  int i = blockIdx.x*blockDim.x + threadIdx.x;   // 65536
  int b = i >> 10, k = i & 1023;
  hfhb[i] = (k < 512) ? est[b*512 + k] : est[(64 + b)*512 + (k - 512)];
}

// ---------------- persistent encoder scan (one launch per biGRU layer) -------
__global__ __launch_bounds__(256) void k_enc_scan(
    const float* __restrict__ xp, const float* __restrict__ uc,
    const float* __restrict__ bn, float* __restrict__ est,
    float* __restrict__ out, unsigned* __restrict__ bar)
{
  __shared__ __align__(16) float As[16][68];
  __shared__ __align__(16) float Bs[16][36];
  int bx = blockIdx.x, t = threadIdx.x;
  unsigned nb = 0;
  float* P = g_P;
  for (int i = bx*256 + t; i < 65536; i += NBLK*256) est[i] = 0.f;
  nb += NBLK; gbar(bar, nb);
  int m0 = (bx & 1) * 64, n0 = (bx >> 1) * 32;
  for (int step = 0; step < 48; step++){
    // phase A: P(128x1536) = est(128x512) @ uc(1536x512)^T
    tile64x32(As, Bs, est, 512, m0, uc, 512, n0, 0, 512, P, 1536, m0, n0);
    nb += NBLK; gbar(bar, nb);
    // phase B: elementwise GRU update (both directions)
    for (int i = bx*256 + t; i < 65536; i += NBLK*256){
      int r = i >> 9, j = i & 511;
      int b = r & 63, fwd = (r < 64);
      int tpos = fwd ? step : 47 - step;
      const float* xrow = xp + ((size_t)tpos*64 + b)*1536;
      const float* prow = P + (size_t)r*1536;
      float h  = est[i];
      float rg = sigmf(xrow[j]       + prow[j]);
      float zg = sigmf(xrow[512 + j] + prow[512 + j]);
      float ng = tanhf(xrow[1024+ j] + rg*(prow[1024 + j] + bn[j]));
      float hn = (1.f - zg)*ng + zg*h;
      est[i] = hn;
      out[((size_t)tpos*64 + b)*1024 + (fwd ? 0 : 512) + j] = hn;
    }
    nb += NBLK; gbar(bar, nb);
  }
}

// ---------------- persistent decoder scan (one launch, 48 steps) -------------
__global__ __launch_bounds__(256) void k_dec_scan(
    const float* __restrict__ xpx, const float* __restrict__ dw,
    const float* __restrict__ bn, float* __restrict__ dst,
    const float* __restrict__ hw, const float* __restrict__ henc,
    const int* __restrict__ src, const float* __restrict__ acw,
    float* __restrict__ hts, unsigned* __restrict__ bar)
{
  __shared__ __align__(16) float As[16][68];
  __shared__ __align__(16) float Bs[16][36];
  __shared__ float hsm[512];
  __shared__ float ssm[48];
  __shared__ float sinv;
  int bx = blockIdx.x, t = threadIdx.x;
  unsigned nb = 0;
  float* G = g_G; float* cc = g_cc; float* cp = g_cp;
  for (int i = bx*256 + t; i < 32768; i += NBLK*256) dst[i] = 0.f;  // ht0 = 0
  nb += NBLK; gbar(bar, nb);
  int gA = bx & 1, nA = (bx >> 1) * 32;        // phase A tile
  int ksC = bx / 16, nC = (bx & 15) * 32;      // phase C tile (6 k-splits x 16 n-tiles)
  for (int step = 0; step < 48; step++){
    // A: G = [ht@WihH^T ; h@Ucat^T]  (128x1536)
    tile64x32(As, Bs, dst, 512, gA*64, dw, 512, gA*1536 + nA, 0, 512,
              G, 1536, gA*64, nA);
    nb += NBLK; gbar(bar, nb);
    // B: GRU elementwise + attention (blocks 0..63 each own one batch b)
    if (bx < 64){
      int b = bx;
      const float* xrow = xpx + ((size_t)step*64 + b)*1536;
      const float* g0 = G + (size_t)b*1536;
      const float* g1 = G + (size_t)(64 + b)*1536;
      for (int j = t; j < 512; j += 256){
        float rg = sigmf(xrow[j]        + g0[j]        + g1[j]);
        float zg = sigmf(xrow[512 + j]  + g0[512 + j]  + g1[512 + j]);
        float ng = tanhf(xrow[1024 + j] + g0[1024 + j] + rg*(g1[1024 + j] + bn[j]));
        float h  = dst[(size_t)(64 + b)*512 + j];
        float hn = (1.f - zg)*ng + zg*h;
        dst[(size_t)(64 + b)*512 + j] = hn;
        hsm[j] = hn;
        cc[(size_t)b*1536 + j] = hn;
      }
      __syncthreads();
      int w = t >> 5, lane = t & 31;
      for (int tp = w; tp < 48; tp += 8){
        const float* hwrow = hw + ((size_t)tp*64 + b)*512;
        float s = 0.f;
        for (int j = lane; j < 512; j += 32) s += hsm[j]*hwrow[j];
#pragma unroll
        for (int o = 16; o; o >>= 1) s += __shfl_xor_sync(0xffffffffu, s, o);
        if (lane == 0) ssm[tp] = (src[tp*64 + b] == 0) ? -1e9f : s;
      }
      __syncthreads();
      if (t == 0){
        float mx = -1e30f;
        for (int i2 = 0; i2 < 48; i2++) mx = fmaxf(mx, ssm[i2]);
        float sum = 0.f;
        for (int i2 = 0; i2 < 48; i2++){ float e = __expf(ssm[i2]-mx); ssm[i2]=e; sum+=e; }
        sinv = 1.f/sum;
      }
      __syncthreads();
      for (int d = t; d < 1024; d += 256){
        float accv = 0.f;
#pragma unroll 4
        for (int tp = 0; tp < 48; tp++)
          accv += ssm[tp]*henc[((size_t)tp*64 + b)*1024 + d];
        cc[(size_t)b*1536 + 512 + d] = accv*sinv;
      }
    }
    nb += NBLK; gbar(bar, nb);
    // C: combine partials: cc(64x1536) @ acw(512x1536)^T, split-K 6x256
    tile64x32(As, Bs, cc, 1536, 0, acw, 1536, nC, ksC*256, 256,
              cp + (size_t)ksC*32768, 512, 0, nC);
    nb += NBLK; gbar(bar, nb);
    // D: reduce 6 partials + tanh -> ht, Hts[step]
    for (int i = bx*256 + t; i < 32768; i += NBLK*256){
      float v = cp[i] + cp[32768+i] + cp[2*32768+i] + cp[3*32768+i]
              + cp[4*32768+i] + cp[5*32768+i];
      v = tanhf(v);
      dst[i] = v;
      hts[(size_t)step*32768 + i] = v;
    }
    nb += NBLK; gbar(bar, nb);
  }
}

// =============================================================================
extern "C" void kernel_launch(void* const* d_in, const int* in_sizes, int n_in,
                              void* d_out, int out_size){
  const int*   src  = (const int*)  d_in[0];
  const int*   tgt  = (const int*)  d_in[1];
  const float* emb  = (const float*)d_in[2];
  const float* e0Wih=(const float*)d_in[3];  const float* e0bih=(const float*)d_in[4];
  const float* e0Ur =(const float*)d_in[5];  const float* e0Uz =(const float*)d_in[6];
  const float* e0Un =(const float*)d_in[7];  const float* e0bn =(const float*)d_in[8];
  const float* e1Wih=(const float*)d_in[9];  const float* e1bih=(const float*)d_in[10];
  const float* e1Ur =(const float*)d_in[11]; const float* e1Uz =(const float*)d_in[12];
  const float* e1Un =(const float*)d_in[13]; const float* e1bn =(const float*)d_in[14];
  const float* fcw  =(const float*)d_in[15]; const float* fcb  =(const float*)d_in[16];
  const float* Wa   =(const float*)d_in[17]; const float* acw  =(const float*)d_in[18];
  const float* dWih =(const float*)d_in[19]; const float* dbih =(const float*)d_in[20];
  const float* dUr  =(const float*)d_in[21]; const float* dUz  =(const float*)d_in[22];
  const float* dUn  =(const float*)d_in[23]; const float* dbn  =(const float*)d_in[24];
  const float* outw =(const float*)d_in[25];
  float* out = (float*)d_out;

  float *se,*te,*xp0,*l0,*xp1,*henc,*hw,*xpx,*hts,*uc0,*uc1,*dw,*wat,*est,*dst,*hfhb;
  unsigned* bc;
  cudaGetSymbolAddress((void**)&se,  g_src_emb);
  cudaGetSymbolAddress((void**)&te,  g_tgt_emb);
  cudaGetSymbolAddress((void**)&xp0, g_xp0);
  cudaGetSymbolAddress((void**)&l0,  g_l0);
  cudaGetSymbolAddress((void**)&xp1, g_xp1);
  cudaGetSymbolAddress((void**)&henc,g_henc);
  cudaGetSymbolAddress((void**)&hw,  g_hw);
  cudaGetSymbolAddress((void**)&xpx, g_xpx);
  cudaGetSymbolAddress((void**)&hts, g_hts);
  cudaGetSymbolAddress((void**)&uc0, g_uc0);
  cudaGetSymbolAddress((void**)&uc1, g_uc1);
  cudaGetSymbolAddress((void**)&dw,  g_dw);
  cudaGetSymbolAddress((void**)&wat, g_wat);
  cudaGetSymbolAddress((void**)&est, g_est);
  cudaGetSymbolAddress((void**)&dst, g_dst);
  cudaGetSymbolAddress((void**)&hfhb,g_hfhb);
  cudaGetSymbolAddress((void**)&bc,  g_barc);

  // 1 gather, 2 prep (also zeroes barrier counters)
  k_gather<<<2*NTB, 128>>>(src, tgt, emb, se, te);
  k_prep<<<1792, 256>>>(e0Ur,e0Uz,e0Un, e1Ur,e1Uz,e1Un, dUr,dUz,dUn, dWih, Wa,
                        uc0, uc1, dw, wat);

  // 3 xp0 = src_emb @ e0Wih^T + b ; 4 encoder layer-0 scan (persistent)
  k_gemm_big<<<dim3(12,24), 256>>>(se, 512, e0Wih, 512, e0bih, xp0, 1536, 512, 1.f, 0);
  k_enc_scan<<<NBLK, 256>>>(xp0, uc0, e0bn, est, l0, bc + 0);

  // 5 xp1 ; 6 encoder layer-1 scan
  k_gemm_big<<<dim3(12,24), 256>>>(l0, 1024, e1Wih, 1024, e1bih, xp1, 1536, 1024, 1.f, 0);
  k_enc_scan<<<NBLK, 256>>>(xp1, uc1, e1bn, est, henc, bc + 1);

  // 7 [hf|hb] ; 8 h0 = tanh(hfhb @ fcw^T + fcb) -> dst rows 64..127
  k_hfhb<<<256, 256>>>(est, hfhb);
  k_gemm_small<<<16, 256>>>(hfhb, 1024, fcw, 1024, fcb, dst + 64*512, 512, 1024, 1);

  // 9 HW = (Henc @ Wa)/sqrt(2H) ; 10 XPx = tgt_emb @ dWih_x^T + dbih
  k_gemm_big<<<dim3(4,24), 256>>>(henc, 1024, wat, 1024, (const float*)nullptr,
                                  hw, 512, 1024, 0.03125f, 0);
  k_gemm_big<<<dim3(12,24), 256>>>(te, 512, dWih, 1024, dbih, xpx, 1536, 512, 1.f, 0);

  // 11 decoder scan (persistent, 48 steps)
  k_dec_scan<<<NBLK, 256>>>(xpx, dw, dbn, dst, hw, henc, src, acw, hts, bc + 2);

  // 12 logits: (3072,512) @ out_w(32000,512)^T
  k_gemm_big<<<dim3(250,24), 256>>>(hts, 512, outw, 512, (const float*)nullptr,
                                    out, 32000, 512, 1.f, 0);
}

// round 12
// speedup vs baseline: 1.1658x; 1.1658x over previous
#include <cuda_runtime.h>
#include <cuda_bf16.h>
#include <math.h>
#include <stdint.h>

// Problem: V=32000, H=512, TS=TT=48, B=64, PAD=0
// Output: logits (48,64,32000) f32

#define NTB (48*64)            // 3072 time-batch rows
#define NBLK 96                // persistent grid size (<=148 SMs -> all resident)

// ---------------- scratch (static device globals; no allocation) -------------
__device__ __align__(256) float g_src_emb[NTB*512];
__device__ __align__(256) float g_tgt_emb[NTB*512];
__device__ __align__(256) float g_xp0[NTB*1536];
__device__ __align__(256) float g_l0 [NTB*1024];
__device__ __align__(256) float g_xp1[NTB*1536];
__device__ __align__(256) float g_henc[NTB*1024];
__device__ __align__(256) float g_hw [NTB*512];
__device__ __align__(256) float g_xpx[NTB*1536];
__device__ __align__(256) float g_hts[NTB*512];
__device__ __align__(256) float g_uc0[1536*512];
__device__ __align__(256) float g_uc1[1536*512];
__device__ __align__(256) float g_dw [3072*512];   // [WihH(1536); dUr;dUz;dUn]
__device__ __align__(256) float g_wat[512*1024];   // Wa transposed (n,k)
__device__ __align__(256) float g_est[128*512];    // enc state
__device__ __align__(256) float g_dst[128*512];    // dec state: rows0-63 ht, 64-127 h
__device__ __align__(256) float g_hfhb[64*1024];
__device__ __align__(256) float g_P [128*1536];
__device__ __align__(256) float g_G [128*1536];
__device__ __align__(256) float g_cc[64*1536];
__device__ __align__(256) float g_cp[6*64*512];
__device__ unsigned g_barc[4];
// bf16-split operands for the tensor-core logits GEMM
__device__ __align__(256) __nv_bfloat16 g_aw[3072*1536];    // A' = [hi | lo | hi]
__device__ __align__(256) __nv_bfloat16 g_bw[32000u*1536];  // B' = [hi | hi | lo]

// ---------------- scalar helpers ---------------------------------------------
__device__ __forceinline__ unsigned long long fma2(unsigned long long a,
                                                   unsigned long long b,
                                                   unsigned long long c){
  unsigned long long d;
  asm("fma.rn.f32x2 %0, %1, %2, %3;" : "=l"(d) : "l"(a), "l"(b), "l"(c));
  return d;
}
__device__ __forceinline__ unsigned long long pack2(float x, float y){
  unsigned long long d;
  asm("mov.b64 %0, {%1, %2};" : "=l"(d) : "f"(x), "f"(y));
  return d;
}
__device__ __forceinline__ float2 unpack2(unsigned long long v){
  float2 r;
  asm("mov.b64 {%0, %1}, %2;" : "=f"(r.x), "=f"(r.y) : "l"(v));
  return r;
}
__device__ __forceinline__ float sigmf(float x){ return 1.f/(1.f+__expf(-x)); }

__device__ __forceinline__ void gbar(unsigned* cnt, unsigned target){
  __syncthreads();
  if (threadIdx.x == 0){
    __threadfence();
    atomicAdd(cnt, 1u);
    volatile unsigned* vc = (volatile unsigned*)cnt;
    while (*vc < target) {}
    __threadfence();
  }
  __syncthreads();
}

__device__ __forceinline__ uint32_t smem_u32(const void* p){
  uint32_t a;
  asm("{ .reg .u64 t; cvta.to.shared.u64 t, %1; cvt.u32.u64 %0, t; }" : "=r"(a) : "l"(p));
  return a;
}

// ---------------- 64x32 tile GEMM (f32x2 FFMA) for persistent scans ----------
__device__ __forceinline__ void tile64x32(
    float (*As)[68], float (*Bs)[36],
    const float* __restrict__ A, int lda, int m0,
    const float* __restrict__ W, int ldw, int wrow0,
    int kstart, int K,
    float* __restrict__ C, int ldc, int cm0, int cn0)
{
  int t = threadIdx.x;
  int ar = t & 63, ak = (t >> 6) << 2;
  int wr = t & 31, wk = ((t & 127) >> 5) << 2;
  const float* Ap = A + (size_t)(m0 + ar)*lda + kstart + ak;
  const float* Wp = W + (size_t)(wrow0 + wr)*ldw + kstart + wk;
  int cm = (t >> 4) << 2, cn = (t & 15) << 1;
  unsigned long long a00=0ull, a01=0ull, a10=0ull, a11=0ull;
  for (int k0 = 0; k0 < K; k0 += 16){
    float4 av = *(const float4*)(Ap + k0);
    float4 wv = make_float4(0.f,0.f,0.f,0.f);
    if (t < 128) wv = *(const float4*)(Wp + k0);
    __syncthreads();
    As[ak+0][ar]=av.x; As[ak+1][ar]=av.y; As[ak+2][ar]=av.z; As[ak+3][ar]=av.w;
    if (t < 128){ Bs[wk+0][wr]=wv.x; Bs[wk+1][wr]=wv.y; Bs[wk+2][wr]=wv.z; Bs[wk+3][wr]=wv.w; }
    __syncthreads();
#pragma unroll
    for (int kk = 0; kk < 16; kk++){
      float4 af = *(const float4*)&As[kk][cm];
      float2 bf = *(const float2*)&Bs[kk][cn];
      unsigned long long ap0 = pack2(af.x, af.y);
      unsigned long long ap1 = pack2(af.z, af.w);
      unsigned long long b0  = pack2(bf.x, bf.x);
      unsigned long long b1  = pack2(bf.y, bf.y);
      a00 = fma2(ap0, b0, a00); a10 = fma2(ap1, b0, a10);
      a01 = fma2(ap0, b1, a01); a11 = fma2(ap1, b1, a11);
    }
  }
  float2 v;
  v = unpack2(a00); C[(size_t)(cm0+cm+0)*ldc + cn0+cn]   = v.x; C[(size_t)(cm0+cm+1)*ldc + cn0+cn]   = v.y;
  v = unpack2(a10); C[(size_t)(cm0+cm+2)*ldc + cn0+cn]   = v.x; C[(size_t)(cm0+cm+3)*ldc + cn0+cn]   = v.y;
  v = unpack2(a01); C[(size_t)(cm0+cm+0)*ldc + cn0+cn+1] = v.x; C[(size_t)(cm0+cm+1)*ldc + cn0+cn+1] = v.y;
  v = unpack2(a11); C[(size_t)(cm0+cm+2)*ldc + cn0+cn+1] = v.x; C[(size_t)(cm0+cm+3)*ldc + cn0+cn+1] = v.y;
}

// ---------------- embedding gather -------------------------------------------
__global__ void k_gather(const int* __restrict__ src, const int* __restrict__ tgt,
                         const float* __restrict__ emb,
                         float* __restrict__ se, float* __restrict__ te){
  int idx = blockIdx.x;
  int is_src = idx < NTB;
  int i = is_src ? idx : idx - NTB;
  int token = is_src ? src[i] : tgt[i];
  const float4* erow = (const float4*)(emb + (size_t)token*512);
  float4* orow = (float4*)((is_src ? se : te) + (size_t)i*512);
  orow[threadIdx.x] = erow[threadIdx.x];
}

// ---------------- weight prep (+ barrier counter reset) ----------------------
__global__ void k_prep(const float* e0Ur, const float* e0Uz, const float* e0Un,
                       const float* e1Ur, const float* e1Uz, const float* e1Un,
                       const float* dUr, const float* dUz, const float* dUn,
                       const float* dWih, const float* Wa,
                       float* uc0, float* uc1, float* dw, float* wat){
  if (blockIdx.x == 0 && threadIdx.x < 4) g_barc[threadIdx.x] = 0u;
  const int n1 = 1536*512;
  const int n2 = 3072*512;
  const int n3 = 512*1024;
  int total = 2*n1 + n2 + n3;
  for (int i = blockIdx.x*blockDim.x + threadIdx.x; i < total;
       i += gridDim.x*blockDim.x){
    if (i < n1){
      int g = i / 262144, r = i % 262144;
      uc0[i] = g==0 ? e0Ur[r] : (g==1 ? e0Uz[r] : e0Un[r]);
    } else if (i < 2*n1){
      int j = i - n1; int g = j / 262144, r = j % 262144;
      uc1[j] = g==0 ? e1Ur[r] : (g==1 ? e1Uz[r] : e1Un[r]);
    } else if (i < 2*n1 + n2){
      int j = i - 2*n1; int row = j >> 9, k = j & 511;
      float v;
      if      (row < 1536) v = dWih[(size_t)row*1024 + 512 + k];
      else if (row < 2048) v = dUr[(row-1536)*512 + k];
      else if (row < 2560) v = dUz[(row-2048)*512 + k];
      else                 v = dUn[(row-2560)*512 + k];
      dw[j] = v;
    } else {
      int j = i - 2*n1 - n2; int nn = j >> 10, k = j & 1023;
      wat[j] = Wa[(size_t)k*512 + nn];
    }
  }
}

// ---------------- bf16 hi/lo splits ------------------------------------------
__global__ void k_wsplit(const float* __restrict__ w, __nv_bfloat16* __restrict__ bw){
  size_t i = (size_t)blockIdx.x*blockDim.x + threadIdx.x;   // 32000*512
  if (i >= 32000u*512) return;
  size_t n = i >> 9, k = i & 511;
  float x = w[i];
  __nv_bfloat16 hi = __float2bfloat16(x);
  __nv_bfloat16 lo = __float2bfloat16(x - __bfloat162float(hi));
  __nv_bfloat16* row = bw + n*1536;
  row[k] = hi; row[512 + k] = hi; row[1024 + k] = lo;
}
__global__ void k_asplit(const float* __restrict__ a, __nv_bfloat16* __restrict__ aw){
  size_t i = (size_t)blockIdx.x*blockDim.x + threadIdx.x;   // 3072*512
  if (i >= 3072u*512) return;
  size_t m = i >> 9, k = i & 511;
  float x = a[i];
  __nv_bfloat16 hi = __float2bfloat16(x);
  __nv_bfloat16 lo = __float2bfloat16(x - __bfloat162float(hi));
  __nv_bfloat16* row = aw + m*1536;
  row[k] = hi; row[512 + k] = lo; row[1024 + k] = hi;
}

// ---------------- big GEMM (FFMA2) for projections ---------------------------
__global__ __launch_bounds__(256) void k_gemm_big(
    const float* __restrict__ A, int lda,
    const float* __restrict__ W, int ldw,
    const float* __restrict__ bias,
    float* __restrict__ C, int ldc,
    int K, float scale, int act)
{
  __shared__ __align__(16) float As[16][136];
  __shared__ __align__(16) float Bs[16][136];
  int t = threadIdx.x;
  int m0 = blockIdx.y * 128, n0 = blockIdx.x * 128;
  int ar = t >> 1, ak = (t & 1) * 8;
  const float* Ap = A + (size_t)(m0 + ar)*lda + ak;
  const float* Wp = W + (size_t)(n0 + ar)*ldw + ak;
  int tx = t & 15, ty = t >> 4;
  int cm = ty * 8, cn = tx * 8;
  unsigned long long acc[8][4];
#pragma unroll
  for (int i=0;i<8;i++)
#pragma unroll
    for (int j=0;j<4;j++) acc[i][j] = 0ull;

  for (int k0 = 0; k0 < K; k0 += 16){
    float4 a0 = *(const float4*)(Ap + k0);
    float4 a1 = *(const float4*)(Ap + k0 + 4);
    float4 w0 = *(const float4*)(Wp + k0);
    float4 w1 = *(const float4*)(Wp + k0 + 4);
    __syncthreads();
    As[ak+0][ar]=a0.x; As[ak+1][ar]=a0.y; As[ak+2][ar]=a0.z; As[ak+3][ar]=a0.w;
    As[ak+4][ar]=a1.x; As[ak+5][ar]=a1.y; As[ak+6][ar]=a1.z; As[ak+7][ar]=a1.w;
    Bs[ak+0][ar]=w0.x; Bs[ak+1][ar]=w0.y; Bs[ak+2][ar]=w0.z; Bs[ak+3][ar]=w0.w;
    Bs[ak+4][ar]=w1.x; Bs[ak+5][ar]=w1.y; Bs[ak+6][ar]=w1.z; Bs[ak+7][ar]=w1.w;
    __syncthreads();
#pragma unroll
    for (int kk=0; kk<16; kk++){
      float4 af0 = *(const float4*)&As[kk][cm];
      float4 af1 = *(const float4*)&As[kk][cm+4];
      float4 bf0 = *(const float4*)&Bs[kk][cn];
      float4 bf1 = *(const float4*)&Bs[kk][cn+4];
      unsigned long long bp0 = pack2(bf0.x, bf0.y);
      unsigned long long bp1 = pack2(bf0.z, bf0.w);
      unsigned long long bp2 = pack2(bf1.x, bf1.y);
      unsigned long long bp3 = pack2(bf1.z, bf1.w);
      float am[8] = {af0.x,af0.y,af0.z,af0.w,af1.x,af1.y,af1.z,af1.w};
#pragma unroll
      for (int i=0;i<8;i++){
        unsigned long long ap = pack2(am[i], am[i]);
        acc[i][0] = fma2(ap, bp0, acc[i][0]);
        acc[i][1] = fma2(ap, bp1, acc[i][1]);
        acc[i][2] = fma2(ap, bp2, acc[i][2]);
        acc[i][3] = fma2(ap, bp3, acc[i][3]);
      }
    }
  }
#pragma unroll
  for (int i=0;i<8;i++){
    float* crow = C + (size_t)(m0+cm+i)*ldc + n0 + cn;
#pragma unroll
    for (int j=0;j<4;j++){
      float2 v = unpack2(acc[i][j]);
      float x0 = v.x*scale, x1 = v.y*scale;
      if (bias){ x0 += bias[n0+cn+2*j]; x1 += bias[n0+cn+2*j+1]; }
      if (act){ x0 = tanhf(x0); x1 = tanhf(x1); }
      *(float2*)(crow + 2*j) = make_float2(x0, x1);
    }
  }
}

// ---------------- small standalone GEMM (decoder h0 init only) ---------------
__global__ __launch_bounds__(256) void k_gemm_small(
    const float* __restrict__ A, int lda,
    const float* __restrict__ W, int ldw,
    const float* __restrict__ bias,
    float* __restrict__ C, int ldc, int K, int act)
{
  __shared__ __align__(16) float As[16][68];
  __shared__ __align__(16) float Bs[16][36];
  int t = threadIdx.x;
  int n0 = blockIdx.x * 32;
  int ar = t & 63, ak = (t >> 6) << 2;
  int wr = t & 31, wk = ((t & 127) >> 5) << 2;
  const float* Ap = A + (size_t)ar*lda + ak;
  const float* Wp = W + (size_t)(n0 + wr)*ldw + wk;
  int tx = t & 15, ty = t >> 4;
  int cm = ty * 4, cn = tx * 2;
  float acc[4][2] = {{0.f,0.f},{0.f,0.f},{0.f,0.f},{0.f,0.f}};
  for (int k0 = 0; k0 < K; k0 += 16){
    float4 av = *(const float4*)(Ap + k0);
    float4 wv = make_float4(0.f,0.f,0.f,0.f);
    if (t < 128) wv = *(const float4*)(Wp + k0);
    __syncthreads();
    As[ak+0][ar]=av.x; As[ak+1][ar]=av.y; As[ak+2][ar]=av.z; As[ak+3][ar]=av.w;
    if (t < 128){ Bs[wk+0][wr]=wv.x; Bs[wk+1][wr]=wv.y; Bs[wk+2][wr]=wv.z; Bs[wk+3][wr]=wv.w; }
    __syncthreads();
#pragma unroll
    for (int kk=0; kk<16; kk++){
      float4 af = *(const float4*)&As[kk][cm];
      float2 bf = *(const float2*)&Bs[kk][cn];
      acc[0][0] += af.x*bf.x; acc[0][1] += af.x*bf.y;
      acc[1][0] += af.y*bf.x; acc[1][1] += af.y*bf.y;
      acc[2][0] += af.z*bf.x; acc[2][1] += af.z*bf.y;
      acc[3][0] += af.w*bf.x; acc[3][1] += af.w*bf.y;
    }
  }
#pragma unroll
  for (int i=0;i<4;i++)
#pragma unroll
    for (int j=0;j<2;j++){
      float v = acc[i][j];
      if (bias) v += bias[n0+cn+j];
      if (act) v = tanhf(v);
      C[(size_t)(cm+i)*ldc + n0 + cn + j] = v;
    }
}

// ---------------- hf|hb concat -----------------------------------------------
__global__ void k_hfhb(const float* __restrict__ est, float* __restrict__ hfhb){
  int i = blockIdx.x*blockDim.x + threadIdx.x;
  int b = i >> 10, k = i & 1023;
  hfhb[i] = (k < 512) ? est[b*512 + k] : est[(64 + b)*512 + (k - 512)];
}

// ---------------- persistent encoder scan ------------------------------------
__global__ __launch_bounds__(256) void k_enc_scan(
    const float* __restrict__ xp, const float* __restrict__ uc,
    const float* __restrict__ bn, float* __restrict__ est,
    float* __restrict__ out, unsigned* __restrict__ bar)
{
  __shared__ __align__(16) float As[16][68];
  __shared__ __align__(16) float Bs[16][36];
  int bx = blockIdx.x, t = threadIdx.x;
  unsigned nb = 0;
  float* P = g_P;
  for (int i = bx*256 + t; i < 65536; i += NBLK*256) est[i] = 0.f;
  nb += NBLK; gbar(bar, nb);
  int m0 = (bx & 1) * 64, n0 = (bx >> 1) * 32;
  for (int step = 0; step < 48; step++){
    tile64x32(As, Bs, est, 512, m0, uc, 512, n0, 0, 512, P, 1536, m0, n0);
    nb += NBLK; gbar(bar, nb);
    for (int i = bx*256 + t; i < 65536; i += NBLK*256){
      int r = i >> 9, j = i & 511;
      int b = r & 63, fwd = (r < 64);
      int tpos = fwd ? step : 47 - step;
      const float* xrow = xp + ((size_t)tpos*64 + b)*1536;
      const float* prow = P + (size_t)r*1536;
      float h  = est[i];
      float rg = sigmf(xrow[j]       + prow[j]);
      float zg = sigmf(xrow[512 + j] + prow[512 + j]);
      float ng = tanhf(xrow[1024+ j] + rg*(prow[1024 + j] + bn[j]));
      float hn = (1.f - zg)*ng + zg*h;
      est[i] = hn;
      out[((size_t)tpos*64 + b)*1024 + (fwd ? 0 : 512) + j] = hn;
    }
    nb += NBLK; gbar(bar, nb);
  }
}

// ---------------- persistent decoder scan ------------------------------------
__global__ __launch_bounds__(256) void k_dec_scan(
    const float* __restrict__ xpx, const float* __restrict__ dw,
    const float* __restrict__ bn, float* __restrict__ dst,
    const float* __restrict__ hw, const float* __restrict__ henc,
    const int* __restrict__ src, const float* __restrict__ acw,
    float* __restrict__ hts, unsigned* __restrict__ bar)
{
  __shared__ __align__(16) float As[16][68];
  __shared__ __align__(16) float Bs[16][36];
  __shared__ float hsm[512];
  __shared__ float ssm[48];
  __shared__ float sinv;
  int bx = blockIdx.x, t = threadIdx.x;
  unsigned nb = 0;
  float* G = g_G; float* cc = g_cc; float* cp = g_cp;
  for (int i = bx*256 + t; i < 32768; i += NBLK*256) dst[i] = 0.f;
  nb += NBLK; gbar(bar, nb);
  int gA = bx & 1, nA = (bx >> 1) * 32;
  int ksC = bx / 16, nC = (bx & 15) * 32;
  for (int step = 0; step < 48; step++){
    tile64x32(As, Bs, dst, 512, gA*64, dw, 512, gA*1536 + nA, 0, 512,
              G, 1536, gA*64, nA);
    nb += NBLK; gbar(bar, nb);
    if (bx < 64){
      int b = bx;
      const float* xrow = xpx + ((size_t)step*64 + b)*1536;
      const float* g0 = G + (size_t)b*1536;
      const float* g1 = G + (size_t)(64 + b)*1536;
      for (int j = t; j < 512; j += 256){
        float rg = sigmf(xrow[j]        + g0[j]        + g1[j]);
        float zg = sigmf(xrow[512 + j]  + g0[512 + j]  + g1[512 + j]);
        float ng = tanhf(xrow[1024 + j] + g0[1024 + j] + rg*(g1[1024 + j] + bn[j]));
        float h  = dst[(size_t)(64 + b)*512 + j];
        float hn = (1.f - zg)*ng + zg*h;
        dst[(size_t)(64 + b)*512 + j] = hn;
        hsm[j] = hn;
        cc[(size_t)b*1536 + j] = hn;
      }
      __syncthreads();
      int w = t >> 5, lane = t & 31;
      for (int tp = w; tp < 48; tp += 8){
        const float* hwrow = hw + ((size_t)tp*64 + b)*512;
        float s = 0.f;
        for (int j = lane; j < 512; j += 32) s += hsm[j]*hwrow[j];
#pragma unroll
        for (int o = 16; o; o >>= 1) s += __shfl_xor_sync(0xffffffffu, s, o);
        if (lane == 0) ssm[tp] = (src[tp*64 + b] == 0) ? -1e9f : s;
      }
      __syncthreads();
      if (t == 0){
        float mx = -1e30f;
        for (int i2 = 0; i2 < 48; i2++) mx = fmaxf(mx, ssm[i2]);
        float sum = 0.f;
        for (int i2 = 0; i2 < 48; i2++){ float e = __expf(ssm[i2]-mx); ssm[i2]=e; sum+=e; }
        sinv = 1.f/sum;
      }
      __syncthreads();
      for (int d = t; d < 1024; d += 256){
        float accv = 0.f;
#pragma unroll 4
        for (int tp = 0; tp < 48; tp++)
          accv += ssm[tp]*henc[((size_t)tp*64 + b)*1024 + d];
        cc[(size_t)b*1536 + 512 + d] = accv*sinv;
      }
    }
    nb += NBLK; gbar(bar, nb);
    tile64x32(As, Bs, cc, 1536, 0, acw, 1536, nC, ksC*256, 256,
              cp + (size_t)ksC*32768, 512, 0, nC);
    nb += NBLK; gbar(bar, nb);
    for (int i = bx*256 + t; i < 32768; i += NBLK*256){
      float v = cp[i] + cp[32768+i] + cp[2*32768+i] + cp[3*32768+i]
              + cp[4*32768+i] + cp[5*32768+i];
      v = tanhf(v);
      dst[i] = v;
      hts[(size_t)step*32768 + i] = v;
    }
    nb += NBLK; gbar(bar, nb);
  }
}

// ---------------- logits: mma.sync bf16-split GEMM (baseline sm_80+ PTX) -----
// C(3072x32000) = A'(3072x1536) @ B'(32000x1536)^T, fp32 accum in registers.
// 128x128 block tile, 8 warps (4m x 2n), warp tile 32x64, K-chunk 64,
// cp.async double buffering, ldmatrix.x4 for both operands.
#define LG_PAD 72                      // smem row stride in bf16 (144B)
#define LG_TILE_B (128*LG_PAD*2)       // 18432 B per tile
#define LG_SMEM_TOTAL (4*LG_TILE_B)    // A0 B0 A1 B1 = 73728 B

__device__ __forceinline__ void ldsm4(uint32_t* r, uint32_t addr){
  asm volatile("ldmatrix.sync.aligned.m8n8.x4.shared.b16 {%0,%1,%2,%3}, [%4];"
               : "=r"(r[0]), "=r"(r[1]), "=r"(r[2]), "=r"(r[3]) : "r"(addr));
}
__device__ __forceinline__ void mma16816(float* d, const uint32_t* a,
                                         uint32_t b0, uint32_t b1){
  asm volatile("mma.sync.aligned.m16n8k16.row.col.f32.bf16.bf16.f32 "
               "{%0,%1,%2,%3}, {%4,%5,%6,%7}, {%8,%9}, {%0,%1,%2,%3};"
               : "+f"(d[0]), "+f"(d[1]), "+f"(d[2]), "+f"(d[3])
               : "r"(a[0]), "r"(a[1]), "r"(a[2]), "r"(a[3]), "r"(b0), "r"(b1));
}
__device__ __forceinline__ void cpasync16(uint32_t dst, const void* src){
  asm volatile("cp.async.ca.shared.global [%0], [%1], 16;" :: "r"(dst), "l"(src));
}

__global__ __launch_bounds__(256) void k_logits_mma(
    const __nv_bfloat16* __restrict__ A, const __nv_bfloat16* __restrict__ B,
    float* __restrict__ C)
{
  extern __shared__ __align__(16) char smem[];
  uint32_t sb = smem_u32(smem);
  uint32_t sA[2] = { sb,                sb + 2*LG_TILE_B };
  uint32_t sBs[2]= { sb + LG_TILE_B,    sb + 3*LG_TILE_B };
  int t = threadIdx.x, lane = t & 31, wid = t >> 5;
  int m0 = blockIdx.y * 128, n0 = blockIdx.x * 128;
  int wm = (wid & 3) * 32, wn = (wid >> 2) * 64;

  // loader: thread t covers rows t/8 + 32p (p=0..3), 16B unit t%8
  int lrow = t >> 3, lc8 = (t & 7) * 8;
  const __nv_bfloat16* Ap = A + (size_t)(m0 + lrow)*1536 + lc8;
  const __nv_bfloat16* Bp = B + (size_t)(n0 + lrow)*1536 + lc8;
  uint32_t sAo = (uint32_t)((lrow*LG_PAD + lc8)*2);
  uint32_t sBo = sAo;

  float acc[2][8][4];
#pragma unroll
  for (int i=0;i<2;i++)
#pragma unroll
    for (int j=0;j<8;j++)
#pragma unroll
      for (int k=0;k<4;k++) acc[i][j][k] = 0.f;

  // ldmatrix lane addressing (row-major padded tiles, non-trans for A and B)
  int lrow16 = lane & 15;
  int lcolk8 = (lane >> 4) << 3;

  // prologue: load chunk 0
#pragma unroll
  for (int p = 0; p < 4; p++){
    cpasync16(sA[0] + sAo + (uint32_t)(p*32*LG_PAD*2), Ap + (size_t)p*32*1536);
    cpasync16(sBs[0]+ sBo + (uint32_t)(p*32*LG_PAD*2), Bp + (size_t)p*32*1536);
  }
  asm volatile("cp.async.commit_group;");

  for (int c = 0; c < 24; c++){
    int buf = c & 1;
    if (c < 23){
      int kc = (c + 1) * 64;
#pragma unroll
      for (int p = 0; p < 4; p++){
        cpasync16(sA[buf^1] + sAo + (uint32_t)(p*32*LG_PAD*2),
                  Ap + (size_t)p*32*1536 + kc);
        cpasync16(sBs[buf^1]+ sBo + (uint32_t)(p*32*LG_PAD*2),
                  Bp + (size_t)p*32*1536 + kc);
      }
      asm volatile("cp.async.commit_group;");
      asm volatile("cp.async.wait_group 1;");
    } else {
      asm volatile("cp.async.wait_group 0;");
    }
    __syncthreads();
#pragma unroll
    for (int kk = 0; kk < 4; kk++){
      int col = kk*16 + lcolk8;
      uint32_t af[2][4], bfr[4][4];
#pragma unroll
      for (int mi = 0; mi < 2; mi++){
        uint32_t addr = sA[buf] + (uint32_t)(((wm + mi*16 + lrow16)*LG_PAD + col)*2);
        ldsm4(af[mi], addr);
      }
#pragma unroll
      for (int nj = 0; nj < 4; nj++){
        uint32_t addr = sBs[buf] + (uint32_t)(((wn + nj*16 + lrow16)*LG_PAD + col)*2);
        ldsm4(bfr[nj], addr);
      }
#pragma unroll
      for (int mi = 0; mi < 2; mi++)
#pragma unroll
        for (int n8 = 0; n8 < 8; n8++){
          int nj = n8 >> 1, sel = n8 & 1;
          mma16816(acc[mi][n8], af[mi], bfr[nj][sel], bfr[nj][sel + 2]);
        }
    }
    __syncthreads();
  }

  // epilogue: direct float2 stores
  int r4 = lane >> 2, c2 = (lane & 3) * 2;
#pragma unroll
  for (int mi = 0; mi < 2; mi++){
#pragma unroll
    for (int n8 = 0; n8 < 8; n8++){
      int row = m0 + wm + mi*16 + r4;
      int col = n0 + wn + n8*8 + c2;
      *(float2*)(C + (size_t)row*32000 + col) =
          make_float2(acc[mi][n8][0], acc[mi][n8][1]);
      *(float2*)(C + (size_t)(row + 8)*32000 + col) =
          make_float2(acc[mi][n8][2], acc[mi][n8][3]);
    }
  }
}

// =============================================================================
extern "C" void kernel_launch(void* const* d_in, const int* in_sizes, int n_in,
                              void* d_out, int out_size){
  const int*   src  = (const int*)  d_in[0];
  const int*   tgt  = (const int*)  d_in[1];
  const float* emb  = (const float*)d_in[2];
  const float* e0Wih=(const float*)d_in[3];  const float* e0bih=(const float*)d_in[4];
  const float* e0Ur =(const float*)d_in[5];  const float* e0Uz =(const float*)d_in[6];
  const float* e0Un =(const float*)d_in[7];  const float* e0bn =(const float*)d_in[8];
  const float* e1Wih=(const float*)d_in[9];  const float* e1bih=(const float*)d_in[10];
  const float* e1Ur =(const float*)d_in[11]; const float* e1Uz =(const float*)d_in[12];
  const float* e1Un =(const float*)d_in[13]; const float* e1bn =(const float*)d_in[14];
  const float* fcw  =(const float*)d_in[15]; const float* fcb  =(const float*)d_in[16];
  const float* Wa   =(const float*)d_in[17]; const float* acw  =(const float*)d_in[18];
  const float* dWih =(const float*)d_in[19]; const float* dbih =(const float*)d_in[20];
  const float* dUr  =(const float*)d_in[21]; const float* dUz  =(const float*)d_in[22];
  const float* dUn  =(const float*)d_in[23]; const float* dbn  =(const float*)d_in[24];
  const float* outw =(const float*)d_in[25];
  float* out = (float*)d_out;

  float *se,*te,*xp0,*l0,*xp1,*henc,*hw,*xpx,*hts,*uc0,*uc1,*dw,*wat,*est,*dst,*hfhb;
  unsigned* bc; __nv_bfloat16 *aw,*bw;
  cudaGetSymbolAddress((void**)&se,  g_src_emb);
  cudaGetSymbolAddress((void**)&te,  g_tgt_emb);
  cudaGetSymbolAddress((void**)&xp0, g_xp0);
  cudaGetSymbolAddress((void**)&l0,  g_l0);
  cudaGetSymbolAddress((void**)&xp1, g_xp1);
  cudaGetSymbolAddress((void**)&henc,g_henc);
  cudaGetSymbolAddress((void**)&hw,  g_hw);
  cudaGetSymbolAddress((void**)&xpx, g_xpx);
  cudaGetSymbolAddress((void**)&hts, g_hts);
  cudaGetSymbolAddress((void**)&uc0, g_uc0);
  cudaGetSymbolAddress((void**)&uc1, g_uc1);
  cudaGetSymbolAddress((void**)&dw,  g_dw);
  cudaGetSymbolAddress((void**)&wat, g_wat);
  cudaGetSymbolAddress((void**)&est, g_est);
  cudaGetSymbolAddress((void**)&dst, g_dst);
  cudaGetSymbolAddress((void**)&hfhb,g_hfhb);
  cudaGetSymbolAddress((void**)&bc,  g_barc);
  cudaGetSymbolAddress((void**)&aw,  g_aw);
  cudaGetSymbolAddress((void**)&bw,  g_bw);

  cudaFuncSetAttribute(k_logits_mma, cudaFuncAttributeMaxDynamicSharedMemorySize,
                       LG_SMEM_TOTAL);

  // 1 gather, 2 prep, 3 wsplit (B' bf16 split of out_w)
  k_gather<<<2*NTB, 128>>>(src, tgt, emb, se, te);
  k_prep<<<1792, 256>>>(e0Ur,e0Uz,e0Un, e1Ur,e1Uz,e1Un, dUr,dUz,dUn, dWih, Wa,
                        uc0, uc1, dw, wat);
  k_wsplit<<<64000, 256>>>(outw, bw);

  // 4 xp0 ; 5 encoder layer-0 scan ; 6 xp1 (ncu -s 5 profiles THIS) ; 7 enc1
  k_gemm_big<<<dim3(12,24), 256>>>(se, 512, e0Wih, 512, e0bih, xp0, 1536, 512, 1.f, 0);
  k_enc_scan<<<NBLK, 256>>>(xp0, uc0, e0bn, est, l0, bc + 0);
  k_gemm_big<<<dim3(12,24), 256>>>(l0, 1024, e1Wih, 1024, e1bih, xp1, 1536, 1024, 1.f, 0);
  k_enc_scan<<<NBLK, 256>>>(xp1, uc1, e1bn, est, henc, bc + 1);

  // 8 [hf|hb] ; 9 h0
  k_hfhb<<<256, 256>>>(est, hfhb);
  k_gemm_small<<<16, 256>>>(hfhb, 1024, fcw, 1024, fcb, dst + 64*512, 512, 1024, 1);

  // 10 HW ; 11 XPx
  k_gemm_big<<<dim3(4,24), 256>>>(henc, 1024, wat, 1024, (const float*)nullptr,
                                  hw, 512, 1024, 0.03125f, 0);
  k_gemm_big<<<dim3(12,24), 256>>>(te, 512, dWih, 1024, dbih, xpx, 1536, 512, 1.f, 0);

  // 12 decoder scan
  k_dec_scan<<<NBLK, 256>>>(xpx, dw, dbn, dst, hw, henc, src, acw, hts, bc + 2);

  // 13 A' split ; 14 logits via mma.sync
  k_asplit<<<6144, 256>>>(hts, aw);
  k_logits_mma<<<dim3(250, 24), 256, LG_SMEM_TOTAL>>>(aw, bw, out);
}

// round 13
// speedup vs baseline: 1.4777x; 1.2675x over previous
#include <cuda_runtime.h>
#include <cuda_bf16.h>
#include <math.h>
#include <stdint.h>

// Problem: V=32000, H=512, TS=TT=48, B=64, PAD=0
// Output: logits (48,64,32000) f32

#define NTB (48*64)            // 3072 time-batch rows
#define NBLK 96                // persistent grid size (<=148 SMs -> all resident)

// ---------------- scratch (static device globals; no allocation) -------------
__device__ __align__(256) float g_src_emb[NTB*512];
__device__ __align__(256) float g_tgt_emb[NTB*512];
__device__ __align__(256) float g_xp0[NTB*1536];
__device__ __align__(256) float g_l0 [NTB*1024];
__device__ __align__(256) float g_xp1[NTB*1536];
__device__ __align__(256) float g_henc[NTB*1024];
__device__ __align__(256) float g_hw [NTB*512];
__device__ __align__(256) float g_xpx[NTB*1536];
__device__ __align__(256) float g_hts[NTB*512];
__device__ __align__(256) float g_uc0[1536*512];
__device__ __align__(256) float g_uc1[1536*512];
__device__ __align__(256) float g_dw [3072*512];   // [WihH(1536); dUr;dUz;dUn]
__device__ __align__(256) float g_wat[512*1024];   // Wa transposed (n,k)
__device__ __align__(256) float g_est[128*512];    // enc state
__device__ __align__(256) float g_dst[128*512];    // dec state: rows0-63 ht, 64-127 h
__device__ __align__(256) float g_hfhb[64*1024];
__device__ __align__(256) float g_P [128*1536];
__device__ __align__(256) float g_G [128*1536];
__device__ __align__(256) float g_cc[64*1536];
__device__ __align__(256) float g_cp[6*64*512];
__device__ unsigned g_barc[4];
// bf16-split operands for the tensor-core logits GEMM
__device__ __align__(256) __nv_bfloat16 g_aw[3072*1536];    // A' = [hi | lo | hi]
__device__ __align__(256) __nv_bfloat16 g_bw[32000u*1536];  // B' = [hi | hi | lo]

// ---------------- scalar helpers ---------------------------------------------
__device__ __forceinline__ unsigned long long fma2(unsigned long long a,
                                                   unsigned long long b,
                                                   unsigned long long c){
  unsigned long long d;
  asm("fma.rn.f32x2 %0, %1, %2, %3;" : "=l"(d) : "l"(a), "l"(b), "l"(c));
  return d;
}
__device__ __forceinline__ unsigned long long pack2(float x, float y){
  unsigned long long d;
  asm("mov.b64 %0, {%1, %2};" : "=l"(d) : "f"(x), "f"(y));
  return d;
}
__device__ __forceinline__ float2 unpack2(unsigned long long v){
  float2 r;
  asm("mov.b64 {%0, %1}, %2;" : "=f"(r.x), "=f"(r.y) : "l"(v));
  return r;
}
__device__ __forceinline__ float sigmf(float x){ return 1.f/(1.f+__expf(-x)); }
__device__ __forceinline__ float gru1(float xr, float xz, float xn,
                                      float pr, float pz, float pn,
                                      float bn, float h){
  float rg = sigmf(xr + pr);
  float zg = sigmf(xz + pz);
  float ng = tanhf(xn + rg*(pn + bn));
  return (1.f - zg)*ng + zg*h;
}

__device__ __forceinline__ void gbar(unsigned* cnt, unsigned target){
  __syncthreads();
  if (threadIdx.x == 0){
    __threadfence();
    atomicAdd(cnt, 1u);
    volatile unsigned* vc = (volatile unsigned*)cnt;
    while (*vc < target) {}
    __threadfence();
  }
  __syncthreads();
}

__device__ __forceinline__ uint32_t smem_u32(const void* p){
  uint32_t a;
  asm("{ .reg .u64 t; cvta.to.shared.u64 t, %1; cvt.u32.u64 %0, t; }" : "=r"(a) : "l"(p));
  return a;
}

// ---- 64x32 tile GEMM (f32x2 FFMA), software-pipelined global loads ----------
__device__ __forceinline__ void tile64x32(
    float (*As)[68], float (*Bs)[36],
    const float* __restrict__ A, int lda, int m0,
    const float* __restrict__ W, int ldw, int wrow0,
    int kstart, int K,
    float* __restrict__ C, int ldc, int cm0, int cn0)
{
  int t = threadIdx.x;
  int ar = t & 63, ak = (t >> 6) << 2;
  int wr = t & 31, wk = ((t & 127) >> 5) << 2;
  const float* Ap = A + (size_t)(m0 + ar)*lda + kstart + ak;
  const float* Wp = W + (size_t)(wrow0 + wr)*ldw + kstart + wk;
  int cm = (t >> 4) << 2, cn = (t & 15) << 1;
  unsigned long long a00=0ull, a01=0ull, a10=0ull, a11=0ull;
  float4 av = *(const float4*)(Ap);
  float4 wv = make_float4(0.f,0.f,0.f,0.f);
  if (t < 128) wv = *(const float4*)(Wp);
  for (int k0 = 0; k0 < K; k0 += 16){
    __syncthreads();
    As[ak+0][ar]=av.x; As[ak+1][ar]=av.y; As[ak+2][ar]=av.z; As[ak+3][ar]=av.w;
    if (t < 128){ Bs[wk+0][wr]=wv.x; Bs[wk+1][wr]=wv.y; Bs[wk+2][wr]=wv.z; Bs[wk+3][wr]=wv.w; }
    if (k0 + 16 < K){
      av = *(const float4*)(Ap + k0 + 16);
      if (t < 128) wv = *(const float4*)(Wp + k0 + 16);
    }
    __syncthreads();
#pragma unroll
    for (int kk = 0; kk < 16; kk++){
      float4 af = *(const float4*)&As[kk][cm];
      float2 bf = *(const float2*)&Bs[kk][cn];
      unsigned long long ap0 = pack2(af.x, af.y);
      unsigned long long ap1 = pack2(af.z, af.w);
      unsigned long long b0  = pack2(bf.x, bf.x);
      unsigned long long b1  = pack2(bf.y, bf.y);
      a00 = fma2(ap0, b0, a00); a10 = fma2(ap1, b0, a10);
      a01 = fma2(ap0, b1, a01); a11 = fma2(ap1, b1, a11);
    }
  }
  float2 v;
  v = unpack2(a00); C[(size_t)(cm0+cm+0)*ldc + cn0+cn]   = v.x; C[(size_t)(cm0+cm+1)*ldc + cn0+cn]   = v.y;
  v = unpack2(a10); C[(size_t)(cm0+cm+2)*ldc + cn0+cn]   = v.x; C[(size_t)(cm0+cm+3)*ldc + cn0+cn]   = v.y;
  v = unpack2(a01); C[(size_t)(cm0+cm+0)*ldc + cn0+cn+1] = v.x; C[(size_t)(cm0+cm+1)*ldc + cn0+cn+1] = v.y;
  v = unpack2(a11); C[(size_t)(cm0+cm+2)*ldc + cn0+cn+1] = v.x; C[(size_t)(cm0+cm+3)*ldc + cn0+cn+1] = v.y;
}

// ---------------- embedding gather -------------------------------------------
__global__ void k_gather(const int* __restrict__ src, const int* __restrict__ tgt,
                         const float* __restrict__ emb,
                         float* __restrict__ se, float* __restrict__ te){
  int idx = blockIdx.x;
  int is_src = idx < NTB;
  int i = is_src ? idx : idx - NTB;
  int token = is_src ? src[i] : tgt[i];
  const float4* erow = (const float4*)(emb + (size_t)token*512);
  float4* orow = (float4*)((is_src ? se : te) + (size_t)i*512);
  orow[threadIdx.x] = erow[threadIdx.x];
}

// ---------------- weight prep (+ barrier counter reset) ----------------------
__global__ void k_prep(const float* e0Ur, const float* e0Uz, const float* e0Un,
                       const float* e1Ur, const float* e1Uz, const float* e1Un,
                       const float* dUr, const float* dUz, const float* dUn,
                       const float* dWih, const float* Wa,
                       float* uc0, float* uc1, float* dw, float* wat){
  if (blockIdx.x == 0 && threadIdx.x < 4) g_barc[threadIdx.x] = 0u;
  const int n1 = 1536*512;
  const int n2 = 3072*512;
  const int n3 = 512*1024;
  int total = 2*n1 + n2 + n3;
  for (int i = blockIdx.x*blockDim.x + threadIdx.x; i < total;
       i += gridDim.x*blockDim.x){
    if (i < n1){
      int g = i / 262144, r = i % 262144;
      uc0[i] = g==0 ? e0Ur[r] : (g==1 ? e0Uz[r] : e0Un[r]);
    } else if (i < 2*n1){
      int j = i - n1; int g = j / 262144, r = j % 262144;
      uc1[j] = g==0 ? e1Ur[r] : (g==1 ? e1Uz[r] : e1Un[r]);
    } else if (i < 2*n1 + n2){
      int j = i - 2*n1; int row = j >> 9, k = j & 511;
      float v;
      if      (row < 1536) v = dWih[(size_t)row*1024 + 512 + k];
      else if (row < 2048) v = dUr[(row-1536)*512 + k];
      else if (row < 2560) v = dUz[(row-2048)*512 + k];
      else                 v = dUn[(row-2560)*512 + k];
      dw[j] = v;
    } else {
      int j = i - 2*n1 - n2; int nn = j >> 10, k = j & 1023;
      wat[j] = Wa[(size_t)k*512 + nn];
    }
  }
}

// ---------------- bf16 hi/lo splits ------------------------------------------
__global__ void k_wsplit(const float* __restrict__ w, __nv_bfloat16* __restrict__ bw){
  size_t i = (size_t)blockIdx.x*blockDim.x + threadIdx.x;   // 32000*512
  if (i >= 32000u*512) return;
  size_t n = i >> 9, k = i & 511;
  float x = w[i];
  __nv_bfloat16 hi = __float2bfloat16(x);
  __nv_bfloat16 lo = __float2bfloat16(x - __bfloat162float(hi));
  __nv_bfloat16* row = bw + n*1536;
  row[k] = hi; row[512 + k] = hi; row[1024 + k] = lo;
}
__global__ void k_asplit(const float* __restrict__ a, __nv_bfloat16* __restrict__ aw){
  size_t i = (size_t)blockIdx.x*blockDim.x + threadIdx.x;   // 3072*512
  if (i >= 3072u*512) return;
  size_t m = i >> 9, k = i & 511;
  float x = a[i];
  __nv_bfloat16 hi = __float2bfloat16(x);
  __nv_bfloat16 lo = __float2bfloat16(x - __bfloat162float(hi));
  __nv_bfloat16* row = aw + m*1536;
  row[k] = hi; row[512 + k] = lo; row[1024 + k] = hi;
}

// ---------------- big GEMM (FFMA2, pipelined) for projections ----------------
__global__ __launch_bounds__(256) void k_gemm_big(
    const float* __restrict__ A, int lda,
    const float* __restrict__ W, int ldw,
    const float* __restrict__ bias,
    float* __restrict__ C, int ldc,
    int K, float scale, int act)
{
  __shared__ __align__(16) float As[16][136];
  __shared__ __align__(16) float Bs[16][136];
  int t = threadIdx.x;
  int m0 = blockIdx.y * 128, n0 = blockIdx.x * 128;
  int ar = t >> 1, ak = (t & 1) * 8;
  const float* Ap = A + (size_t)(m0 + ar)*lda + ak;
  const float* Wp = W + (size_t)(n0 + ar)*ldw + ak;
  int tx = t & 15, ty = t >> 4;
  int cm = ty * 8, cn = tx * 8;
  unsigned long long acc[8][4];
#pragma unroll
  for (int i=0;i<8;i++)
#pragma unroll
    for (int j=0;j<4;j++) acc[i][j] = 0ull;

  float4 a0 = *(const float4*)(Ap);
  float4 a1 = *(const float4*)(Ap + 4);
  float4 w0 = *(const float4*)(Wp);
  float4 w1 = *(const float4*)(Wp + 4);
  for (int k0 = 0; k0 < K; k0 += 16){
    __syncthreads();
    As[ak+0][ar]=a0.x; As[ak+1][ar]=a0.y; As[ak+2][ar]=a0.z; As[ak+3][ar]=a0.w;
    As[ak+4][ar]=a1.x; As[ak+5][ar]=a1.y; As[ak+6][ar]=a1.z; As[ak+7][ar]=a1.w;
    Bs[ak+0][ar]=w0.x; Bs[ak+1][ar]=w0.y; Bs[ak+2][ar]=w0.z; Bs[ak+3][ar]=w0.w;
    Bs[ak+4][ar]=w1.x; Bs[ak+5][ar]=w1.y; Bs[ak+6][ar]=w1.z; Bs[ak+7][ar]=w1.w;
    if (k0 + 16 < K){
      a0 = *(const float4*)(Ap + k0 + 16);
      a1 = *(const float4*)(Ap + k0 + 20);
      w0 = *(const float4*)(Wp + k0 + 16);
      w1 = *(const float4*)(Wp + k0 + 20);
    }
    __syncthreads();
#pragma unroll
    for (int kk=0; kk<16; kk++){
      float4 bf0 = *(const float4*)&Bs[kk][cn];
      float4 bf1 = *(const float4*)&Bs[kk][cn+4];
      float4 af0 = *(const float4*)&As[kk][cm];
      float4 af1 = *(const float4*)&As[kk][cm+4];
      unsigned long long bp0 = pack2(bf0.x, bf0.y);
      unsigned long long bp1 = pack2(bf0.z, bf0.w);
      unsigned long long bp2 = pack2(bf1.x, bf1.y);
      unsigned long long bp3 = pack2(bf1.z, bf1.w);
      float am[8] = {af0.x,af0.y,af0.z,af0.w,af1.x,af1.y,af1.z,af1.w};
#pragma unroll
      for (int i=0;i<8;i++){
        unsigned long long ap = pack2(am[i], am[i]);
        acc[i][0] = fma2(ap, bp0, acc[i][0]);
        acc[i][1] = fma2(ap, bp1, acc[i][1]);
        acc[i][2] = fma2(ap, bp2, acc[i][2]);
        acc[i][3] = fma2(ap, bp3, acc[i][3]);
      }
    }
  }
#pragma unroll
  for (int i=0;i<8;i++){
    float* crow = C + (size_t)(m0+cm+i)*ldc + n0 + cn;
#pragma unroll
    for (int j=0;j<4;j++){
      float2 v = unpack2(acc[i][j]);
      float x0 = v.x*scale, x1 = v.y*scale;
      if (bias){ x0 += bias[n0+cn+2*j]; x1 += bias[n0+cn+2*j+1]; }
      if (act){ x0 = tanhf(x0); x1 = tanhf(x1); }
      *(float2*)(crow + 2*j) = make_float2(x0, x1);
    }
  }
}

// ---------------- small standalone GEMM (decoder h0 init only) ---------------
__global__ __launch_bounds__(256) void k_gemm_small(
    const float* __restrict__ A, int lda,
    const float* __restrict__ W, int ldw,
    const float* __restrict__ bias,
    float* __restrict__ C, int ldc, int K, int act)
{
  __shared__ __align__(16) float As[16][68];
  __shared__ __align__(16) float Bs[16][36];
  int t = threadIdx.x;
  int n0 = blockIdx.x * 32;
  int ar = t & 63, ak = (t >> 6) << 2;
  int wr = t & 31, wk = ((t & 127) >> 5) << 2;
  const float* Ap = A + (size_t)ar*lda + ak;
  const float* Wp = W + (size_t)(n0 + wr)*ldw + wk;
  int tx = t & 15, ty = t >> 4;
  int cm = ty * 4, cn = tx * 2;
  float acc[4][2] = {{0.f,0.f},{0.f,0.f},{0.f,0.f},{0.f,0.f}};
  for (int k0 = 0; k0 < K; k0 += 16){
    float4 av = *(const float4*)(Ap + k0);
    float4 wv = make_float4(0.f,0.f,0.f,0.f);
    if (t < 128) wv = *(const float4*)(Wp + k0);
    __syncthreads();
    As[ak+0][ar]=av.x; As[ak+1][ar]=av.y; As[ak+2][ar]=av.z; As[ak+3][ar]=av.w;
    if (t < 128){ Bs[wk+0][wr]=wv.x; Bs[wk+1][wr]=wv.y; Bs[wk+2][wr]=wv.z; Bs[wk+3][wr]=wv.w; }
    __syncthreads();
#pragma unroll
    for (int kk=0; kk<16; kk++){
      float4 af = *(const float4*)&As[kk][cm];
      float2 bf = *(const float2*)&Bs[kk][cn];
      acc[0][0] += af.x*bf.x; acc[0][1] += af.x*bf.y;
      acc[1][0] += af.y*bf.x; acc[1][1] += af.y*bf.y;
      acc[2][0] += af.z*bf.x; acc[2][1] += af.z*bf.y;
      acc[3][0] += af.w*bf.x; acc[3][1] += af.w*bf.y;
    }
  }
#pragma unroll
  for (int i=0;i<4;i++)
#pragma unroll
    for (int j=0;j<2;j++){
      float v = acc[i][j];
      if (bias) v += bias[n0+cn+j];
      if (act) v = tanhf(v);
      C[(size_t)(cm+i)*ldc + n0 + cn + j] = v;
    }
}

// ---------------- hf|hb concat -----------------------------------------------
__global__ void k_hfhb(const float* __restrict__ est, float* __restrict__ hfhb){
  int i = blockIdx.x*blockDim.x + threadIdx.x;
  int b = i >> 10, k = i & 1023;
  hfhb[i] = (k < 512) ? est[b*512 + k] : est[(64 + b)*512 + (k - 512)];
}

// ---------------- persistent encoder scan ------------------------------------
__global__ __launch_bounds__(256) void k_enc_scan(
    const float* __restrict__ xp, const float* __restrict__ uc,
    const float* __restrict__ bn, float* __restrict__ est,
    float* __restrict__ out, unsigned* __restrict__ bar)
{
  __shared__ __align__(16) float As[16][68];
  __shared__ __align__(16) float Bs[16][36];
  int bx = blockIdx.x, t = threadIdx.x;
  unsigned nb = 0;
  float* P = g_P;
  for (int i = bx*256 + t; i < 65536; i += NBLK*256) est[i] = 0.f;
  nb += NBLK; gbar(bar, nb);
  int m0 = (bx & 1) * 64, n0 = (bx >> 1) * 32;
  for (int step = 0; step < 48; step++){
    tile64x32(As, Bs, est, 512, m0, uc, 512, n0, 0, 512, P, 1536, m0, n0);
    nb += NBLK; gbar(bar, nb);
    // float4-vectorized elementwise GRU (16384 work items)
    int w = bx*256 + t;
    if (w < 16384){
      int r = w >> 7, j4 = (w & 127) << 2;
      int b = r & 63, fwd = (r < 64);
      int tpos = fwd ? step : 47 - step;
      const float* xrow = xp + ((size_t)tpos*64 + b)*1536;
      const float* prow = P + (size_t)r*1536;
      float4 xr = *(const float4*)(xrow + j4);
      float4 xz = *(const float4*)(xrow + 512 + j4);
      float4 xn = *(const float4*)(xrow + 1024 + j4);
      float4 pr = *(const float4*)(prow + j4);
      float4 pz = *(const float4*)(prow + 512 + j4);
      float4 pn = *(const float4*)(prow + 1024 + j4);
      float4 bnv = *(const float4*)(bn + j4);
      float4 h  = *(const float4*)(est + r*512 + j4);
      float4 hn;
      hn.x = gru1(xr.x,xz.x,xn.x,pr.x,pz.x,pn.x,bnv.x,h.x);
      hn.y = gru1(xr.y,xz.y,xn.y,pr.y,pz.y,pn.y,bnv.y,h.y);
      hn.z = gru1(xr.z,xz.z,xn.z,pr.z,pz.z,pn.z,bnv.z,h.z);
      hn.w = gru1(xr.w,xz.w,xn.w,pr.w,pz.w,pn.w,bnv.w,h.w);
      *(float4*)(est + r*512 + j4) = hn;
      *(float4*)(out + ((size_t)tpos*64 + b)*1024 + (fwd ? 0 : 512) + j4) = hn;
    }
    nb += NBLK; gbar(bar, nb);
  }
}

// ---------------- persistent decoder scan ------------------------------------
__global__ __launch_bounds__(256) void k_dec_scan(
    const float* __restrict__ xpx, const float* __restrict__ dw,
    const float* __restrict__ bn, float* __restrict__ dst,
    const float* __restrict__ hw, const float* __restrict__ henc,
    const int* __restrict__ src, const float* __restrict__ acw,
    float* __restrict__ hts, unsigned* __restrict__ bar)
{
  __shared__ __align__(16) float As[16][68];
  __shared__ __align__(16) float Bs[16][36];
  __shared__ __align__(16) float hsm[512];
  __shared__ float ssm[48];
  __shared__ float sinv;
  int bx = blockIdx.x, t = threadIdx.x;
  unsigned nb = 0;
  float* G = g_G; float* cc = g_cc; float* cp = g_cp;
  for (int i = bx*256 + t; i < 32768; i += NBLK*256) dst[i] = 0.f;
  nb += NBLK; gbar(bar, nb);
  int gA = bx & 1, nA = (bx >> 1) * 32;
  int ksC = bx / 16, nC = (bx & 15) * 32;
  for (int step = 0; step < 48; step++){
    tile64x32(As, Bs, dst, 512, gA*64, dw, 512, gA*1536 + nA, 0, 512,
              G, 1536, gA*64, nA);
    nb += NBLK; gbar(bar, nb);
    if (bx < 64){
      int b = bx;
      const float* xrow = xpx + ((size_t)step*64 + b)*1536;
      const float* g0 = G + (size_t)b*1536;
      const float* g1 = G + (size_t)(64 + b)*1536;
      if (t < 128){
        int j4 = t << 2;
        float4 xr = *(const float4*)(xrow + j4);
        float4 xz = *(const float4*)(xrow + 512 + j4);
        float4 xn = *(const float4*)(xrow + 1024 + j4);
        float4 ar0 = *(const float4*)(g0 + j4);
        float4 az0 = *(const float4*)(g0 + 512 + j4);
        float4 an0 = *(const float4*)(g0 + 1024 + j4);
        float4 ar1 = *(const float4*)(g1 + j4);
        float4 az1 = *(const float4*)(g1 + 512 + j4);
        float4 an1 = *(const float4*)(g1 + 1024 + j4);
        float4 bnv = *(const float4*)(bn + j4);
        float4 h   = *(const float4*)(dst + (size_t)(64 + b)*512 + j4);
        float4 hn;
        hn.x = gru1(xr.x+ar0.x, xz.x+az0.x, xn.x+an0.x, ar1.x, az1.x, an1.x, bnv.x, h.x);
        hn.y = gru1(xr.y+ar0.y, xz.y+az0.y, xn.y+an0.y, ar1.y, az1.y, an1.y, bnv.y, h.y);
        hn.z = gru1(xr.z+ar0.z, xz.z+az0.z, xn.z+an0.z, ar1.z, az1.z, an1.z, bnv.z, h.z);
        hn.w = gru1(xr.w+ar0.w, xz.w+az0.w, xn.w+an0.w, ar1.w, az1.w, an1.w, bnv.w, h.w);
        *(float4*)(dst + (size_t)(64 + b)*512 + j4) = hn;
        *(float4*)&hsm[j4] = hn;
        *(float4*)(cc + (size_t)b*1536 + j4) = hn;
      }
      __syncthreads();
      int w = t >> 5, lane = t & 31;
      for (int tp = w; tp < 48; tp += 8){
        const float* hwrow = hw + ((size_t)tp*64 + b)*512;
        float s = 0.f;
#pragma unroll
        for (int j = lane*4; j < 512; j += 128){
          float4 a = *(const float4*)&hsm[j];
          float4 q = *(const float4*)(hwrow + j);
          s += a.x*q.x + a.y*q.y + a.z*q.z + a.w*q.w;
        }
#pragma unroll
        for (int o = 16; o; o >>= 1) s += __shfl_xor_sync(0xffffffffu, s, o);
        if (lane == 0) ssm[tp] = (src[tp*64 + b] == 0) ? -1e9f : s;
      }
      __syncthreads();
      if (t == 0){
        float mx = -1e30f;
        for (int i2 = 0; i2 < 48; i2++) mx = fmaxf(mx, ssm[i2]);
        float sum = 0.f;
        for (int i2 = 0; i2 < 48; i2++){ float e = __expf(ssm[i2]-mx); ssm[i2]=e; sum+=e; }
        sinv = 1.f/sum;
      }
      __syncthreads();
      {
        int d4 = t << 2;   // 256 threads x 4 = 1024 dims
        float4 a4 = make_float4(0.f,0.f,0.f,0.f);
#pragma unroll 4
        for (int tp = 0; tp < 48; tp++){
          float e = ssm[tp];
          float4 hv = *(const float4*)(henc + ((size_t)tp*64 + b)*1024 + d4);
          a4.x += e*hv.x; a4.y += e*hv.y; a4.z += e*hv.z; a4.w += e*hv.w;
        }
        float si = sinv;
        *(float4*)(cc + (size_t)b*1536 + 512 + d4) =
            make_float4(a4.x*si, a4.y*si, a4.z*si, a4.w*si);
      }
    }
    nb += NBLK; gbar(bar, nb);
    tile64x32(As, Bs, cc, 1536, 0, acw, 1536, nC, ksC*256, 256,
              cp + (size_t)ksC*32768, 512, 0, nC);
    nb += NBLK; gbar(bar, nb);
    {
      int w = bx*256 + t;     // 8192 float4 items
      if (w < 8192){
        int i4 = w << 2;
        float4 v0 = *(const float4*)(cp + i4);
        float4 v1 = *(const float4*)(cp + 32768 + i4);
        float4 v2 = *(const float4*)(cp + 2*32768 + i4);
        float4 v3 = *(const float4*)(cp + 3*32768 + i4);
        float4 v4 = *(const float4*)(cp + 4*32768 + i4);
        float4 v5 = *(const float4*)(cp + 5*32768 + i4);
        float4 r;
        r.x = tanhf(v0.x+v1.x+v2.x+v3.x+v4.x+v5.x);
        r.y = tanhf(v0.y+v1.y+v2.y+v3.y+v4.y+v5.y);
        r.z = tanhf(v0.z+v1.z+v2.z+v3.z+v4.z+v5.z);
        r.w = tanhf(v0.w+v1.w+v2.w+v3.w+v4.w+v5.w);
        *(float4*)(dst + i4) = r;
        *(float4*)(hts + (size_t)step*32768 + i4) = r;
      }
    }
    nb += NBLK; gbar(bar, nb);
  }
}

// ---------------- logits: mma.sync bf16-split GEMM ---------------------------
#define LG_PAD 72                      // smem row stride in bf16 (144B)
#define LG_TILE_B (128*LG_PAD*2)       // 18432 B per tile
#define LG_SMEM_TOTAL (4*LG_TILE_B)    // A0 B0 A1 B1 = 73728 B

__device__ __forceinline__ void ldsm4(uint32_t* r, uint32_t addr){
  asm volatile("ldmatrix.sync.aligned.m8n8.x4.shared.b16 {%0,%1,%2,%3}, [%4];"
               : "=r"(r[0]), "=r"(r[1]), "=r"(r[2]), "=r"(r[3]) : "r"(addr));
}
__device__ __forceinline__ void mma16816(float* d, const uint32_t* a,
                                         uint32_t b0, uint32_t b1){
  asm volatile("mma.sync.aligned.m16n8k16.row.col.f32.bf16.bf16.f32 "
               "{%0,%1,%2,%3}, {%4,%5,%6,%7}, {%8,%9}, {%0,%1,%2,%3};"
               : "+f"(d[0]), "+f"(d[1]), "+f"(d[2]), "+f"(d[3])
               : "r"(a[0]), "r"(a[1]), "r"(a[2]), "r"(a[3]), "r"(b0), "r"(b1));
}
__device__ __forceinline__ void cpasync16(uint32_t dst, const void* src){
  asm volatile("cp.async.ca.shared.global [%0], [%1], 16;" :: "r"(dst), "l"(src));
}

__global__ __launch_bounds__(256) void k_logits_mma(
    const __nv_bfloat16* __restrict__ A, const __nv_bfloat16* __restrict__ B,
    float* __restrict__ C)
{
  extern __shared__ __align__(16) char smem[];
  uint32_t sb = smem_u32(smem);
  uint32_t sA[2] = { sb,                sb + 2*LG_TILE_B };
  uint32_t sBs[2]= { sb + LG_TILE_B,    sb + 3*LG_TILE_B };
  int t = threadIdx.x, lane = t & 31, wid = t >> 5;
  int m0 = blockIdx.y * 128, n0 = blockIdx.x * 128;
  int wm = (wid & 3) * 32, wn = (wid >> 2) * 64;

  int lrow = t >> 3, lc8 = (t & 7) * 8;
  const __nv_bfloat16* Ap = A + (size_t)(m0 + lrow)*1536 + lc8;
  const __nv_bfloat16* Bp = B + (size_t)(n0 + lrow)*1536 + lc8;
  uint32_t sAo = (uint32_t)((lrow*LG_PAD + lc8)*2);
  uint32_t sBo = sAo;

  float acc[2][8][4];
#pragma unroll
  for (int i=0;i<2;i++)
#pragma unroll
    for (int j=0;j<8;j++)
#pragma unroll
      for (int k=0;k<4;k++) acc[i][j][k] = 0.f;

  int lrow16 = lane & 15;
  int lcolk8 = (lane >> 4) << 3;

#pragma unroll
  for (int p = 0; p < 4; p++){
    cpasync16(sA[0] + sAo + (uint32_t)(p*32*LG_PAD*2), Ap + (size_t)p*32*1536);
    cpasync16(sBs[0]+ sBo + (uint32_t)(p*32*LG_PAD*2), Bp + (size_t)p*32*1536);
  }
  asm volatile("cp.async.commit_group;");

  for (int c = 0; c < 24; c++){
    int buf = c & 1;
    if (c < 23){
      int kc = (c + 1) * 64;
#pragma unroll
      for (int p = 0; p < 4; p++){
        cpasync16(sA[buf^1] + sAo + (uint32_t)(p*32*LG_PAD*2),
                  Ap + (size_t)p*32*1536 + kc);
        cpasync16(sBs[buf^1]+ sBo + (uint32_t)(p*32*LG_PAD*2),
                  Bp + (size_t)p*32*1536 + kc);
      }
      asm volatile("cp.async.commit_group;");
      asm volatile("cp.async.wait_group 1;");
    } else {
      asm volatile("cp.async.wait_group 0;");
    }
    __syncthreads();
#pragma unroll
    for (int kk = 0; kk < 4; kk++){
      int col = kk*16 + lcolk8;
      uint32_t af[2][4], bfr[4][4];
#pragma unroll
      for (int mi = 0; mi < 2; mi++){
        uint32_t addr = sA[buf] + (uint32_t)(((wm + mi*16 + lrow16)*LG_PAD + col)*2);
        ldsm4(af[mi], addr);
      }
#pragma unroll
      for (int nj = 0; nj < 4; nj++){
        uint32_t addr = sBs[buf] + (uint32_t)(((wn + nj*16 + lrow16)*LG_PAD + col)*2);
        ldsm4(bfr[nj], addr);
      }
#pragma unroll
      for (int mi = 0; mi < 2; mi++)
#pragma unroll
        for (int n8 = 0; n8 < 8; n8++){
          int nj = n8 >> 1, sel = n8 & 1;
          mma16816(acc[mi][n8], af[mi], bfr[nj][sel], bfr[nj][sel + 2]);
        }
    }
    __syncthreads();
  }

  int r4 = lane >> 2, c2 = (lane & 3) * 2;
#pragma unroll
  for (int mi = 0; mi < 2; mi++){
#pragma unroll
    for (int n8 = 0; n8 < 8; n8++){
      int row = m0 + wm + mi*16 + r4;
      int col = n0 + wn + n8*8 + c2;
      *(float2*)(C + (size_t)row*32000 + col) =
          make_float2(acc[mi][n8][0], acc[mi][n8][1]);
      *(float2*)(C + (size_t)(row + 8)*32000 + col) =
          make_float2(acc[mi][n8][2], acc[mi][n8][3]);
    }
  }
}

// =============================================================================
extern "C" void kernel_launch(void* const* d_in, const int* in_sizes, int n_in,
                              void* d_out, int out_size){
  const int*   src  = (const int*)  d_in[0];
  const int*   tgt  = (const int*)  d_in[1];
  const float* emb  = (const float*)d_in[2];
  const float* e0Wih=(const float*)d_in[3];  const float* e0bih=(const float*)d_in[4];
  const float* e0Ur =(const float*)d_in[5];  const float* e0Uz =(const float*)d_in[6];
  const float* e0Un =(const float*)d_in[7];  const float* e0bn =(const float*)d_in[8];
  const float* e1Wih=(const float*)d_in[9];  const float* e1bih=(const float*)d_in[10];
  const float* e1Ur =(const float*)d_in[11]; const float* e1Uz =(const float*)d_in[12];
  const float* e1Un =(const float*)d_in[13]; const float* e1bn =(const float*)d_in[14];
  const float* fcw  =(const float*)d_in[15]; const float* fcb  =(const float*)d_in[16];
  const float* Wa   =(const float*)d_in[17]; const float* acw  =(const float*)d_in[18];
  const float* dWih =(const float*)d_in[19]; const float* dbih =(const float*)d_in[20];
  const float* dUr  =(const float*)d_in[21]; const float* dUz  =(const float*)d_in[22];
  const float* dUn  =(const float*)d_in[23]; const float* dbn  =(const float*)d_in[24];
  const float* outw =(const float*)d_in[25];
  float* out = (float*)d_out;

  float *se,*te,*xp0,*l0,*xp1,*henc,*hw,*xpx,*hts,*uc0,*uc1,*dw,*wat,*est,*dst,*hfhb;
  unsigned* bc; __nv_bfloat16 *aw,*bw;
  cudaGetSymbolAddress((void**)&se,  g_src_emb);
  cudaGetSymbolAddress((void**)&te,  g_tgt_emb);
  cudaGetSymbolAddress((void**)&xp0, g_xp0);
  cudaGetSymbolAddress((void**)&l0,  g_l0);
  cudaGetSymbolAddress((void**)&xp1, g_xp1);
  cudaGetSymbolAddress((void**)&henc,g_henc);
  cudaGetSymbolAddress((void**)&hw,  g_hw);
  cudaGetSymbolAddress((void**)&xpx, g_xpx);
  cudaGetSymbolAddress((void**)&hts, g_hts);
  cudaGetSymbolAddress((void**)&uc0, g_uc0);
  cudaGetSymbolAddress((void**)&uc1, g_uc1);
  cudaGetSymbolAddress((void**)&dw,  g_dw);
  cudaGetSymbolAddress((void**)&wat, g_wat);
  cudaGetSymbolAddress((void**)&est, g_est);
  cudaGetSymbolAddress((void**)&dst, g_dst);
  cudaGetSymbolAddress((void**)&hfhb,g_hfhb);
  cudaGetSymbolAddress((void**)&bc,  g_barc);
  cudaGetSymbolAddress((void**)&aw,  g_aw);
  cudaGetSymbolAddress((void**)&bw,  g_bw);

  cudaFuncSetAttribute(k_logits_mma, cudaFuncAttributeMaxDynamicSharedMemorySize,
                       LG_SMEM_TOTAL);

  // 1 gather, 2 prep, 3 xp0, 4 enc0, 5 xp1, 6 enc1  <- ncu -s 5 captures enc1
  k_gather<<<2*NTB, 128>>>(src, tgt, emb, se, te);
  k_prep<<<1792, 256>>>(e0Ur,e0Uz,e0Un, e1Ur,e1Uz,e1Un, dUr,dUz,dUn, dWih, Wa,
                        uc0, uc1, dw, wat);
  k_gemm_big<<<dim3(12,24), 256>>>(se, 512, e0Wih, 512, e0bih, xp0, 1536, 512, 1.f, 0);
  k_enc_scan<<<NBLK, 256>>>(xp0, uc0, e0bn, est, l0, bc + 0);
  k_gemm_big<<<dim3(12,24), 256>>>(l0, 1024, e1Wih, 1024, e1bih, xp1, 1536, 1024, 1.f, 0);
  k_enc_scan<<<NBLK, 256>>>(xp1, uc1, e1bn, est, henc, bc + 1);

  // B' split (independent; needed only before logits)
  k_wsplit<<<64000, 256>>>(outw, bw);

  // [hf|hb] ; h0
  k_hfhb<<<256, 256>>>(est, hfhb);
  k_gemm_small<<<16, 256>>>(hfhb, 1024, fcw, 1024, fcb, dst + 64*512, 512, 1024, 1);

  // HW ; XPx
  k_gemm_big<<<dim3(4,24), 256>>>(henc, 1024, wat, 1024, (const float*)nullptr,
                                  hw, 512, 1024, 0.03125f, 0);
  k_gemm_big<<<dim3(12,24), 256>>>(te, 512, dWih, 1024, dbih, xpx, 1536, 512, 1.f, 0);

  // decoder scan
  k_dec_scan<<<NBLK, 256>>>(xpx, dw, dbn, dst, hw, henc, src, acw, hts, bc + 2);

  // A' split ; logits via mma.sync
  k_asplit<<<6144, 256>>>(hts, aw);
  k_logits_mma<<<dim3(250, 24), 256, LG_SMEM_TOTAL>>>(aw, bw, out);
}

// round 14
// speedup vs baseline: 1.4803x; 1.0018x over previous
#include <cuda_runtime.h>
#include <cuda_bf16.h>
#include <math.h>
#include <stdint.h>

// Problem: V=32000, H=512, TS=TT=48, B=64, PAD=0
// Output: logits (48,64,32000) f32

#define NTB (48*64)            // 3072 time-batch rows
#define NBLK 96                // persistent grid size (<=148 SMs -> all resident)

// ---------------- scratch (static device globals; no allocation) -------------
__device__ __align__(256) float g_src_emb[NTB*512];
__device__ __align__(256) float g_tgt_emb[NTB*512];
__device__ __align__(256) float g_xp0[NTB*1536];
__device__ __align__(256) float g_l0 [NTB*1024];
__device__ __align__(256) float g_xp1[NTB*1536];
__device__ __align__(256) float g_henc[NTB*1024];
__device__ __align__(256) float g_hw [NTB*512];
__device__ __align__(256) float g_xpx[NTB*1536];
__device__ __align__(256) float g_hts[NTB*512];
__device__ __align__(256) float g_uc0[1536*512];
__device__ __align__(256) float g_uc1[1536*512];
__device__ __align__(256) float g_dw [3072*512];   // [WihH(1536); dUr;dUz;dUn]
__device__ __align__(256) float g_wat[512*1024];   // Wa transposed (n,k)
__device__ __align__(256) float g_est[128*512];    // enc state
__device__ __align__(256) float g_dst[128*512];    // dec state: rows0-63 ht, 64-127 h
__device__ __align__(256) float g_hfhb[64*1024];
__device__ __align__(256) float g_P [128*1536];
__device__ __align__(256) float g_G [128*1536];
__device__ __align__(256) float g_cc[64*1536];
__device__ __align__(256) float g_cp[6*64*512];
__device__ unsigned g_barc[4];
// bf16-split operands for the tensor-core logits GEMM
__device__ __align__(256) __nv_bfloat16 g_aw[3072*1536];    // A' = [hi | lo | hi]
__device__ __align__(256) __nv_bfloat16 g_bw[32000u*1536];  // B' = [hi | hi | lo]

// ---------------- scalar helpers ---------------------------------------------
__device__ __forceinline__ unsigned long long fma2(unsigned long long a,
                                                   unsigned long long b,
                                                   unsigned long long c){
  unsigned long long d;
  asm("fma.rn.f32x2 %0, %1, %2, %3;" : "=l"(d) : "l"(a), "l"(b), "l"(c));
  return d;
}
__device__ __forceinline__ unsigned long long pack2(float x, float y){
  unsigned long long d;
  asm("mov.b64 %0, {%1, %2};" : "=l"(d) : "f"(x), "f"(y));
  return d;
}
__device__ __forceinline__ float2 unpack2(unsigned long long v){
  float2 r;
  asm("mov.b64 {%0, %1}, %2;" : "=f"(r.x), "=f"(r.y) : "l"(v));
  return r;
}
__device__ __forceinline__ float sigmf(float x){ return 1.f/(1.f+__expf(-x)); }
__device__ __forceinline__ float gru1(float xr, float xz, float xn,
                                      float pr, float pz, float pn,
                                      float bn, float h){
  float rg = sigmf(xr + pr);
  float zg = sigmf(xz + pz);
  float ng = tanhf(xn + rg*(pn + bn));
  return (1.f - zg)*ng + zg*h;
}

__device__ __forceinline__ void gbar(unsigned* cnt, unsigned target){
  __syncthreads();
  if (threadIdx.x == 0){
    __threadfence();
    atomicAdd(cnt, 1u);
    volatile unsigned* vc = (volatile unsigned*)cnt;
    while (*vc < target) {}
    __threadfence();
  }
  __syncthreads();
}

__device__ __forceinline__ uint32_t smem_u32(const void* p){
  uint32_t a;
  asm("{ .reg .u64 t; cvta.to.shared.u64 t, %1; cvt.u32.u64 %0, t; }" : "=r"(a) : "l"(p));
  return a;
}

// ---- 64x32 tile GEMM (f32x2 FFMA), software-pipelined global loads ----------
__device__ __forceinline__ void tile64x32(
    float (*As)[68], float (*Bs)[36],
    const float* __restrict__ A, int lda, int m0,
    const float* __restrict__ W, int ldw, int wrow0,
    int kstart, int K,
    float* __restrict__ C, int ldc, int cm0, int cn0)
{
  int t = threadIdx.x;
  int ar = t & 63, ak = (t >> 6) << 2;
  int wr = t & 31, wk = ((t & 127) >> 5) << 2;
  const float* Ap = A + (size_t)(m0 + ar)*lda + kstart + ak;
  const float* Wp = W + (size_t)(wrow0 + wr)*ldw + kstart + wk;
  int cm = (t >> 4) << 2, cn = (t & 15) << 1;
  unsigned long long a00=0ull, a01=0ull, a10=0ull, a11=0ull;
  float4 av = *(const float4*)(Ap);
  float4 wv = make_float4(0.f,0.f,0.f,0.f);
  if (t < 128) wv = *(const float4*)(Wp);
  for (int k0 = 0; k0 < K; k0 += 16){
    __syncthreads();
    As[ak+0][ar]=av.x; As[ak+1][ar]=av.y; As[ak+2][ar]=av.z; As[ak+3][ar]=av.w;
    if (t < 128){ Bs[wk+0][wr]=wv.x; Bs[wk+1][wr]=wv.y; Bs[wk+2][wr]=wv.z; Bs[wk+3][wr]=wv.w; }
    if (k0 + 16 < K){
      av = *(const float4*)(Ap + k0 + 16);
      if (t < 128) wv = *(const float4*)(Wp + k0 + 16);
    }
    __syncthreads();
#pragma unroll
    for (int kk = 0; kk < 16; kk++){
      float4 af = *(const float4*)&As[kk][cm];
      float2 bf = *(const float2*)&Bs[kk][cn];
      unsigned long long ap0 = pack2(af.x, af.y);
      unsigned long long ap1 = pack2(af.z, af.w);
      unsigned long long b0  = pack2(bf.x, bf.x);
      unsigned long long b1  = pack2(bf.y, bf.y);
      a00 = fma2(ap0, b0, a00); a10 = fma2(ap1, b0, a10);
      a01 = fma2(ap0, b1, a01); a11 = fma2(ap1, b1, a11);
    }
  }
  float2 v;
  v = unpack2(a00); C[(size_t)(cm0+cm+0)*ldc + cn0+cn]   = v.x; C[(size_t)(cm0+cm+1)*ldc + cn0+cn]   = v.y;
  v = unpack2(a10); C[(size_t)(cm0+cm+2)*ldc + cn0+cn]   = v.x; C[(size_t)(cm0+cm+3)*ldc + cn0+cn]   = v.y;
  v = unpack2(a01); C[(size_t)(cm0+cm+0)*ldc + cn0+cn+1] = v.x; C[(size_t)(cm0+cm+1)*ldc + cn0+cn+1] = v.y;
  v = unpack2(a11); C[(size_t)(cm0+cm+2)*ldc + cn0+cn+1] = v.x; C[(size_t)(cm0+cm+3)*ldc + cn0+cn+1] = v.y;
}

// ---------------- embedding gather -------------------------------------------
__global__ void k_gather(const int* __restrict__ src, const int* __restrict__ tgt,
                         const float* __restrict__ emb,
                         float* __restrict__ se, float* __restrict__ te){
  int idx = blockIdx.x;
  int is_src = idx < NTB;
  int i = is_src ? idx : idx - NTB;
  int token = is_src ? src[i] : tgt[i];
  const float4* erow = (const float4*)(emb + (size_t)token*512);
  float4* orow = (float4*)((is_src ? se : te) + (size_t)i*512);
  orow[threadIdx.x] = erow[threadIdx.x];
}

// ---------------- weight prep (+ barrier counter reset) ----------------------
__global__ void k_prep(const float* e0Ur, const float* e0Uz, const float* e0Un,
                       const float* e1Ur, const float* e1Uz, const float* e1Un,
                       const float* dUr, const float* dUz, const float* dUn,
                       const float* dWih, const float* Wa,
                       float* uc0, float* uc1, float* dw, float* wat){
  if (blockIdx.x == 0 && threadIdx.x < 4) g_barc[threadIdx.x] = 0u;
  const int n1 = 1536*512;
  const int n2 = 3072*512;
  const int n3 = 512*1024;
  int total = 2*n1 + n2 + n3;
  for (int i = blockIdx.x*blockDim.x + threadIdx.x; i < total;
       i += gridDim.x*blockDim.x){
    if (i < n1){
      int g = i / 262144, r = i % 262144;
      uc0[i] = g==0 ? e0Ur[r] : (g==1 ? e0Uz[r] : e0Un[r]);
    } else if (i < 2*n1){
      int j = i - n1; int g = j / 262144, r = j % 262144;
      uc1[j] = g==0 ? e1Ur[r] : (g==1 ? e1Uz[r] : e1Un[r]);
    } else if (i < 2*n1 + n2){
      int j = i - 2*n1; int row = j >> 9, k = j & 511;
      float v;
      if      (row < 1536) v = dWih[(size_t)row*1024 + 512 + k];
      else if (row < 2048) v = dUr[(row-1536)*512 + k];
      else if (row < 2560) v = dUz[(row-2048)*512 + k];
      else                 v = dUn[(row-2560)*512 + k];
      dw[j] = v;
    } else {
      int j = i - 2*n1 - n2; int nn = j >> 10, k = j & 1023;
      wat[j] = Wa[(size_t)k*512 + nn];
    }
  }
}

// ---------------- bf16 hi/lo splits ------------------------------------------
__global__ void k_wsplit(const float* __restrict__ w, __nv_bfloat16* __restrict__ bw){
  size_t i = (size_t)blockIdx.x*blockDim.x + threadIdx.x;   // 32000*512
  if (i >= 32000u*512) return;
  size_t n = i >> 9, k = i & 511;
  float x = w[i];
  __nv_bfloat16 hi = __float2bfloat16(x);
  __nv_bfloat16 lo = __float2bfloat16(x - __bfloat162float(hi));
  __nv_bfloat16* row = bw + n*1536;
  row[k] = hi; row[512 + k] = hi; row[1024 + k] = lo;
}
__global__ void k_asplit(const float* __restrict__ a, __nv_bfloat16* __restrict__ aw){
  size_t i = (size_t)blockIdx.x*blockDim.x + threadIdx.x;   // 3072*512
  if (i >= 3072u*512) return;
  size_t m = i >> 9, k = i & 511;
  float x = a[i];
  __nv_bfloat16 hi = __float2bfloat16(x);
  __nv_bfloat16 lo = __float2bfloat16(x - __bfloat162float(hi));
  __nv_bfloat16* row = aw + m*1536;
  row[k] = hi; row[512 + k] = lo; row[1024 + k] = hi;
}

// ---------------- big GEMM (FFMA2, pipelined) for projections ----------------
__global__ __launch_bounds__(256) void k_gemm_big(
    const float* __restrict__ A, int lda,
    const float* __restrict__ W, int ldw,
    const float* __restrict__ bias,
    float* __restrict__ C, int ldc,
    int K, float scale, int act)
{
  __shared__ __align__(16) float As[16][136];
  __shared__ __align__(16) float Bs[16][136];
  int t = threadIdx.x;
  int m0 = blockIdx.y * 128, n0 = blockIdx.x * 128;
  int ar = t >> 1, ak = (t & 1) * 8;
  const float* Ap = A + (size_t)(m0 + ar)*lda + ak;
  const float* Wp = W + (size_t)(n0 + ar)*ldw + ak;
  int tx = t & 15, ty = t >> 4;
  int cm = ty * 8, cn = tx * 8;
  unsigned long long acc[8][4];
#pragma unroll
  for (int i=0;i<8;i++)
#pragma unroll
    for (int j=0;j<4;j++) acc[i][j] = 0ull;

  float4 a0 = *(const float4*)(Ap);
  float4 a1 = *(const float4*)(Ap + 4);
  float4 w0 = *(const float4*)(Wp);
  float4 w1 = *(const float4*)(Wp + 4);
  for (int k0 = 0; k0 < K; k0 += 16){
    __syncthreads();
    As[ak+0][ar]=a0.x; As[ak+1][ar]=a0.y; As[ak+2][ar]=a0.z; As[ak+3][ar]=a0.w;
    As[ak+4][ar]=a1.x; As[ak+5][ar]=a1.y; As[ak+6][ar]=a1.z; As[ak+7][ar]=a1.w;
    Bs[ak+0][ar]=w0.x; Bs[ak+1][ar]=w0.y; Bs[ak+2][ar]=w0.z; Bs[ak+3][ar]=w0.w;
    Bs[ak+4][ar]=w1.x; Bs[ak+5][ar]=w1.y; Bs[ak+6][ar]=w1.z; Bs[ak+7][ar]=w1.w;
    if (k0 + 16 < K){
      a0 = *(const float4*)(Ap + k0 + 16);
      a1 = *(const float4*)(Ap + k0 + 20);
      w0 = *(const float4*)(Wp + k0 + 16);
      w1 = *(const float4*)(Wp + k0 + 20);
    }
    __syncthreads();
#pragma unroll
    for (int kk=0; kk<16; kk++){
      float4 bf0 = *(const float4*)&Bs[kk][cn];
      float4 bf1 = *(const float4*)&Bs[kk][cn+4];
      float4 af0 = *(const float4*)&As[kk][cm];
      float4 af1 = *(const float4*)&As[kk][cm+4];
      unsigned long long bp0 = pack2(bf0.x, bf0.y);
      unsigned long long bp1 = pack2(bf0.z, bf0.w);
      unsigned long long bp2 = pack2(bf1.x, bf1.y);
      unsigned long long bp3 = pack2(bf1.z, bf1.w);
      float am[8] = {af0.x,af0.y,af0.z,af0.w,af1.x,af1.y,af1.z,af1.w};
#pragma unroll
      for (int i=0;i<8;i++){
        unsigned long long ap = pack2(am[i], am[i]);
        acc[i][0] = fma2(ap, bp0, acc[i][0]);
        acc[i][1] = fma2(ap, bp1, acc[i][1]);
        acc[i][2] = fma2(ap, bp2, acc[i][2]);
        acc[i][3] = fma2(ap, bp3, acc[i][3]);
      }
    }
  }
#pragma unroll
  for (int i=0;i<8;i++){
    float* crow = C + (size_t)(m0+cm+i)*ldc + n0 + cn;
#pragma unroll
    for (int j=0;j<4;j++){
      float2 v = unpack2(acc[i][j]);
      float x0 = v.x*scale, x1 = v.y*scale;
      if (bias){ x0 += bias[n0+cn+2*j]; x1 += bias[n0+cn+2*j+1]; }
      if (act){ x0 = tanhf(x0); x1 = tanhf(x1); }
      *(float2*)(crow + 2*j) = make_float2(x0, x1);
    }
  }
}

// ---------------- small standalone GEMM (decoder h0 init only) ---------------
__global__ __launch_bounds__(256) void k_gemm_small(
    const float* __restrict__ A, int lda,
    const float* __restrict__ W, int ldw,
    const float* __restrict__ bias,
    float* __restrict__ C, int ldc, int K, int act)
{
  __shared__ __align__(16) float As[16][68];
  __shared__ __align__(16) float Bs[16][36];
  int t = threadIdx.x;
  int n0 = blockIdx.x * 32;
  int ar = t & 63, ak = (t >> 6) << 2;
  int wr = t & 31, wk = ((t & 127) >> 5) << 2;
  const float* Ap = A + (size_t)ar*lda + ak;
  const float* Wp = W + (size_t)(n0 + wr)*ldw + wk;
  int tx = t & 15, ty = t >> 4;
  int cm = ty * 4, cn = tx * 2;
  float acc[4][2] = {{0.f,0.f},{0.f,0.f},{0.f,0.f},{0.f,0.f}};
  for (int k0 = 0; k0 < K; k0 += 16){
    float4 av = *(const float4*)(Ap + k0);
    float4 wv = make_float4(0.f,0.f,0.f,0.f);
    if (t < 128) wv = *(const float4*)(Wp + k0);
    __syncthreads();
    As[ak+0][ar]=av.x; As[ak+1][ar]=av.y; As[ak+2][ar]=av.z; As[ak+3][ar]=av.w;
    if (t < 128){ Bs[wk+0][wr]=wv.x; Bs[wk+1][wr]=wv.y; Bs[wk+2][wr]=wv.z; Bs[wk+3][wr]=wv.w; }
    __syncthreads();
#pragma unroll
    for (int kk=0; kk<16; kk++){
      float4 af = *(const float4*)&As[kk][cm];
      float2 bf = *(const float2*)&Bs[kk][cn];
      acc[0][0] += af.x*bf.x; acc[0][1] += af.x*bf.y;
      acc[1][0] += af.y*bf.x; acc[1][1] += af.y*bf.y;
      acc[2][0] += af.z*bf.x; acc[2][1] += af.z*bf.y;
      acc[3][0] += af.w*bf.x; acc[3][1] += af.w*bf.y;
    }
  }
#pragma unroll
  for (int i=0;i<4;i++)
#pragma unroll
    for (int j=0;j<2;j++){
      float v = acc[i][j];
      if (bias) v += bias[n0+cn+j];
      if (act) v = tanhf(v);
      C[(size_t)(cm+i)*ldc + n0 + cn + j] = v;
    }
}

// ---------------- hf|hb concat -----------------------------------------------
__global__ void k_hfhb(const float* __restrict__ est, float* __restrict__ hfhb){
  int i = blockIdx.x*blockDim.x + threadIdx.x;
  int b = i >> 10, k = i & 1023;
  hfhb[i] = (k < 512) ? est[b*512 + k] : est[(64 + b)*512 + (k - 512)];
}

// ---------------- persistent encoder scan ------------------------------------
__global__ __launch_bounds__(256) void k_enc_scan(
    const float* __restrict__ xp, const float* __restrict__ uc,
    const float* __restrict__ bn, float* __restrict__ est,
    float* __restrict__ out, unsigned* __restrict__ bar)
{
  __shared__ __align__(16) float As[16][68];
  __shared__ __align__(16) float Bs[16][36];
  int bx = blockIdx.x, t = threadIdx.x;
  unsigned nb = 0;
  float* P = g_P;
  for (int i = bx*256 + t; i < 65536; i += NBLK*256) est[i] = 0.f;
  nb += NBLK; gbar(bar, nb);
  int m0 = (bx & 1) * 64, n0 = (bx >> 1) * 32;
  for (int step = 0; step < 48; step++){
    tile64x32(As, Bs, est, 512, m0, uc, 512, n0, 0, 512, P, 1536, m0, n0);
    nb += NBLK; gbar(bar, nb);
    // float4-vectorized elementwise GRU (16384 work items)
    int w = bx*256 + t;
    if (w < 16384){
      int r = w >> 7, j4 = (w & 127) << 2;
      int b = r & 63, fwd = (r < 64);
      int tpos = fwd ? step : 47 - step;
      const float* xrow = xp + ((size_t)tpos*64 + b)*1536;
      const float* prow = P + (size_t)r*1536;
      float4 xr = *(const float4*)(xrow + j4);
      float4 xz = *(const float4*)(xrow + 512 + j4);
      float4 xn = *(const float4*)(xrow + 1024 + j4);
      float4 pr = *(const float4*)(prow + j4);
      float4 pz = *(const float4*)(prow + 512 + j4);
      float4 pn = *(const float4*)(prow + 1024 + j4);
      float4 bnv = *(const float4*)(bn + j4);
      float4 h  = *(const float4*)(est + r*512 + j4);
      float4 hn;
      hn.x = gru1(xr.x,xz.x,xn.x,pr.x,pz.x,pn.x,bnv.x,h.x);
      hn.y = gru1(xr.y,xz.y,xn.y,pr.y,pz.y,pn.y,bnv.y,h.y);
      hn.z = gru1(xr.z,xz.z,xn.z,pr.z,pz.z,pn.z,bnv.z,h.z);
      hn.w = gru1(xr.w,xz.w,xn.w,pr.w,pz.w,pn.w,bnv.w,h.w);
      *(float4*)(est + r*512 + j4) = hn;
      *(float4*)(out + ((size_t)tpos*64 + b)*1024 + (fwd ? 0 : 512) + j4) = hn;
    }
    nb += NBLK; gbar(bar, nb);
  }
}

// ---------------- persistent decoder scan ------------------------------------
__global__ __launch_bounds__(256) void k_dec_scan(
    const float* __restrict__ xpx, const float* __restrict__ dw,
    const float* __restrict__ bn, float* __restrict__ dst,
    const float* __restrict__ hw, const float* __restrict__ henc,
    const int* __restrict__ src, const float* __restrict__ acw,
    float* __restrict__ hts, unsigned* __restrict__ bar)
{
  __shared__ __align__(16) float As[16][68];
  __shared__ __align__(16) float Bs[16][36];
  __shared__ __align__(16) float hsm[512];
  __shared__ float ssm[48];
  __shared__ float sinv;
  int bx = blockIdx.x, t = threadIdx.x;
  unsigned nb = 0;
  float* G = g_G; float* cc = g_cc; float* cp = g_cp;
  for (int i = bx*256 + t; i < 32768; i += NBLK*256) dst[i] = 0.f;
  nb += NBLK; gbar(bar, nb);
  int gA = bx & 1, nA = (bx >> 1) * 32;
  int ksC = bx / 16, nC = (bx & 15) * 32;
  for (int step = 0; step < 48; step++){
    tile64x32(As, Bs, dst, 512, gA*64, dw, 512, gA*1536 + nA, 0, 512,
              G, 1536, gA*64, nA);
    nb += NBLK; gbar(bar, nb);
    if (bx < 64){
      int b = bx;
      const float* xrow = xpx + ((size_t)step*64 + b)*1536;
      const float* g0 = G + (size_t)b*1536;
      const float* g1 = G + (size_t)(64 + b)*1536;
      if (t < 128){
        int j4 = t << 2;
        float4 xr = *(const float4*)(xrow + j4);
        float4 xz = *(const float4*)(xrow + 512 + j4);
        float4 xn = *(const float4*)(xrow + 1024 + j4);
        float4 ar0 = *(const float4*)(g0 + j4);
        float4 az0 = *(const float4*)(g0 + 512 + j4);
        float4 an0 = *(const float4*)(g0 + 1024 + j4);
        float4 ar1 = *(const float4*)(g1 + j4);
        float4 az1 = *(const float4*)(g1 + 512 + j4);
        float4 an1 = *(const float4*)(g1 + 1024 + j4);
        float4 bnv = *(const float4*)(bn + j4);
        float4 h   = *(const float4*)(dst + (size_t)(64 + b)*512 + j4);
        float4 hn;
        hn.x = gru1(xr.x+ar0.x, xz.x+az0.x, xn.x+an0.x, ar1.x, az1.x, an1.x, bnv.x, h.x);
        hn.y = gru1(xr.y+ar0.y, xz.y+az0.y, xn.y+an0.y, ar1.y, az1.y, an1.y, bnv.y, h.y);
        hn.z = gru1(xr.z+ar0.z, xz.z+az0.z, xn.z+an0.z, ar1.z, az1.z, an1.z, bnv.z, h.z);
        hn.w = gru1(xr.w+ar0.w, xz.w+az0.w, xn.w+an0.w, ar1.w, az1.w, an1.w, bnv.w, h.w);
        *(float4*)(dst + (size_t)(64 + b)*512 + j4) = hn;
        *(float4*)&hsm[j4] = hn;
        *(float4*)(cc + (size_t)b*1536 + j4) = hn;
      }
      __syncthreads();
      int w = t >> 5, lane = t & 31;
      for (int tp = w; tp < 48; tp += 8){
        const float* hwrow = hw + ((size_t)tp*64 + b)*512;
        float s = 0.f;
#pragma unroll
        for (int j = lane*4; j < 512; j += 128){
          float4 a = *(const float4*)&hsm[j];
          float4 q = *(const float4*)(hwrow + j);
          s += a.x*q.x + a.y*q.y + a.z*q.z + a.w*q.w;
        }
#pragma unroll
        for (int o = 16; o; o >>= 1) s += __shfl_xor_sync(0xffffffffu, s, o);
        if (lane == 0) ssm[tp] = (src[tp*64 + b] == 0) ? -1e9f : s;
      }
      __syncthreads();
      if (t == 0){
        float mx = -1e30f;
        for (int i2 = 0; i2 < 48; i2++) mx = fmaxf(mx, ssm[i2]);
        float sum = 0.f;
        for (int i2 = 0; i2 < 48; i2++){ float e = __expf(ssm[i2]-mx); ssm[i2]=e; sum+=e; }
        sinv = 1.f/sum;
      }
      __syncthreads();
      {
        int d4 = t << 2;   // 256 threads x 4 = 1024 dims
        float4 a4 = make_float4(0.f,0.f,0.f,0.f);
#pragma unroll 4
        for (int tp = 0; tp < 48; tp++){
          float e = ssm[tp];
          float4 hv = *(const float4*)(henc + ((size_t)tp*64 + b)*1024 + d4);
          a4.x += e*hv.x; a4.y += e*hv.y; a4.z += e*hv.z; a4.w += e*hv.w;
        }
        float si = sinv;
        *(float4*)(cc + (size_t)b*1536 + 512 + d4) =
            make_float4(a4.x*si, a4.y*si, a4.z*si, a4.w*si);
      }
    }
    nb += NBLK; gbar(bar, nb);
    tile64x32(As, Bs, cc, 1536, 0, acw, 1536, nC, ksC*256, 256,
              cp + (size_t)ksC*32768, 512, 0, nC);
    nb += NBLK; gbar(bar, nb);
    {
      int w = bx*256 + t;     // 8192 float4 items
      if (w < 8192){
        int i4 = w << 2;
        float4 v0 = *(const float4*)(cp + i4);
        float4 v1 = *(const float4*)(cp + 32768 + i4);
        float4 v2 = *(const float4*)(cp + 2*32768 + i4);
        float4 v3 = *(const float4*)(cp + 3*32768 + i4);
        float4 v4 = *(const float4*)(cp + 4*32768 + i4);
        float4 v5 = *(const float4*)(cp + 5*32768 + i4);
        float4 r;
        r.x = tanhf(v0.x+v1.x+v2.x+v3.x+v4.x+v5.x);
        r.y = tanhf(v0.y+v1.y+v2.y+v3.y+v4.y+v5.y);
        r.z = tanhf(v0.z+v1.z+v2.z+v3.z+v4.z+v5.z);
        r.w = tanhf(v0.w+v1.w+v2.w+v3.w+v4.w+v5.w);
        *(float4*)(dst + i4) = r;
        *(float4*)(hts + (size_t)step*32768 + i4) = r;
      }
    }
    nb += NBLK; gbar(bar, nb);
  }
}

// ---------------- logits: mma.sync bf16-split GEMM ---------------------------
#define LG_PAD 72                      // smem row stride in bf16 (144B)
#define LG_TILE_B (128*LG_PAD*2)       // 18432 B per tile
#define LG_SMEM_TOTAL (4*LG_TILE_B)    // A0 B0 A1 B1 = 73728 B

__device__ __forceinline__ void ldsm4(uint32_t* r, uint32_t addr){
  asm volatile("ldmatrix.sync.aligned.m8n8.x4.shared.b16 {%0,%1,%2,%3}, [%4];"
               : "=r"(r[0]), "=r"(r[1]), "=r"(r[2]), "=r"(r[3]) : "r"(addr));
}
__device__ __forceinline__ void mma16816(float* d, const uint32_t* a,
                                         uint32_t b0, uint32_t b1){
  asm volatile("mma.sync.aligned.m16n8k16.row.col.f32.bf16.bf16.f32 "
               "{%0,%1,%2,%3}, {%4,%5,%6,%7}, {%8,%9}, {%0,%1,%2,%3};"
               : "+f"(d[0]), "+f"(d[1]), "+f"(d[2]), "+f"(d[3])
               : "r"(a[0]), "r"(a[1]), "r"(a[2]), "r"(a[3]), "r"(b0), "r"(b1));
}
__device__ __forceinline__ void cpasync16(uint32_t dst, const void* src){
  asm volatile("cp.async.ca.shared.global [%0], [%1], 16;" :: "r"(dst), "l"(src));
}

__global__ __launch_bounds__(256) void k_logits_mma(
    const __nv_bfloat16* __restrict__ A, const __nv_bfloat16* __restrict__ B,
    float* __restrict__ C)
{
  extern __shared__ __align__(16) char smem[];
  uint32_t sb = smem_u32(smem);
  uint32_t sA[2] = { sb,                sb + 2*LG_TILE_B };
  uint32_t sBs[2]= { sb + LG_TILE_B,    sb + 3*LG_TILE_B };
  int t = threadIdx.x, lane = t & 31, wid = t >> 5;
  int m0 = blockIdx.y * 128, n0 = blockIdx.x * 128;
  int wm = (wid & 3) * 32, wn = (wid >> 2) * 64;

  int lrow = t >> 3, lc8 = (t & 7) * 8;
  const __nv_bfloat16* Ap = A + (size_t)(m0 + lrow)*1536 + lc8;
  const __nv_bfloat16* Bp = B + (size_t)(n0 + lrow)*1536 + lc8;
  uint32_t sAo = (uint32_t)((lrow*LG_PAD + lc8)*2);
  uint32_t sBo = sAo;

  float acc[2][8][4];
#pragma unroll
  for (int i=0;i<2;i++)
#pragma unroll
    for (int j=0;j<8;j++)
#pragma unroll
      for (int k=0;k<4;k++) acc[i][j][k] = 0.f;

  int lrow16 = lane & 15;
  int lcolk8 = (lane >> 4) << 3;

#pragma unroll
  for (int p = 0; p < 4; p++){
    cpasync16(sA[0] + sAo + (uint32_t)(p*32*LG_PAD*2), Ap + (size_t)p*32*1536);
    cpasync16(sBs[0]+ sBo + (uint32_t)(p*32*LG_PAD*2), Bp + (size_t)p*32*1536);
  }
  asm volatile("cp.async.commit_group;");

  for (int c = 0; c < 24; c++){
    int buf = c & 1;
    if (c < 23){
      int kc = (c + 1) * 64;
#pragma unroll
      for (int p = 0; p < 4; p++){
        cpasync16(sA[buf^1] + sAo + (uint32_t)(p*32*LG_PAD*2),
                  Ap + (size_t)p*32*1536 + kc);
        cpasync16(sBs[buf^1]+ sBo + (uint32_t)(p*32*LG_PAD*2),
                  Bp + (size_t)p*32*1536 + kc);
      }
      asm volatile("cp.async.commit_group;");
      asm volatile("cp.async.wait_group 1;");
    } else {
      asm volatile("cp.async.wait_group 0;");
    }
    __syncthreads();
#pragma unroll
    for (int kk = 0; kk < 4; kk++){
      int col = kk*16 + lcolk8;
      uint32_t af[2][4], bfr[4][4];
#pragma unroll
      for (int mi = 0; mi < 2; mi++){
        uint32_t addr = sA[buf] + (uint32_t)(((wm + mi*16 + lrow16)*LG_PAD + col)*2);
        ldsm4(af[mi], addr);
      }
#pragma unroll
      for (int nj = 0; nj < 4; nj++){
        uint32_t addr = sBs[buf] + (uint32_t)(((wn + nj*16 + lrow16)*LG_PAD + col)*2);
        ldsm4(bfr[nj], addr);
      }
#pragma unroll
      for (int mi = 0; mi < 2; mi++)
#pragma unroll
        for (int n8 = 0; n8 < 8; n8++){
          int nj = n8 >> 1, sel = n8 & 1;
          mma16816(acc[mi][n8], af[mi], bfr[nj][sel], bfr[nj][sel + 2]);
        }
    }
    __syncthreads();
  }

  int r4 = lane >> 2, c2 = (lane & 3) * 2;
#pragma unroll
  for (int mi = 0; mi < 2; mi++){
#pragma unroll
    for (int n8 = 0; n8 < 8; n8++){
      int row = m0 + wm + mi*16 + r4;
      int col = n0 + wn + n8*8 + c2;
      *(float2*)(C + (size_t)row*32000 + col) =
          make_float2(acc[mi][n8][0], acc[mi][n8][1]);
      *(float2*)(C + (size_t)(row + 8)*32000 + col) =
          make_float2(acc[mi][n8][2], acc[mi][n8][3]);
    }
  }
}

// =============================================================================
extern "C" void kernel_launch(void* const* d_in, const int* in_sizes, int n_in,
                              void* d_out, int out_size){
  const int*   src  = (const int*)  d_in[0];
  const int*   tgt  = (const int*)  d_in[1];
  const float* emb  = (const float*)d_in[2];
  const float* e0Wih=(const float*)d_in[3];  const float* e0bih=(const float*)d_in[4];
  const float* e0Ur =(const float*)d_in[5];  const float* e0Uz =(const float*)d_in[6];
  const float* e0Un =(const float*)d_in[7];  const float* e0bn =(const float*)d_in[8];
  const float* e1Wih=(const float*)d_in[9];  const float* e1bih=(const float*)d_in[10];
  const float* e1Ur =(const float*)d_in[11]; const float* e1Uz =(const float*)d_in[12];
  const float* e1Un =(const float*)d_in[13]; const float* e1bn =(const float*)d_in[14];
  const float* fcw  =(const float*)d_in[15]; const float* fcb  =(const float*)d_in[16];
  const float* Wa   =(const float*)d_in[17]; const float* acw  =(const float*)d_in[18];
  const float* dWih =(const float*)d_in[19]; const float* dbih =(const float*)d_in[20];
  const float* dUr  =(const float*)d_in[21]; const float* dUz  =(const float*)d_in[22];
  const float* dUn  =(const float*)d_in[23]; const float* dbn  =(const float*)d_in[24];
  const float* outw =(const float*)d_in[25];
  float* out = (float*)d_out;

  float *se,*te,*xp0,*l0,*xp1,*henc,*hw,*xpx,*hts,*uc0,*uc1,*dw,*wat,*est,*dst,*hfhb;
  unsigned* bc; __nv_bfloat16 *aw,*bw;
  cudaGetSymbolAddress((void**)&se,  g_src_emb);
  cudaGetSymbolAddress((void**)&te,  g_tgt_emb);
  cudaGetSymbolAddress((void**)&xp0, g_xp0);
  cudaGetSymbolAddress((void**)&l0,  g_l0);
  cudaGetSymbolAddress((void**)&xp1, g_xp1);
  cudaGetSymbolAddress((void**)&henc,g_henc);
  cudaGetSymbolAddress((void**)&hw,  g_hw);
  cudaGetSymbolAddress((void**)&xpx, g_xpx);
  cudaGetSymbolAddress((void**)&hts, g_hts);
  cudaGetSymbolAddress((void**)&uc0, g_uc0);
  cudaGetSymbolAddress((void**)&uc1, g_uc1);
  cudaGetSymbolAddress((void**)&dw,  g_dw);
  cudaGetSymbolAddress((void**)&wat, g_wat);
  cudaGetSymbolAddress((void**)&est, g_est);
  cudaGetSymbolAddress((void**)&dst, g_dst);
  cudaGetSymbolAddress((void**)&hfhb,g_hfhb);
  cudaGetSymbolAddress((void**)&bc,  g_barc);
  cudaGetSymbolAddress((void**)&aw,  g_aw);
  cudaGetSymbolAddress((void**)&bw,  g_bw);

  cudaFuncSetAttribute(k_logits_mma, cudaFuncAttributeMaxDynamicSharedMemorySize,
                       LG_SMEM_TOTAL);

  // 1 gather, 2 prep, 3 xp0, 4 enc0, 5 xp1, 6 enc1  <- ncu -s 5 captures enc1
  k_gather<<<2*NTB, 128>>>(src, tgt, emb, se, te);
  k_prep<<<1792, 256>>>(e0Ur,e0Uz,e0Un, e1Ur,e1Uz,e1Un, dUr,dUz,dUn, dWih, Wa,
                        uc0, uc1, dw, wat);
  k_gemm_big<<<dim3(12,24), 256>>>(se, 512, e0Wih, 512, e0bih, xp0, 1536, 512, 1.f, 0);
  k_enc_scan<<<NBLK, 256>>>(xp0, uc0, e0bn, est, l0, bc + 0);
  k_gemm_big<<<dim3(12,24), 256>>>(l0, 1024, e1Wih, 1024, e1bih, xp1, 1536, 1024, 1.f, 0);
  k_enc_scan<<<NBLK, 256>>>(xp1, uc1, e1bn, est, henc, bc + 1);

  // B' split (independent; needed only before logits)
  k_wsplit<<<64000, 256>>>(outw, bw);

  // [hf|hb] ; h0
  k_hfhb<<<256, 256>>>(est, hfhb);
  k_gemm_small<<<16, 256>>>(hfhb, 1024, fcw, 1024, fcb, dst + 64*512, 512, 1024, 1);

  // HW ; XPx
  k_gemm_big<<<dim3(4,24), 256>>>(henc, 1024, wat, 1024, (const float*)nullptr,
                                  hw, 512, 1024, 0.03125f, 0);
  k_gemm_big<<<dim3(12,24), 256>>>(te, 512, dWih, 1024, dbih, xpx, 1536, 512, 1.f, 0);

  // decoder scan
  k_dec_scan<<<NBLK, 256>>>(xpx, dw, dbn, dst, hw, henc, src, acw, hts, bc + 2);

  // A' split ; logits via mma.sync
  k_asplit<<<6144, 256>>>(hts, aw);
  k_logits_mma<<<dim3(250, 24), 256, LG_SMEM_TOTAL>>>(aw, bw, out);
}

// round 15
// speedup vs baseline: 1.6551x; 1.1181x over previous
#include <cuda_runtime.h>
#include <cuda_bf16.h>
#include <math.h>
#include <stdint.h>

// Problem: V=32000, H=512, TS=TT=48, B=64, PAD=0. Output: logits (48,64,32000) f32

#define NTB (48*64)
#define NBLK 96     // decoder persistent grid
#define NBE 128     // encoder persistent grid

// ---------------- scratch ----------------------------------------------------
__device__ __align__(256) float g_src_emb[NTB*512];
__device__ __align__(256) float g_tgt_emb[NTB*512];
__device__ __align__(256) float g_xp0[NTB*1536];
__device__ __align__(256) float g_l0 [NTB*1024];
__device__ __align__(256) float g_xp1[NTB*1536];
__device__ __align__(256) float g_henc[NTB*1024];
__device__ __align__(256) float g_hw [NTB*512];
__device__ __align__(256) float g_xpx[NTB*1536];
__device__ __align__(256) float g_hts[NTB*512];
__device__ __align__(256) float g_uc0[1536*512];
__device__ __align__(256) float g_uc1[1536*512];
__device__ __align__(256) float g_dw [3072*512];
__device__ __align__(256) float g_wat[512*1024];
__device__ __align__(256) float g_est [128*512];   // enc state ping (final here)
__device__ __align__(256) float g_est2[128*512];   // enc state pong
__device__ __align__(256) float g_dst[128*512];    // dec: rows0-63 ht, 64-127 h
__device__ __align__(256) float g_hfhb[64*1024];
__device__ __align__(256) float g_G [128*1536];
__device__ __align__(256) float g_cc[64*1536];
__device__ __align__(256) float g_cp[6*64*512];
__device__ unsigned g_barc[4];
__device__ __align__(256) __nv_bfloat16 g_aw[3072*1536];
__device__ __align__(256) __nv_bfloat16 g_bw[32000u*1536];

// ---------------- helpers ----------------------------------------------------
__device__ __forceinline__ unsigned long long fma2(unsigned long long a,
                                                   unsigned long long b,
                                                   unsigned long long c){
  unsigned long long d;
  asm("fma.rn.f32x2 %0, %1, %2, %3;" : "=l"(d) : "l"(a), "l"(b), "l"(c));
  return d;
}
__device__ __forceinline__ unsigned long long pack2(float x, float y){
  unsigned long long d;
  asm("mov.b64 %0, {%1, %2};" : "=l"(d) : "f"(x), "f"(y));
  return d;
}
__device__ __forceinline__ float2 unpack2(unsigned long long v){
  float2 r;
  asm("mov.b64 {%0, %1}, %2;" : "=f"(r.x), "=f"(r.y) : "l"(v));
  return r;
}
__device__ __forceinline__ float hadd2(unsigned long long v){
  float2 r = unpack2(v); return r.x + r.y;
}
__device__ __forceinline__ float sigmf(float x){ return 1.f/(1.f+__expf(-x)); }
__device__ __forceinline__ float gru1(float xr, float xz, float xn,
                                      float pr, float pz, float pn,
                                      float bn, float h){
  float rg = sigmf(xr + pr);
  float zg = sigmf(xz + pz);
  float ng = tanhf(xn + rg*(pn + bn));
  return (1.f - zg)*ng + zg*h;
}
__device__ __forceinline__ void gbar(unsigned* cnt, unsigned target){
  __syncthreads();
  if (threadIdx.x == 0){
    __threadfence();
    atomicAdd(cnt, 1u);
    volatile unsigned* vc = (volatile unsigned*)cnt;
    while (*vc < target) {}
    __threadfence();
  }
  __syncthreads();
}
__device__ __forceinline__ uint32_t smem_u32(const void* p){
  uint32_t a;
  asm("{ .reg .u64 t; cvta.to.shared.u64 t, %1; cvt.u32.u64 %0, t; }" : "=r"(a) : "l"(p));
  return a;
}
__device__ __forceinline__ void cpasync16(uint32_t dst, const void* src){
  asm volatile("cp.async.ca.shared.global [%0], [%1], 16;" :: "r"(dst), "l"(src));
}

// ---- 64x32 tile GEMM (decoder scan phases) ----------------------------------
__device__ __forceinline__ void tile64x32(
    float (*As)[68], float (*Bs)[36],
    const float* __restrict__ A, int lda, int m0,
    const float* __restrict__ W, int ldw, int wrow0,
    int kstart, int K,
    float* __restrict__ C, int ldc, int cm0, int cn0)
{
  int t = threadIdx.x;
  int ar = t & 63, ak = (t >> 6) << 2;
  int wr = t & 31, wk = ((t & 127) >> 5) << 2;
  const float* Ap = A + (size_t)(m0 + ar)*lda + kstart + ak;
  const float* Wp = W + (size_t)(wrow0 + wr)*ldw + kstart + wk;
  int cm = (t >> 4) << 2, cn = (t & 15) << 1;
  unsigned long long a00=0ull, a01=0ull, a10=0ull, a11=0ull;
  float4 av = *(const float4*)(Ap);
  float4 wv = make_float4(0.f,0.f,0.f,0.f);
  if (t < 128) wv = *(const float4*)(Wp);
  for (int k0 = 0; k0 < K; k0 += 16){
    __syncthreads();
    As[ak+0][ar]=av.x; As[ak+1][ar]=av.y; As[ak+2][ar]=av.z; As[ak+3][ar]=av.w;
    if (t < 128){ Bs[wk+0][wr]=wv.x; Bs[wk+1][wr]=wv.y; Bs[wk+2][wr]=wv.z; Bs[wk+3][wr]=wv.w; }
    if (k0 + 16 < K){
      av = *(const float4*)(Ap + k0 + 16);
      if (t < 128) wv = *(const float4*)(Wp + k0 + 16);
    }
    __syncthreads();
#pragma unroll
    for (int kk = 0; kk < 16; kk++){
      float4 af = *(const float4*)&As[kk][cm];
      float2 bf = *(const float2*)&Bs[kk][cn];
      unsigned long long ap0 = pack2(af.x, af.y);
      unsigned long long ap1 = pack2(af.z, af.w);
      unsigned long long b0  = pack2(bf.x, bf.x);
      unsigned long long b1  = pack2(bf.y, bf.y);
      a00 = fma2(ap0, b0, a00); a10 = fma2(ap1, b0, a10);
      a01 = fma2(ap0, b1, a01); a11 = fma2(ap1, b1, a11);
    }
  }
  float2 v;
  v = unpack2(a00); C[(size_t)(cm0+cm+0)*ldc + cn0+cn]   = v.x; C[(size_t)(cm0+cm+1)*ldc + cn0+cn]   = v.y;
  v = unpack2(a10); C[(size_t)(cm0+cm+2)*ldc + cn0+cn]   = v.x; C[(size_t)(cm0+cm+3)*ldc + cn0+cn]   = v.y;
  v = unpack2(a01); C[(size_t)(cm0+cm+0)*ldc + cn0+cn+1] = v.x; C[(size_t)(cm0+cm+1)*ldc + cn0+cn+1] = v.y;
  v = unpack2(a11); C[(size_t)(cm0+cm+2)*ldc + cn0+cn+1] = v.x; C[(size_t)(cm0+cm+3)*ldc + cn0+cn+1] = v.y;
}

// ---------------- embedding gather -------------------------------------------
__global__ void k_gather(const int* __restrict__ src, const int* __restrict__ tgt,
                         const float* __restrict__ emb,
                         float* __restrict__ se, float* __restrict__ te){
  int idx = blockIdx.x;
  int is_src = idx < NTB;
  int i = is_src ? idx : idx - NTB;
  int token = is_src ? src[i] : tgt[i];
  const float4* erow = (const float4*)(emb + (size_t)token*512);
  float4* orow = (float4*)((is_src ? se : te) + (size_t)i*512);
  orow[threadIdx.x] = erow[threadIdx.x];
}

// ---------------- weight prep ------------------------------------------------
__global__ void k_prep(const float* e0Ur, const float* e0Uz, const float* e0Un,
                       const float* e1Ur, const float* e1Uz, const float* e1Un,
                       const float* dUr, const float* dUz, const float* dUn,
                       const float* dWih, const float* Wa,
                       float* uc0, float* uc1, float* dw, float* wat){
  if (blockIdx.x == 0 && threadIdx.x < 4) g_barc[threadIdx.x] = 0u;
  const int n1 = 1536*512;
  const int n2 = 3072*512;
  const int n3 = 512*1024;
  int total = 2*n1 + n2 + n3;
  for (int i = blockIdx.x*blockDim.x + threadIdx.x; i < total;
       i += gridDim.x*blockDim.x){
    if (i < n1){
      int g = i / 262144, r = i % 262144;
      uc0[i] = g==0 ? e0Ur[r] : (g==1 ? e0Uz[r] : e0Un[r]);
    } else if (i < 2*n1){
      int j = i - n1; int g = j / 262144, r = j % 262144;
      uc1[j] = g==0 ? e1Ur[r] : (g==1 ? e1Uz[r] : e1Un[r]);
    } else if (i < 2*n1 + n2){
      int j = i - 2*n1; int row = j >> 9, k = j & 511;
      float v;
      if      (row < 1536) v = dWih[(size_t)row*1024 + 512 + k];
      else if (row < 2048) v = dUr[(row-1536)*512 + k];
      else if (row < 2560) v = dUz[(row-2048)*512 + k];
      else                 v = dUn[(row-2560)*512 + k];
      dw[j] = v;
    } else {
      int j = i - 2*n1 - n2; int nn = j >> 10, k = j & 1023;
      wat[j] = Wa[(size_t)k*512 + nn];
    }
  }
}

// ---------------- bf16 hi/lo splits ------------------------------------------
__global__ void k_wsplit(const float* __restrict__ w, __nv_bfloat16* __restrict__ bw){
  size_t i = (size_t)blockIdx.x*blockDim.x + threadIdx.x;
  if (i >= 32000u*512) return;
  size_t n = i >> 9, k = i & 511;
  float x = w[i];
  __nv_bfloat16 hi = __float2bfloat16(x);
  __nv_bfloat16 lo = __float2bfloat16(x - __bfloat162float(hi));
  __nv_bfloat16* row = bw + n*1536;
  row[k] = hi; row[512 + k] = hi; row[1024 + k] = lo;
}
__global__ void k_asplit(const float* __restrict__ a, __nv_bfloat16* __restrict__ aw){
  size_t i = (size_t)blockIdx.x*blockDim.x + threadIdx.x;
  if (i >= 3072u*512) return;
  size_t m = i >> 9, k = i & 511;
  float x = a[i];
  __nv_bfloat16 hi = __float2bfloat16(x);
  __nv_bfloat16 lo = __float2bfloat16(x - __bfloat162float(hi));
  __nv_bfloat16* row = aw + m*1536;
  row[k] = hi; row[512 + k] = lo; row[1024 + k] = hi;
}

// ---------------- big GEMM (FFMA2, pipelined) --------------------------------
__global__ __launch_bounds__(256) void k_gemm_big(
    const float* __restrict__ A, int lda,
    const float* __restrict__ W, int ldw,
    const float* __restrict__ bias,
    float* __restrict__ C, int ldc,
    int K, float scale, int act)
{
  __shared__ __align__(16) float As[16][136];
  __shared__ __align__(16) float Bs[16][136];
  int t = threadIdx.x;
  int m0 = blockIdx.y * 128, n0 = blockIdx.x * 128;
  int ar = t >> 1, ak = (t & 1) * 8;
  const float* Ap = A + (size_t)(m0 + ar)*lda + ak;
  const float* Wp = W + (size_t)(n0 + ar)*ldw + ak;
  int tx = t & 15, ty = t >> 4;
  int cm = ty * 8, cn = tx * 8;
  unsigned long long acc[8][4];
#pragma unroll
  for (int i=0;i<8;i++)
#pragma unroll
    for (int j=0;j<4;j++) acc[i][j] = 0ull;

  float4 a0 = *(const float4*)(Ap);
  float4 a1 = *(const float4*)(Ap + 4);
  float4 w0 = *(const float4*)(Wp);
  float4 w1 = *(const float4*)(Wp + 4);
  for (int k0 = 0; k0 < K; k0 += 16){
    __syncthreads();
    As[ak+0][ar]=a0.x; As[ak+1][ar]=a0.y; As[ak+2][ar]=a0.z; As[ak+3][ar]=a0.w;
    As[ak+4][ar]=a1.x; As[ak+5][ar]=a1.y; As[ak+6][ar]=a1.z; As[ak+7][ar]=a1.w;
    Bs[ak+0][ar]=w0.x; Bs[ak+1][ar]=w0.y; Bs[ak+2][ar]=w0.z; Bs[ak+3][ar]=w0.w;
    Bs[ak+4][ar]=w1.x; Bs[ak+5][ar]=w1.y; Bs[ak+6][ar]=w1.z; Bs[ak+7][ar]=w1.w;
    if (k0 + 16 < K){
      a0 = *(const float4*)(Ap + k0 + 16);
      a1 = *(const float4*)(Ap + k0 + 20);
      w0 = *(const float4*)(Wp + k0 + 16);
      w1 = *(const float4*)(Wp + k0 + 20);
    }
    __syncthreads();
#pragma unroll
    for (int kk=0; kk<16; kk++){
      float4 bf0 = *(const float4*)&Bs[kk][cn];
      float4 bf1 = *(const float4*)&Bs[kk][cn+4];
      float4 af0 = *(const float4*)&As[kk][cm];
      float4 af1 = *(const float4*)&As[kk][cm+4];
      unsigned long long bp0 = pack2(bf0.x, bf0.y);
      unsigned long long bp1 = pack2(bf0.z, bf0.w);
      unsigned long long bp2 = pack2(bf1.x, bf1.y);
      unsigned long long bp3 = pack2(bf1.z, bf1.w);
      float am[8] = {af0.x,af0.y,af0.z,af0.w,af1.x,af1.y,af1.z,af1.w};
#pragma unroll
      for (int i=0;i<8;i++){
        unsigned long long ap = pack2(am[i], am[i]);
        acc[i][0] = fma2(ap, bp0, acc[i][0]);
        acc[i][1] = fma2(ap, bp1, acc[i][1]);
        acc[i][2] = fma2(ap, bp2, acc[i][2]);
        acc[i][3] = fma2(ap, bp3, acc[i][3]);
      }
    }
  }
#pragma unroll
  for (int i=0;i<8;i++){
    float* crow = C + (size_t)(m0+cm+i)*ldc + n0 + cn;
#pragma unroll
    for (int j=0;j<4;j++){
      float2 v = unpack2(acc[i][j]);
      float x0 = v.x*scale, x1 = v.y*scale;
      if (bias){ x0 += bias[n0+cn+2*j]; x1 += bias[n0+cn+2*j+1]; }
      if (act){ x0 = tanhf(x0); x1 = tanhf(x1); }
      *(float2*)(crow + 2*j) = make_float2(x0, x1);
    }
  }
}

// ---------------- small GEMM (decoder h0 init) -------------------------------
__global__ __launch_bounds__(256) void k_gemm_small(
    const float* __restrict__ A, int lda,
    const float* __restrict__ W, int ldw,
    const float* __restrict__ bias,
    float* __restrict__ C, int ldc, int K, int act)
{
  __shared__ __align__(16) float As[16][68];
  __shared__ __align__(16) float Bs[16][36];
  int t = threadIdx.x;
  int n0 = blockIdx.x * 32;
  int ar = t & 63, ak = (t >> 6) << 2;
  int wr = t & 31, wk = ((t & 127) >> 5) << 2;
  const float* Ap = A + (size_t)ar*lda + ak;
  const float* Wp = W + (size_t)(n0 + wr)*ldw + wk;
  int tx = t & 15, ty = t >> 4;
  int cm = ty * 4, cn = tx * 2;
  float acc[4][2] = {{0.f,0.f},{0.f,0.f},{0.f,0.f},{0.f,0.f}};
  for (int k0 = 0; k0 < K; k0 += 16){
    float4 av = *(const float4*)(Ap + k0);
    float4 wv = make_float4(0.f,0.f,0.f,0.f);
    if (t < 128) wv = *(const float4*)(Wp + k0);
    __syncthreads();
    As[ak+0][ar]=av.x; As[ak+1][ar]=av.y; As[ak+2][ar]=av.z; As[ak+3][ar]=av.w;
    if (t < 128){ Bs[wk+0][wr]=wv.x; Bs[wk+1][wr]=wv.y; Bs[wk+2][wr]=wv.z; Bs[wk+3][wr]=wv.w; }
    __syncthreads();
#pragma unroll
    for (int kk=0; kk<16; kk++){
      float4 af = *(const float4*)&As[kk][cm];
      float2 bf = *(const float2*)&Bs[kk][cn];
      acc[0][0] += af.x*bf.x; acc[0][1] += af.x*bf.y;
      acc[1][0] += af.y*bf.x; acc[1][1] += af.y*bf.y;
      acc[2][0] += af.z*bf.x; acc[2][1] += af.z*bf.y;
      acc[3][0] += af.w*bf.x; acc[3][1] += af.w*bf.y;
    }
  }
#pragma unroll
  for (int i=0;i<4;i++)
#pragma unroll
    for (int j=0;j<2;j++){
      float v = acc[i][j];
      if (bias) v += bias[n0+cn+j];
      if (act) v = tanhf(v);
      C[(size_t)(cm+i)*ldc + n0 + cn + j] = v;
    }
}

// ---------------- hf|hb concat -----------------------------------------------
__global__ void k_hfhb(const float* __restrict__ est, float* __restrict__ hfhb){
  int i = blockIdx.x*blockDim.x + threadIdx.x;
  int b = i >> 10, k = i & 1023;
  hfhb[i] = (k < 512) ? est[b*512 + k] : est[(64 + b)*512 + (k - 512)];
}

// ---------------- FUSED persistent encoder scan: 1 barrier/step --------------
// 128 blocks = rhalf(2) x jtile(64 of 8 cols). U-slice (24x512) SMEM-resident
// across all 48 steps; state staged per step via double-buffered cp.async.
#define ENC_SMEM ((24*516 + 2*64*132)*4)   // 117120 B
__global__ __launch_bounds__(256) void k_enc_scan(
    const float* __restrict__ xp, const float* __restrict__ uc,
    const float* __restrict__ bn, float* __restrict__ est0,
    float* __restrict__ est1, float* __restrict__ out,
    unsigned* __restrict__ bar)
{
  extern __shared__ __align__(16) float sm[];
  float* Ws = sm;                      // 24 x 516
  float* Es = sm + 24*516;             // 2 x 64 x 132
  uint32_t es_a = smem_u32(Es);
  int bx = blockIdx.x, t = threadIdx.x;
  int rhalf = bx >> 6, jt = bx & 63, j0 = jt << 3;
  for (int idx = t; idx < 24*512; idx += 256){
    int row = idx >> 9, k = idx & 511;
    int g = row >> 3, jj = row & 7;
    Ws[row*516 + k] = uc[(size_t)(g*512 + j0 + jj)*512 + k];
  }
  for (int i = bx*256 + t; i < 65536; i += NBE*256) est0[i] = 0.f;
  unsigned nb = NBE; gbar(bar, nb);

  int rloc = t >> 2, jg = t & 3;
  int r = rhalf*64 + rloc;
  int jA = j0 + jg, jB = j0 + jg + 4;
  float bnA = bn[jA], bnB = bn[jB];
  int fwd = (rhalf == 0);
  const float* wrA = Ws + jg*516;
  const float* wzA = Ws + (8 + jg)*516;
  const float* wnA = Ws + (16 + jg)*516;
  const float* wrB = wrA + 4*516;
  const float* wzB = wzA + 4*516;
  const float* wnB = wnA + 4*516;

  for (int step = 0; step < 48; step++){
    const float* S = (step & 1) ? est1 : est0;
    float*       D = (step & 1) ? est0 : est1;
    const float* Srow = S + (size_t)rhalf*64*512;
#pragma unroll
    for (int q = 0; q < 8; q++){
      int lin = q*256 + t, row = lin >> 5, kc = (lin & 31) << 2;
      cpasync16(es_a + (uint32_t)((row*132 + kc)*4), Srow + (size_t)row*512 + kc);
    }
    asm volatile("cp.async.commit_group;");
    unsigned long long arA=0,azA=0,anA=0,arB=0,azB=0,anB=0;
#pragma unroll
    for (int c = 0; c < 4; c++){
      int buf = c & 1;
      __syncthreads();   // prev compute done before overwriting its buffer
      if (c < 3){
#pragma unroll
        for (int q = 0; q < 8; q++){
          int lin = q*256 + t, row = lin >> 5, kc = (lin & 31) << 2;
          cpasync16(es_a + (uint32_t)(((buf^1)*8448 + row*132 + kc)*4),
                    Srow + (size_t)row*512 + (c+1)*128 + kc);
        }
        asm volatile("cp.async.commit_group;");
        asm volatile("cp.async.wait_group 1;" ::: "memory");
      } else {
        asm volatile("cp.async.wait_group 0;" ::: "memory");
      }
      __syncthreads();   // chunk c visible
      const float* ep  = Es + buf*8448 + rloc*132;
      const float* w1r = wrA + c*128; const float* w2r = wrB + c*128;
      const float* w1z = wzA + c*128; const float* w2z = wzB + c*128;
      const float* w1n = wnA + c*128; const float* w2n = wnB + c*128;
#pragma unroll
      for (int kk = 0; kk < 128; kk += 4){
        ulonglong2 ev = *(const ulonglong2*)(ep + kk);
        ulonglong2 w;
        w = *(const ulonglong2*)(w1r + kk); arA = fma2(ev.x, w.x, arA); arA = fma2(ev.y, w.y, arA);
        w = *(const ulonglong2*)(w1z + kk); azA = fma2(ev.x, w.x, azA); azA = fma2(ev.y, w.y, azA);
        w = *(const ulonglong2*)(w1n + kk); anA = fma2(ev.x, w.x, anA); anA = fma2(ev.y, w.y, anA);
        w = *(const ulonglong2*)(w2r + kk); arB = fma2(ev.x, w.x, arB); arB = fma2(ev.y, w.y, arB);
        w = *(const ulonglong2*)(w2z + kk); azB = fma2(ev.x, w.x, azB); azB = fma2(ev.y, w.y, azB);
        w = *(const ulonglong2*)(w2n + kk); anB = fma2(ev.x, w.x, anB); anB = fma2(ev.y, w.y, anB);
      }
    }
    int tpos = fwd ? step : 47 - step;
    int b = rloc;
    const float* x = xp + ((size_t)tpos*64 + b)*1536;
    float hA = S[(size_t)r*512 + jA];
    float hB = S[(size_t)r*512 + jB];
    float hnA = gru1(x[jA], x[512+jA], x[1024+jA],
                     hadd2(arA), hadd2(azA), hadd2(anA), bnA, hA);
    float hnB = gru1(x[jB], x[512+jB], x[1024+jB],
                     hadd2(arB), hadd2(azB), hadd2(anB), bnB, hB);
    D[(size_t)r*512 + jA] = hnA;
    D[(size_t)r*512 + jB] = hnB;
    size_t ob = ((size_t)tpos*64 + b)*1024 + (fwd ? 0 : 512);
    out[ob + jA] = hnA;
    out[ob + jB] = hnB;
    nb += NBE; gbar(bar, nb);
  }
}

// ---------------- persistent decoder scan (unchanged structure) --------------
__global__ __launch_bounds__(256) void k_dec_scan(
    const float* __restrict__ xpx, const float* __restrict__ dw,
    const float* __restrict__ bn, float* __restrict__ dst,
    const float* __restrict__ hw, const float* __restrict__ henc,
    const int* __restrict__ src, const float* __restrict__ acw,
    float* __restrict__ hts, unsigned* __restrict__ bar)
{
  __shared__ __align__(16) float As[16][68];
  __shared__ __align__(16) float Bs[16][36];
  __shared__ __align__(16) float hsm[512];
  __shared__ float ssm[48];
  __shared__ float sinv;
  int bx = blockIdx.x, t = threadIdx.x;
  unsigned nb = 0;
  float* G = g_G; float* cc = g_cc; float* cp = g_cp;
  for (int i = bx*256 + t; i < 32768; i += NBLK*256) dst[i] = 0.f;
  nb += NBLK; gbar(bar, nb);
  int gA = bx & 1, nA = (bx >> 1) * 32;
  int ksC = bx / 16, nC = (bx & 15) * 32;
  for (int step = 0; step < 48; step++){
    tile64x32(As, Bs, dst, 512, gA*64, dw, 512, gA*1536 + nA, 0, 512,
              G, 1536, gA*64, nA);
    nb += NBLK; gbar(bar, nb);
    if (bx < 64){
      int b = bx;
      const float* xrow = xpx + ((size_t)step*64 + b)*1536;
      const float* g0 = G + (size_t)b*1536;
      const float* g1 = G + (size_t)(64 + b)*1536;
      if (t < 128){
        int j4 = t << 2;
        float4 xr = *(const float4*)(xrow + j4);
        float4 xz = *(const float4*)(xrow + 512 + j4);
        float4 xn = *(const float4*)(xrow + 1024 + j4);
        float4 ar0 = *(const float4*)(g0 + j4);
        float4 az0 = *(const float4*)(g0 + 512 + j4);
        float4 an0 = *(const float4*)(g0 + 1024 + j4);
        float4 ar1 = *(const float4*)(g1 + j4);
        float4 az1 = *(const float4*)(g1 + 512 + j4);
        float4 an1 = *(const float4*)(g1 + 1024 + j4);
        float4 bnv = *(const float4*)(bn + j4);
        float4 h   = *(const float4*)(dst + (size_t)(64 + b)*512 + j4);
        float4 hn;
        hn.x = gru1(xr.x+ar0.x, xz.x+az0.x, xn.x+an0.x, ar1.x, az1.x, an1.x, bnv.x, h.x);
        hn.y = gru1(xr.y+ar0.y, xz.y+az0.y, xn.y+an0.y, ar1.y, az1.y, an1.y, bnv.y, h.y);
        hn.z = gru1(xr.z+ar0.z, xz.z+az0.z, xn.z+an0.z, ar1.z, az1.z, an1.z, bnv.z, h.z);
        hn.w = gru1(xr.w+ar0.w, xz.w+az0.w, xn.w+an0.w, ar1.w, az1.w, an1.w, bnv.w, h.w);
        *(float4*)(dst + (size_t)(64 + b)*512 + j4) = hn;
        *(float4*)&hsm[j4] = hn;
        *(float4*)(cc + (size_t)b*1536 + j4) = hn;
      }
      __syncthreads();
      int w = t >> 5, lane = t & 31;
      for (int tp = w; tp < 48; tp += 8){
        const float* hwrow = hw + ((size_t)tp*64 + b)*512;
        float s = 0.f;
#pragma unroll
        for (int j = lane*4; j < 512; j += 128){
          float4 a = *(const float4*)&hsm[j];
          float4 q = *(const float4*)(hwrow + j);
          s += a.x*q.x + a.y*q.y + a.z*q.z + a.w*q.w;
        }
#pragma unroll
        for (int o = 16; o; o >>= 1) s += __shfl_xor_sync(0xffffffffu, s, o);
        if (lane == 0) ssm[tp] = (src[tp*64 + b] == 0) ? -1e9f : s;
      }
      __syncthreads();
      if (t == 0){
        float mx = -1e30f;
        for (int i2 = 0; i2 < 48; i2++) mx = fmaxf(mx, ssm[i2]);
        float sum = 0.f;
        for (int i2 = 0; i2 < 48; i2++){ float e = __expf(ssm[i2]-mx); ssm[i2]=e; sum+=e; }
        sinv = 1.f/sum;
      }
      __syncthreads();
      {
        int d4 = t << 2;
        float4 a4 = make_float4(0.f,0.f,0.f,0.f);
#pragma unroll 4
        for (int tp = 0; tp < 48; tp++){
          float e = ssm[tp];
          float4 hv = *(const float4*)(henc + ((size_t)tp*64 + b)*1024 + d4);
          a4.x += e*hv.x; a4.y += e*hv.y; a4.z += e*hv.z; a4.w += e*hv.w;
        }
        float si = sinv;
        *(float4*)(cc + (size_t)b*1536 + 512 + d4) =
            make_float4(a4.x*si, a4.y*si, a4.z*si, a4.w*si);
      }
    }
    nb += NBLK; gbar(bar, nb);
    tile64x32(As, Bs, cc, 1536, 0, acw, 1536, nC, ksC*256, 256,
              cp + (size_t)ksC*32768, 512, 0, nC);
    nb += NBLK; gbar(bar, nb);
    {
      int w = bx*256 + t;
      if (w < 8192){
        int i4 = w << 2;
        float4 v0 = *(const float4*)(cp + i4);
        float4 v1 = *(const float4*)(cp + 32768 + i4);
        float4 v2 = *(const float4*)(cp + 2*32768 + i4);
        float4 v3 = *(const float4*)(cp + 3*32768 + i4);
        float4 v4 = *(const float4*)(cp + 4*32768 + i4);
        float4 v5 = *(const float4*)(cp + 5*32768 + i4);
        float4 r;
        r.x = tanhf(v0.x+v1.x+v2.x+v3.x+v4.x+v5.x);
        r.y = tanhf(v0.y+v1.y+v2.y+v3.y+v4.y+v5.y);
        r.z = tanhf(v0.z+v1.z+v2.z+v3.z+v4.z+v5.z);
        r.w = tanhf(v0.w+v1.w+v2.w+v3.w+v4.w+v5.w);
        *(float4*)(dst + i4) = r;
        *(float4*)(hts + (size_t)step*32768 + i4) = r;
      }
    }
    nb += NBLK; gbar(bar, nb);
  }
}

// ---------------- logits: mma.sync bf16-split GEMM ---------------------------
#define LG_PAD 72
#define LG_TILE_B (128*LG_PAD*2)
#define LG_SMEM_TOTAL (4*LG_TILE_B)

__device__ __forceinline__ void ldsm4(uint32_t* r, uint32_t addr){
  asm volatile("ldmatrix.sync.aligned.m8n8.x4.shared.b16 {%0,%1,%2,%3}, [%4];"
               : "=r"(r[0]), "=r"(r[1]), "=r"(r[2]), "=r"(r[3]) : "r"(addr));
}
__device__ __forceinline__ void mma16816(float* d, const uint32_t* a,
                                         uint32_t b0, uint32_t b1){
  asm volatile("mma.sync.aligned.m16n8k16.row.col.f32.bf16.bf16.f32 "
               "{%0,%1,%2,%3}, {%4,%5,%6,%7}, {%8,%9}, {%0,%1,%2,%3};"
               : "+f"(d[0]), "+f"(d[1]), "+f"(d[2]), "+f"(d[3])
               : "r"(a[0]), "r"(a[1]), "r"(a[2]), "r"(a[3]), "r"(b0), "r"(b1));
}

__global__ __launch_bounds__(256) void k_logits_mma(
    const __nv_bfloat16* __restrict__ A, const __nv_bfloat16* __restrict__ B,
    float* __restrict__ C)
{
  extern __shared__ __align__(16) char smem[];
  uint32_t sb = smem_u32(smem);
  uint32_t sA[2] = { sb,                sb + 2*LG_TILE_B };
  uint32_t sBs[2]= { sb + LG_TILE_B,    sb + 3*LG_TILE_B };
  int t = threadIdx.x, lane = t & 31, wid = t >> 5;
  int m0 = blockIdx.y * 128, n0 = blockIdx.x * 128;
  int wm = (wid & 3) * 32, wn = (wid >> 2) * 64;

  int lrow = t >> 3, lc8 = (t & 7) * 8;
  const __nv_bfloat16* Ap = A + (size_t)(m0 + lrow)*1536 + lc8;
  const __nv_bfloat16* Bp = B + (size_t)(n0 + lrow)*1536 + lc8;
  uint32_t sAo = (uint32_t)((lrow*LG_PAD + lc8)*2);
  uint32_t sBo = sAo;

  float acc[2][8][4];
#pragma unroll
  for (int i=0;i<2;i++)
#pragma unroll
    for (int j=0;j<8;j++)
#pragma unroll
      for (int k=0;k<4;k++) acc[i][j][k] = 0.f;

  int lrow16 = lane & 15;
  int lcolk8 = (lane >> 4) << 3;

#pragma unroll
  for (int p = 0; p < 4; p++){
    cpasync16(sA[0] + sAo + (uint32_t)(p*32*LG_PAD*2), Ap + (size_t)p*32*1536);
    cpasync16(sBs[0]+ sBo + (uint32_t)(p*32*LG_PAD*2), Bp + (size_t)p*32*1536);
  }
  asm volatile("cp.async.commit_group;");

  for (int c = 0; c < 24; c++){
    int buf = c & 1;
    if (c < 23){
      int kc = (c + 1) * 64;
#pragma unroll
      for (int p = 0; p < 4; p++){
        cpasync16(sA[buf^1] + sAo + (uint32_t)(p*32*LG_PAD*2),
                  Ap + (size_t)p*32*1536 + kc);
        cpasync16(sBs[buf^1]+ sBo + (uint32_t)(p*32*LG_PAD*2),
                  Bp + (size_t)p*32*1536 + kc);
      }
      asm volatile("cp.async.commit_group;");
      asm volatile("cp.async.wait_group 1;");
    } else {
      asm volatile("cp.async.wait_group 0;");
    }
    __syncthreads();
#pragma unroll
    for (int kk = 0; kk < 4; kk++){
      int col = kk*16 + lcolk8;
      uint32_t af[2][4], bfr[4][4];
#pragma unroll
      for (int mi = 0; mi < 2; mi++){
        uint32_t addr = sA[buf] + (uint32_t)(((wm + mi*16 + lrow16)*LG_PAD + col)*2);
        ldsm4(af[mi], addr);
      }
#pragma unroll
      for (int nj = 0; nj < 4; nj++){
        uint32_t addr = sBs[buf] + (uint32_t)(((wn + nj*16 + lrow16)*LG_PAD + col)*2);
        ldsm4(bfr[nj], addr);
      }
#pragma unroll
      for (int mi = 0; mi < 2; mi++)
#pragma unroll
        for (int n8 = 0; n8 < 8; n8++){
          int nj = n8 >> 1, sel = n8 & 1;
          mma16816(acc[mi][n8], af[mi], bfr[nj][sel], bfr[nj][sel + 2]);
        }
    }
    __syncthreads();
  }

  int r4 = lane >> 2, c2 = (lane & 3) * 2;
#pragma unroll
  for (int mi = 0; mi < 2; mi++){
#pragma unroll
    for (int n8 = 0; n8 < 8; n8++){
      int row = m0 + wm + mi*16 + r4;
      int col = n0 + wn + n8*8 + c2;
      *(float2*)(C + (size_t)row*32000 + col) =
          make_float2(acc[mi][n8][0], acc[mi][n8][1]);
      *(float2*)(C + (size_t)(row + 8)*32000 + col) =
          make_float2(acc[mi][n8][2], acc[mi][n8][3]);
    }
  }
}

// =============================================================================
extern "C" void kernel_launch(void* const* d_in, const int* in_sizes, int n_in,
                              void* d_out, int out_size){
  const int*   src  = (const int*)  d_in[0];
  const int*   tgt  = (const int*)  d_in[1];
  const float* emb  = (const float*)d_in[2];
  const float* e0Wih=(const float*)d_in[3];  const float* e0bih=(const float*)d_in[4];
  const float* e0Ur =(const float*)d_in[5];  const float* e0Uz =(const float*)d_in[6];
  const float* e0Un =(const float*)d_in[7];  const float* e0bn =(const float*)d_in[8];
  const float* e1Wih=(const float*)d_in[9];  const float* e1bih=(const float*)d_in[10];
  const float* e1Ur =(const float*)d_in[11]; const float* e1Uz =(const float*)d_in[12];
  const float* e1Un =(const float*)d_in[13]; const float* e1bn =(const float*)d_in[14];
  const float* fcw  =(const float*)d_in[15]; const float* fcb  =(const float*)d_in[16];
  const float* Wa   =(const float*)d_in[17]; const float* acw  =(const float*)d_in[18];
  const float* dWih =(const float*)d_in[19]; const float* dbih =(const float*)d_in[20];
  const float* dUr  =(const float*)d_in[21]; const float* dUz  =(const float*)d_in[22];
  const float* dUn  =(const float*)d_in[23]; const float* dbn  =(const float*)d_in[24];
  const float* outw =(const float*)d_in[25];
  float* out = (float*)d_out;

  float *se,*te,*xp0,*l0,*xp1,*henc,*hw,*xpx,*hts,*uc0,*uc1,*dw,*wat,*est,*est2,*dst,*hfhb;
  unsigned* bc; __nv_bfloat16 *aw,*bw;
  cudaGetSymbolAddress((void**)&se,  g_src_emb);
  cudaGetSymbolAddress((void**)&te,  g_tgt_emb);
  cudaGetSymbolAddress((void**)&xp0, g_xp0);
  cudaGetSymbolAddress((void**)&l0,  g_l0);
  cudaGetSymbolAddress((void**)&xp1, g_xp1);
  cudaGetSymbolAddress((void**)&henc,g_henc);
  cudaGetSymbolAddress((void**)&hw,  g_hw);
  cudaGetSymbolAddress((void**)&xpx, g_xpx);
  cudaGetSymbolAddress((void**)&hts, g_hts);
  cudaGetSymbolAddress((void**)&uc0, g_uc0);
  cudaGetSymbolAddress((void**)&uc1, g_uc1);
  cudaGetSymbolAddress((void**)&dw,  g_dw);
  cudaGetSymbolAddress((void**)&wat, g_wat);
  cudaGetSymbolAddress((void**)&est, g_est);
  cudaGetSymbolAddress((void**)&est2,g_est2);
  cudaGetSymbolAddress((void**)&dst, g_dst);
  cudaGetSymbolAddress((void**)&hfhb,g_hfhb);
  cudaGetSymbolAddress((void**)&bc,  g_barc);
  cudaGetSymbolAddress((void**)&aw,  g_aw);
  cudaGetSymbolAddress((void**)&bw,  g_bw);

  cudaFuncSetAttribute(k_logits_mma, cudaFuncAttributeMaxDynamicSharedMemorySize,
                       LG_SMEM_TOTAL);
  cudaFuncSetAttribute(k_enc_scan, cudaFuncAttributeMaxDynamicSharedMemorySize,
                       ENC_SMEM);

  // 1 gather, 2 prep, 3 xp0, 4 enc0, 5 xp1, 6 enc1  <- ncu -s 5 captures enc1
  k_gather<<<2*NTB, 128>>>(src, tgt, emb, se, te);
  k_prep<<<1792, 256>>>(e0Ur,e0Uz,e0Un, e1Ur,e1Uz,e1Un, dUr,dUz,dUn, dWih, Wa,
                        uc0, uc1, dw, wat);
  k_gemm_big<<<dim3(12,24), 256>>>(se, 512, e0Wih, 512, e0bih, xp0, 1536, 512, 1.f, 0);
  k_enc_scan<<<NBE, 256, ENC_SMEM>>>(xp0, uc0, e0bn, est, est2, l0, bc + 0);
  k_gemm_big<<<dim3(12,24), 256>>>(l0, 1024, e1Wih, 1024, e1bih, xp1, 1536, 1024, 1.f, 0);
  k_enc_scan<<<NBE, 256, ENC_SMEM>>>(xp1, uc1, e1bn, est, est2, henc, bc + 1);

  // B' split
  k_wsplit<<<64000, 256>>>(outw, bw);

  // [hf|hb] ; h0   (48 steps even -> final encoder state is in g_est)
  k_hfhb<<<256, 256>>>(est, hfhb);
  k_gemm_small<<<16, 256>>>(hfhb, 1024, fcw, 1024, fcb, dst + 64*512, 512, 1024, 1);

  // HW ; XPx
  k_gemm_big<<<dim3(4,24), 256>>>(henc, 1024, wat, 1024, (const float*)nullptr,
                                  hw, 512, 1024, 0.03125f, 0);
  k_gemm_big<<<dim3(12,24), 256>>>(te, 512, dWih, 1024, dbih, xpx, 1536, 512, 1.f, 0);

  // decoder scan
  k_dec_scan<<<NBLK, 256>>>(xpx, dw, dbn, dst, hw, henc, src, acw, hts, bc + 2);

  // A' split ; logits
  k_asplit<<<6144, 256>>>(hts, aw);
  k_logits_mma<<<dim3(250, 24), 256, LG_SMEM_TOTAL>>>(aw, bw, out);
}

// round 16
// speedup vs baseline: 1.6585x; 1.0021x over previous
#include <cuda_runtime.h>
#include <cuda_bf16.h>
#include <math.h>
#include <stdint.h>

// Problem: V=32000, H=512, TS=TT=48, B=64, PAD=0. Output: logits (48,64,32000) f32

#define NTB (48*64)
#define NBLK 96     // decoder persistent grid
#define NBE 128     // encoder persistent grid

// ---------------- scratch ----------------------------------------------------
__device__ __align__(256) float g_src_emb[NTB*512];
__device__ __align__(256) float g_tgt_emb[NTB*512];
__device__ __align__(256) float g_xp0[NTB*1536];
__device__ __align__(256) float g_l0 [NTB*1024];
__device__ __align__(256) float g_xp1[NTB*1536];
__device__ __align__(256) float g_henc[NTB*1024];
__device__ __align__(256) float g_hw [NTB*512];
__device__ __align__(256) float g_xpx[NTB*1536];
__device__ __align__(256) float g_hts[NTB*512];
__device__ __align__(256) float g_uc0[1536*512];
__device__ __align__(256) float g_uc1[1536*512];
__device__ __align__(256) float g_dw [3072*512];
__device__ __align__(256) float g_wat[512*1024];
__device__ __align__(256) float g_est [128*512];   // enc state ping (final here)
__device__ __align__(256) float g_est2[128*512];   // enc state pong
__device__ __align__(256) float g_dst[128*512];    // dec: rows0-63 ht, 64-127 h
__device__ __align__(256) float g_hfhb[64*1024];
__device__ __align__(256) float g_G [128*1536];
__device__ __align__(256) float g_cc[64*1536];
__device__ __align__(256) float g_cp[6*64*512];
__device__ unsigned g_barc[8];
__device__ __align__(256) __nv_bfloat16 g_aw[3072*1536];
__device__ __align__(256) __nv_bfloat16 g_bw[32000u*1536];

// ---------------- helpers ----------------------------------------------------
__device__ __forceinline__ unsigned long long fma2(unsigned long long a,
                                                   unsigned long long b,
                                                   unsigned long long c){
  unsigned long long d;
  asm("fma.rn.f32x2 %0, %1, %2, %3;" : "=l"(d) : "l"(a), "l"(b), "l"(c));
  return d;
}
__device__ __forceinline__ unsigned long long pack2(float x, float y){
  unsigned long long d;
  asm("mov.b64 %0, {%1, %2};" : "=l"(d) : "f"(x), "f"(y));
  return d;
}
__device__ __forceinline__ float2 unpack2(unsigned long long v){
  float2 r;
  asm("mov.b64 {%0, %1}, %2;" : "=f"(r.x), "=f"(r.y) : "l"(v));
  return r;
}
__device__ __forceinline__ float hadd2(unsigned long long v){
  float2 r = unpack2(v); return r.x + r.y;
}
__device__ __forceinline__ float sigmf(float x){ return 1.f/(1.f+__expf(-x)); }
__device__ __forceinline__ float gru1(float xr, float xz, float xn,
                                      float pr, float pz, float pn,
                                      float bn, float h){
  float rg = sigmf(xr + pr);
  float zg = sigmf(xz + pz);
  float ng = tanhf(xn + rg*(pn + bn));
  return (1.f - zg)*ng + zg*h;
}
__device__ __forceinline__ void gbar(unsigned* cnt, unsigned target){
  __syncthreads();
  if (threadIdx.x == 0){
    __threadfence();
    atomicAdd(cnt, 1u);
    volatile unsigned* vc = (volatile unsigned*)cnt;
    while (*vc < target) {}
    __threadfence();
  }
  __syncthreads();
}
__device__ __forceinline__ uint32_t smem_u32(const void* p){
  uint32_t a;
  asm("{ .reg .u64 t; cvta.to.shared.u64 t, %1; cvt.u32.u64 %0, t; }" : "=r"(a) : "l"(p));
  return a;
}
__device__ __forceinline__ void cpasync16(uint32_t dst, const void* src){
  asm volatile("cp.async.ca.shared.global [%0], [%1], 16;" :: "r"(dst), "l"(src));
}

// ---- 64x32 tile GEMM (decoder scan phases) ----------------------------------
__device__ __forceinline__ void tile64x32(
    float (*As)[68], float (*Bs)[36],
    const float* __restrict__ A, int lda, int m0,
    const float* __restrict__ W, int ldw, int wrow0,
    int kstart, int K,
    float* __restrict__ C, int ldc, int cm0, int cn0)
{
  int t = threadIdx.x;
  int ar = t & 63, ak = (t >> 6) << 2;
  int wr = t & 31, wk = ((t & 127) >> 5) << 2;
  const float* Ap = A + (size_t)(m0 + ar)*lda + kstart + ak;
  const float* Wp = W + (size_t)(wrow0 + wr)*ldw + kstart + wk;
  int cm = (t >> 4) << 2, cn = (t & 15) << 1;
  unsigned long long a00=0ull, a01=0ull, a10=0ull, a11=0ull;
  float4 av = *(const float4*)(Ap);
  float4 wv = make_float4(0.f,0.f,0.f,0.f);
  if (t < 128) wv = *(const float4*)(Wp);
  for (int k0 = 0; k0 < K; k0 += 16){
    __syncthreads();
    As[ak+0][ar]=av.x; As[ak+1][ar]=av.y; As[ak+2][ar]=av.z; As[ak+3][ar]=av.w;
    if (t < 128){ Bs[wk+0][wr]=wv.x; Bs[wk+1][wr]=wv.y; Bs[wk+2][wr]=wv.z; Bs[wk+3][wr]=wv.w; }
    if (k0 + 16 < K){
      av = *(const float4*)(Ap + k0 + 16);
      if (t < 128) wv = *(const float4*)(Wp + k0 + 16);
    }
    __syncthreads();
#pragma unroll
    for (int kk = 0; kk < 16; kk++){
      float4 af = *(const float4*)&As[kk][cm];
      float2 bf = *(const float2*)&Bs[kk][cn];
      unsigned long long ap0 = pack2(af.x, af.y);
      unsigned long long ap1 = pack2(af.z, af.w);
      unsigned long long b0  = pack2(bf.x, bf.x);
      unsigned long long b1  = pack2(bf.y, bf.y);
      a00 = fma2(ap0, b0, a00); a10 = fma2(ap1, b0, a10);
      a01 = fma2(ap0, b1, a01); a11 = fma2(ap1, b1, a11);
    }
  }
  float2 v;
  v = unpack2(a00); C[(size_t)(cm0+cm+0)*ldc + cn0+cn]   = v.x; C[(size_t)(cm0+cm+1)*ldc + cn0+cn]   = v.y;
  v = unpack2(a10); C[(size_t)(cm0+cm+2)*ldc + cn0+cn]   = v.x; C[(size_t)(cm0+cm+3)*ldc + cn0+cn]   = v.y;
  v = unpack2(a01); C[(size_t)(cm0+cm+0)*ldc + cn0+cn+1] = v.x; C[(size_t)(cm0+cm+1)*ldc + cn0+cn+1] = v.y;
  v = unpack2(a11); C[(size_t)(cm0+cm+2)*ldc + cn0+cn+1] = v.x; C[(size_t)(cm0+cm+3)*ldc + cn0+cn+1] = v.y;
}

// ---------------- embedding gather -------------------------------------------
__global__ void k_gather(const int* __restrict__ src, const int* __restrict__ tgt,
                         const float* __restrict__ emb,
                         float* __restrict__ se, float* __restrict__ te){
  int idx = blockIdx.x;
  int is_src = idx < NTB;
  int i = is_src ? idx : idx - NTB;
  int token = is_src ? src[i] : tgt[i];
  const float4* erow = (const float4*)(emb + (size_t)token*512);
  float4* orow = (float4*)((is_src ? se : te) + (size_t)i*512);
  orow[threadIdx.x] = erow[threadIdx.x];
}

// ---------------- weight prep ------------------------------------------------
__global__ void k_prep(const float* e0Ur, const float* e0Uz, const float* e0Un,
                       const float* e1Ur, const float* e1Uz, const float* e1Un,
                       const float* dUr, const float* dUz, const float* dUn,
                       const float* dWih, const float* Wa,
                       float* uc0, float* uc1, float* dw, float* wat){
  if (blockIdx.x == 0 && threadIdx.x < 8) g_barc[threadIdx.x] = 0u;
  const int n1 = 1536*512;
  const int n2 = 3072*512;
  const int n3 = 512*1024;
  int total = 2*n1 + n2 + n3;
  for (int i = blockIdx.x*blockDim.x + threadIdx.x; i < total;
       i += gridDim.x*blockDim.x){
    if (i < n1){
      int g = i / 262144, r = i % 262144;
      uc0[i] = g==0 ? e0Ur[r] : (g==1 ? e0Uz[r] : e0Un[r]);
    } else if (i < 2*n1){
      int j = i - n1; int g = j / 262144, r = j % 262144;
      uc1[j] = g==0 ? e1Ur[r] : (g==1 ? e1Uz[r] : e1Un[r]);
    } else if (i < 2*n1 + n2){
      int j = i - 2*n1; int row = j >> 9, k = j & 511;
      float v;
      if      (row < 1536) v = dWih[(size_t)row*1024 + 512 + k];
      else if (row < 2048) v = dUr[(row-1536)*512 + k];
      else if (row < 2560) v = dUz[(row-2048)*512 + k];
      else                 v = dUn[(row-2560)*512 + k];
      dw[j] = v;
    } else {
      int j = i - 2*n1 - n2; int nn = j >> 10, k = j & 1023;
      wat[j] = Wa[(size_t)k*512 + nn];
    }
  }
}

// ---------------- bf16 hi/lo splits ------------------------------------------
__global__ void k_wsplit(const float* __restrict__ w, __nv_bfloat16* __restrict__ bw){
  size_t i = (size_t)blockIdx.x*blockDim.x + threadIdx.x;
  if (i >= 32000u*512) return;
  size_t n = i >> 9, k = i & 511;
  float x = w[i];
  __nv_bfloat16 hi = __float2bfloat16(x);
  __nv_bfloat16 lo = __float2bfloat16(x - __bfloat162float(hi));
  __nv_bfloat16* row = bw + n*1536;
  row[k] = hi; row[512 + k] = hi; row[1024 + k] = lo;
}
__global__ void k_asplit(const float* __restrict__ a, __nv_bfloat16* __restrict__ aw){
  size_t i = (size_t)blockIdx.x*blockDim.x + threadIdx.x;
  if (i >= 3072u*512) return;
  size_t m = i >> 9, k = i & 511;
  float x = a[i];
  __nv_bfloat16 hi = __float2bfloat16(x);
  __nv_bfloat16 lo = __float2bfloat16(x - __bfloat162float(hi));
  __nv_bfloat16* row = aw + m*1536;
  row[k] = hi; row[512 + k] = lo; row[1024 + k] = hi;
}

// ---------------- big GEMM (FFMA2, pipelined) --------------------------------
__global__ __launch_bounds__(256) void k_gemm_big(
    const float* __restrict__ A, int lda,
    const float* __restrict__ W, int ldw,
    const float* __restrict__ bias,
    float* __restrict__ C, int ldc,
    int K, float scale, int act)
{
  __shared__ __align__(16) float As[16][136];
  __shared__ __align__(16) float Bs[16][136];
  int t = threadIdx.x;
  int m0 = blockIdx.y * 128, n0 = blockIdx.x * 128;
  int ar = t >> 1, ak = (t & 1) * 8;
  const float* Ap = A + (size_t)(m0 + ar)*lda + ak;
  const float* Wp = W + (size_t)(n0 + ar)*ldw + ak;
  int tx = t & 15, ty = t >> 4;
  int cm = ty * 8, cn = tx * 8;
  unsigned long long acc[8][4];
#pragma unroll
  for (int i=0;i<8;i++)
#pragma unroll
    for (int j=0;j<4;j++) acc[i][j] = 0ull;

  float4 a0 = *(const float4*)(Ap);
  float4 a1 = *(const float4*)(Ap + 4);
  float4 w0 = *(const float4*)(Wp);
  float4 w1 = *(const float4*)(Wp + 4);
  for (int k0 = 0; k0 < K; k0 += 16){
    __syncthreads();
    As[ak+0][ar]=a0.x; As[ak+1][ar]=a0.y; As[ak+2][ar]=a0.z; As[ak+3][ar]=a0.w;
    As[ak+4][ar]=a1.x; As[ak+5][ar]=a1.y; As[ak+6][ar]=a1.z; As[ak+7][ar]=a1.w;
    Bs[ak+0][ar]=w0.x; Bs[ak+1][ar]=w0.y; Bs[ak+2][ar]=w0.z; Bs[ak+3][ar]=w0.w;
    Bs[ak+4][ar]=w1.x; Bs[ak+5][ar]=w1.y; Bs[ak+6][ar]=w1.z; Bs[ak+7][ar]=w1.w;
    if (k0 + 16 < K){
      a0 = *(const float4*)(Ap + k0 + 16);
      a1 = *(const float4*)(Ap + k0 + 20);
      w0 = *(const float4*)(Wp + k0 + 16);
      w1 = *(const float4*)(Wp + k0 + 20);
    }
    __syncthreads();
#pragma unroll
    for (int kk=0; kk<16; kk++){
      float4 bf0 = *(const float4*)&Bs[kk][cn];
      float4 bf1 = *(const float4*)&Bs[kk][cn+4];
      float4 af0 = *(const float4*)&As[kk][cm];
      float4 af1 = *(const float4*)&As[kk][cm+4];
      unsigned long long bp0 = pack2(bf0.x, bf0.y);
      unsigned long long bp1 = pack2(bf0.z, bf0.w);
      unsigned long long bp2 = pack2(bf1.x, bf1.y);
      unsigned long long bp3 = pack2(bf1.z, bf1.w);
      float am[8] = {af0.x,af0.y,af0.z,af0.w,af1.x,af1.y,af1.z,af1.w};
#pragma unroll
      for (int i=0;i<8;i++){
        unsigned long long ap = pack2(am[i], am[i]);
        acc[i][0] = fma2(ap, bp0, acc[i][0]);
        acc[i][1] = fma2(ap, bp1, acc[i][1]);
        acc[i][2] = fma2(ap, bp2, acc[i][2]);
        acc[i][3] = fma2(ap, bp3, acc[i][3]);
      }
    }
  }
#pragma unroll
  for (int i=0;i<8;i++){
    float* crow = C + (size_t)(m0+cm+i)*ldc + n0 + cn;
#pragma unroll
    for (int j=0;j<4;j++){
      float2 v = unpack2(acc[i][j]);
      float x0 = v.x*scale, x1 = v.y*scale;
      if (bias){ x0 += bias[n0+cn+2*j]; x1 += bias[n0+cn+2*j+1]; }
      if (act){ x0 = tanhf(x0); x1 = tanhf(x1); }
      *(float2*)(crow + 2*j) = make_float2(x0, x1);
    }
  }
}

// ---------------- small GEMM (decoder h0 init) -------------------------------
__global__ __launch_bounds__(256) void k_gemm_small(
    const float* __restrict__ A, int lda,
    const float* __restrict__ W, int ldw,
    const float* __restrict__ bias,
    float* __restrict__ C, int ldc, int K, int act)
{
  __shared__ __align__(16) float As[16][68];
  __shared__ __align__(16) float Bs[16][36];
  int t = threadIdx.x;
  int n0 = blockIdx.x * 32;
  int ar = t & 63, ak = (t >> 6) << 2;
  int wr = t & 31, wk = ((t & 127) >> 5) << 2;
  const float* Ap = A + (size_t)ar*lda + ak;
  const float* Wp = W + (size_t)(n0 + wr)*ldw + wk;
  int tx = t & 15, ty = t >> 4;
  int cm = ty * 4, cn = tx * 2;
  float acc[4][2] = {{0.f,0.f},{0.f,0.f},{0.f,0.f},{0.f,0.f}};
  for (int k0 = 0; k0 < K; k0 += 16){
    float4 av = *(const float4*)(Ap + k0);
    float4 wv = make_float4(0.f,0.f,0.f,0.f);
    if (t < 128) wv = *(const float4*)(Wp + k0);
    __syncthreads();
    As[ak+0][ar]=av.x; As[ak+1][ar]=av.y; As[ak+2][ar]=av.z; As[ak+3][ar]=av.w;
    if (t < 128){ Bs[wk+0][wr]=wv.x; Bs[wk+1][wr]=wv.y; Bs[wk+2][wr]=wv.z; Bs[wk+3][wr]=wv.w; }
    __syncthreads();
#pragma unroll
    for (int kk=0; kk<16; kk++){
      float4 af = *(const float4*)&As[kk][cm];
      float2 bf = *(const float2*)&Bs[kk][cn];
      acc[0][0] += af.x*bf.x; acc[0][1] += af.x*bf.y;
      acc[1][0] += af.y*bf.x; acc[1][1] += af.y*bf.y;
      acc[2][0] += af.z*bf.x; acc[2][1] += af.z*bf.y;
      acc[3][0] += af.w*bf.x; acc[3][1] += af.w*bf.y;
    }
  }
#pragma unroll
  for (int i=0;i<4;i++)
#pragma unroll
    for (int j=0;j<2;j++){
      float v = acc[i][j];
      if (bias) v += bias[n0+cn+j];
      if (act) v = tanhf(v);
      C[(size_t)(cm+i)*ldc + n0 + cn + j] = v;
    }
}

// ---------------- hf|hb concat -----------------------------------------------
__global__ void k_hfhb(const float* __restrict__ est, float* __restrict__ hfhb){
  int i = blockIdx.x*blockDim.x + threadIdx.x;
  int b = i >> 10, k = i & 1023;
  hfhb[i] = (k < 512) ? est[b*512 + k] : est[(64 + b)*512 + (k - 512)];
}

// ---------------- FUSED encoder scan: single-shot staging, split barriers ----
// 128 blocks = rhalf(2) x jtile(64 of 8 cols). Weights (24x516) + full state
// half (64x516) SMEM-resident; ONE __syncthreads + ONE 64-block barrier/step.
#define ENC_SMEM ((24*516 + 64*516)*4)   // 181632 B
__global__ __launch_bounds__(256) void k_enc_scan(
    const float* __restrict__ xp, const float* __restrict__ uc,
    const float* __restrict__ bn, float* __restrict__ est0,
    float* __restrict__ est1, float* __restrict__ out,
    unsigned* __restrict__ bar)
{
  extern __shared__ __align__(16) float sm[];
  float* Ws = sm;                      // 24 x 516
  float* Es = sm + 24*516;             // 64 x 516
  uint32_t es_a = smem_u32(Es);
  int bx = blockIdx.x, t = threadIdx.x;
  int rhalf = bx >> 6, jt = bx & 63, j0 = jt << 3;
  unsigned* cnt = bar + rhalf;
  for (int idx = t; idx < 24*512; idx += 256){
    int row = idx >> 9, k = idx & 511;
    int g = row >> 3, jj = row & 7;
    Ws[row*516 + k] = uc[(size_t)(g*512 + j0 + jj)*512 + k];
  }
  // each half zeroes its own half of est0 (64 blocks x 256 thr x 2)
  {
    int base = rhalf*64*512;
    for (int i = (bx & 63)*256 + t; i < 32768; i += 64*256)
      est0[base + i] = 0.f;
  }
  unsigned nb = 64; gbar(cnt, nb);

  int rloc = t >> 2, jg = t & 3;
  int r = rhalf*64 + rloc;
  int jA = j0 + jg, jB = j0 + jg + 4;
  float bnA = bn[jA], bnB = bn[jB];
  int fwd = (rhalf == 0);
  const float* wrA = Ws + jg*516;
  const float* wzA = Ws + (8 + jg)*516;
  const float* wnA = Ws + (16 + jg)*516;
  const float* wrB = wrA + 4*516;
  const float* wzB = wzA + 4*516;
  const float* wnB = wnA + 4*516;

  for (int step = 0; step < 48; step++){
    const float* S = (step & 1) ? est1 : est0;
    float*       D = (step & 1) ? est0 : est1;
    const float* Srow = S + (size_t)rhalf*64*512;
    // single-shot stage: 64x512 -> SMEM (32 cp.async per thread)
#pragma unroll
    for (int q = 0; q < 32; q++){
      int lin = q*256 + t;
      int row = lin >> 7, kc = (lin & 127) << 2;
      cpasync16(es_a + (uint32_t)((row*516 + kc)*4), Srow + (size_t)row*512 + kc);
    }
    asm volatile("cp.async.commit_group;");
    asm volatile("cp.async.wait_group 0;" ::: "memory");
    __syncthreads();
    unsigned long long arA=0,azA=0,anA=0,arB=0,azB=0,anB=0;
    const float* ep = Es + rloc*516;
#pragma unroll 8
    for (int kk = 0; kk < 512; kk += 4){
      ulonglong2 ev = *(const ulonglong2*)(ep + kk);
      ulonglong2 w;
      w = *(const ulonglong2*)(wrA + kk); arA = fma2(ev.x, w.x, arA); arA = fma2(ev.y, w.y, arA);
      w = *(const ulonglong2*)(wzA + kk); azA = fma2(ev.x, w.x, azA); azA = fma2(ev.y, w.y, azA);
      w = *(const ulonglong2*)(wnA + kk); anA = fma2(ev.x, w.x, anA); anA = fma2(ev.y, w.y, anA);
      w = *(const ulonglong2*)(wrB + kk); arB = fma2(ev.x, w.x, arB); arB = fma2(ev.y, w.y, arB);
      w = *(const ulonglong2*)(wzB + kk); azB = fma2(ev.x, w.x, azB); azB = fma2(ev.y, w.y, azB);
      w = *(const ulonglong2*)(wnB + kk); anB = fma2(ev.x, w.x, anB); anB = fma2(ev.y, w.y, anB);
    }
    int tpos = fwd ? step : 47 - step;
    int b = rloc;
    const float* x = xp + ((size_t)tpos*64 + b)*1536;
    float hA = Es[rloc*516 + jA];
    float hB = Es[rloc*516 + jB];
    float hnA = gru1(x[jA], x[512+jA], x[1024+jA],
                     hadd2(arA), hadd2(azA), hadd2(anA), bnA, hA);
    float hnB = gru1(x[jB], x[512+jB], x[1024+jB],
                     hadd2(arB), hadd2(azB), hadd2(anB), bnB, hB);
    D[(size_t)r*512 + jA] = hnA;
    D[(size_t)r*512 + jB] = hnB;
    size_t ob = ((size_t)tpos*64 + b)*1024 + (fwd ? 0 : 512);
    out[ob + jA] = hnA;
    out[ob + jB] = hnB;
    if (step < 47){ nb += 64; gbar(cnt, nb); }
  }
}

// ---------------- persistent decoder scan (unchanged) ------------------------
__global__ __launch_bounds__(256) void k_dec_scan(
    const float* __restrict__ xpx, const float* __restrict__ dw,
    const float* __restrict__ bn, float* __restrict__ dst,
    const float* __restrict__ hw, const float* __restrict__ henc,
    const int* __restrict__ src, const float* __restrict__ acw,
    float* __restrict__ hts, unsigned* __restrict__ bar)
{
  __shared__ __align__(16) float As[16][68];
  __shared__ __align__(16) float Bs[16][36];
  __shared__ __align__(16) float hsm[512];
  __shared__ float ssm[48];
  __shared__ float sinv;
  int bx = blockIdx.x, t = threadIdx.x;
  unsigned nb = 0;
  float* G = g_G; float* cc = g_cc; float* cp = g_cp;
  for (int i = bx*256 + t; i < 32768; i += NBLK*256) dst[i] = 0.f;
  nb += NBLK; gbar(bar, nb);
  int gA = bx & 1, nA = (bx >> 1) * 32;
  int ksC = bx / 16, nC = (bx & 15) * 32;
  for (int step = 0; step < 48; step++){
    tile64x32(As, Bs, dst, 512, gA*64, dw, 512, gA*1536 + nA, 0, 512,
              G, 1536, gA*64, nA);
    nb += NBLK; gbar(bar, nb);
    if (bx < 64){
      int b = bx;
      const float* xrow = xpx + ((size_t)step*64 + b)*1536;
      const float* g0 = G + (size_t)b*1536;
      const float* g1 = G + (size_t)(64 + b)*1536;
      if (t < 128){
        int j4 = t << 2;
        float4 xr = *(const float4*)(xrow + j4);
        float4 xz = *(const float4*)(xrow + 512 + j4);
        float4 xn = *(const float4*)(xrow + 1024 + j4);
        float4 ar0 = *(const float4*)(g0 + j4);
        float4 az0 = *(const float4*)(g0 + 512 + j4);
        float4 an0 = *(const float4*)(g0 + 1024 + j4);
        float4 ar1 = *(const float4*)(g1 + j4);
        float4 az1 = *(const float4*)(g1 + 512 + j4);
        float4 an1 = *(const float4*)(g1 + 1024 + j4);
        float4 bnv = *(const float4*)(bn + j4);
        float4 h   = *(const float4*)(dst + (size_t)(64 + b)*512 + j4);
        float4 hn;
        hn.x = gru1(xr.x+ar0.x, xz.x+az0.x, xn.x+an0.x, ar1.x, az1.x, an1.x, bnv.x, h.x);
        hn.y = gru1(xr.y+ar0.y, xz.y+az0.y, xn.y+an0.y, ar1.y, az1.y, an1.y, bnv.y, h.y);
        hn.z = gru1(xr.z+ar0.z, xz.z+az0.z, xn.z+an0.z, ar1.z, az1.z, an1.z, bnv.z, h.z);
        hn.w = gru1(xr.w+ar0.w, xz.w+az0.w, xn.w+an0.w, ar1.w, az1.w, an1.w, bnv.w, h.w);
        *(float4*)(dst + (size_t)(64 + b)*512 + j4) = hn;
        *(float4*)&hsm[j4] = hn;
        *(float4*)(cc + (size_t)b*1536 + j4) = hn;
      }
      __syncthreads();
      int w = t >> 5, lane = t & 31;
      for (int tp = w; tp < 48; tp += 8){
        const float* hwrow = hw + ((size_t)tp*64 + b)*512;
        float s = 0.f;
#pragma unroll
        for (int j = lane*4; j < 512; j += 128){
          float4 a = *(const float4*)&hsm[j];
          float4 q = *(const float4*)(hwrow + j);
          s += a.x*q.x + a.y*q.y + a.z*q.z + a.w*q.w;
        }
#pragma unroll
        for (int o = 16; o; o >>= 1) s += __shfl_xor_sync(0xffffffffu, s, o);
        if (lane == 0) ssm[tp] = (src[tp*64 + b] == 0) ? -1e9f : s;
      }
      __syncthreads();
      if (t == 0){
        float mx = -1e30f;
        for (int i2 = 0; i2 < 48; i2++) mx = fmaxf(mx, ssm[i2]);
        float sum = 0.f;
        for (int i2 = 0; i2 < 48; i2++){ float e = __expf(ssm[i2]-mx); ssm[i2]=e; sum+=e; }
        sinv = 1.f/sum;
      }
      __syncthreads();
      {
        int d4 = t << 2;
        float4 a4 = make_float4(0.f,0.f,0.f,0.f);
#pragma unroll 4
        for (int tp = 0; tp < 48; tp++){
          float e = ssm[tp];
          float4 hv = *(const float4*)(henc + ((size_t)tp*64 + b)*1024 + d4);
          a4.x += e*hv.x; a4.y += e*hv.y; a4.z += e*hv.z; a4.w += e*hv.w;
        }
        float si = sinv;
        *(float4*)(cc + (size_t)b*1536 + 512 + d4) =
            make_float4(a4.x*si, a4.y*si, a4.z*si, a4.w*si);
      }
    }
    nb += NBLK; gbar(bar, nb);
    tile64x32(As, Bs, cc, 1536, 0, acw, 1536, nC, ksC*256, 256,
              cp + (size_t)ksC*32768, 512, 0, nC);
    nb += NBLK; gbar(bar, nb);
    {
      int w = bx*256 + t;
      if (w < 8192){
        int i4 = w << 2;
        float4 v0 = *(const float4*)(cp + i4);
        float4 v1 = *(const float4*)(cp + 32768 + i4);
        float4 v2 = *(const float4*)(cp + 2*32768 + i4);
        float4 v3 = *(const float4*)(cp + 3*32768 + i4);
        float4 v4 = *(const float4*)(cp + 4*32768 + i4);
        float4 v5 = *(const float4*)(cp + 5*32768 + i4);
        float4 r;
        r.x = tanhf(v0.x+v1.x+v2.x+v3.x+v4.x+v5.x);
        r.y = tanhf(v0.y+v1.y+v2.y+v3.y+v4.y+v5.y);
        r.z = tanhf(v0.z+v1.z+v2.z+v3.z+v4.z+v5.z);
        r.w = tanhf(v0.w+v1.w+v2.w+v3.w+v4.w+v5.w);
        *(float4*)(dst + i4) = r;
        *(float4*)(hts + (size_t)step*32768 + i4) = r;
      }
    }
    if (step < 47){ nb += NBLK; gbar(bar, nb); }
  }
}

// ---------------- logits: mma.sync bf16-split GEMM ---------------------------
#define LG_PAD 72
#define LG_TILE_B (128*LG_PAD*2)
#define LG_SMEM_TOTAL (4*LG_TILE_B)

__device__ __forceinline__ void ldsm4(uint32_t* r, uint32_t addr){
  asm volatile("ldmatrix.sync.aligned.m8n8.x4.shared.b16 {%0,%1,%2,%3}, [%4];"
               : "=r"(r[0]), "=r"(r[1]), "=r"(r[2]), "=r"(r[3]) : "r"(addr));
}
__device__ __forceinline__ void mma16816(float* d, const uint32_t* a,
                                         uint32_t b0, uint32_t b1){
  asm volatile("mma.sync.aligned.m16n8k16.row.col.f32.bf16.bf16.f32 "
               "{%0,%1,%2,%3}, {%4,%5,%6,%7}, {%8,%9}, {%0,%1,%2,%3};"
               : "+f"(d[0]), "+f"(d[1]), "+f"(d[2]), "+f"(d[3])
               : "r"(a[0]), "r"(a[1]), "r"(a[2]), "r"(a[3]), "r"(b0), "r"(b1));
}

__global__ __launch_bounds__(256) void k_logits_mma(
    const __nv_bfloat16* __restrict__ A, const __nv_bfloat16* __restrict__ B,
    float* __restrict__ C)
{
  extern __shared__ __align__(16) char smem[];
  uint32_t sb = smem_u32(smem);
  uint32_t sA[2] = { sb,                sb + 2*LG_TILE_B };
  uint32_t sBs[2]= { sb + LG_TILE_B,    sb + 3*LG_TILE_B };
  int t = threadIdx.x, lane = t & 31, wid = t >> 5;
  int m0 = blockIdx.y * 128, n0 = blockIdx.x * 128;
  int wm = (wid & 3) * 32, wn = (wid >> 2) * 64;

  int lrow = t >> 3, lc8 = (t & 7) * 8;
  const __nv_bfloat16* Ap = A + (size_t)(m0 + lrow)*1536 + lc8;
  const __nv_bfloat16* Bp = B + (size_t)(n0 + lrow)*1536 + lc8;
  uint32_t sAo = (uint32_t)((lrow*LG_PAD + lc8)*2);
  uint32_t sBo = sAo;

  float acc[2][8][4];
#pragma unroll
  for (int i=0;i<2;i++)
#pragma unroll
    for (int j=0;j<8;j++)
#pragma unroll
      for (int k=0;k<4;k++) acc[i][j][k] = 0.f;

  int lrow16 = lane & 15;
  int lcolk8 = (lane >> 4) << 3;

#pragma unroll
  for (int p = 0; p < 4; p++){
    cpasync16(sA[0] + sAo + (uint32_t)(p*32*LG_PAD*2), Ap + (size_t)p*32*1536);
    cpasync16(sBs[0]+ sBo + (uint32_t)(p*32*LG_PAD*2), Bp + (size_t)p*32*1536);
  }
  asm volatile("cp.async.commit_group;");

  for (int c = 0; c < 24; c++){
    int buf = c & 1;
    if (c < 23){
      int kc = (c + 1) * 64;
#pragma unroll
      for (int p = 0; p < 4; p++){
        cpasync16(sA[buf^1] + sAo + (uint32_t)(p*32*LG_PAD*2),
                  Ap + (size_t)p*32*1536 + kc);
        cpasync16(sBs[buf^1]+ sBo + (uint32_t)(p*32*LG_PAD*2),
                  Bp + (size_t)p*32*1536 + kc);
      }
      asm volatile("cp.async.commit_group;");
      asm volatile("cp.async.wait_group 1;");
    } else {
      asm volatile("cp.async.wait_group 0;");
    }
    __syncthreads();
#pragma unroll
    for (int kk = 0; kk < 4; kk++){
      int col = kk*16 + lcolk8;
      uint32_t af[2][4], bfr[4][4];
#pragma unroll
      for (int mi = 0; mi < 2; mi++){
        uint32_t addr = sA[buf] + (uint32_t)(((wm + mi*16 + lrow16)*LG_PAD + col)*2);
        ldsm4(af[mi], addr);
      }
#pragma unroll
      for (int nj = 0; nj < 4; nj++){
        uint32_t addr = sBs[buf] + (uint32_t)(((wn + nj*16 + lrow16)*LG_PAD + col)*2);
        ldsm4(bfr[nj], addr);
      }
#pragma unroll
      for (int mi = 0; mi < 2; mi++)
#pragma unroll
        for (int n8 = 0; n8 < 8; n8++){
          int nj = n8 >> 1, sel = n8 & 1;
          mma16816(acc[mi][n8], af[mi], bfr[nj][sel], bfr[nj][sel + 2]);
        }
    }
    __syncthreads();
  }

  int r4 = lane >> 2, c2 = (lane & 3) * 2;
#pragma unroll
  for (int mi = 0; mi < 2; mi++){
#pragma unroll
    for (int n8 = 0; n8 < 8; n8++){
      int row = m0 + wm + mi*16 + r4;
      int col = n0 + wn + n8*8 + c2;
      *(float2*)(C + (size_t)row*32000 + col) =
          make_float2(acc[mi][n8][0], acc[mi][n8][1]);
      *(float2*)(C + (size_t)(row + 8)*32000 + col) =
          make_float2(acc[mi][n8][2], acc[mi][n8][3]);
    }
  }
}

// =============================================================================
extern "C" void kernel_launch(void* const* d_in, const int* in_sizes, int n_in,
                              void* d_out, int out_size){
  const int*   src  = (const int*)  d_in[0];
  const int*   tgt  = (const int*)  d_in[1];
  const float* emb  = (const float*)d_in[2];
  const float* e0Wih=(const float*)d_in[3];  const float* e0bih=(const float*)d_in[4];
  const float* e0Ur =(const float*)d_in[5];  const float* e0Uz =(const float*)d_in[6];
  const float* e0Un =(const float*)d_in[7];  const float* e0bn =(const float*)d_in[8];
  const float* e1Wih=(const float*)d_in[9];  const float* e1bih=(const float*)d_in[10];
  const float* e1Ur =(const float*)d_in[11]; const float* e1Uz =(const float*)d_in[12];
  const float* e1Un =(const float*)d_in[13]; const float* e1bn =(const float*)d_in[14];
  const float* fcw  =(const float*)d_in[15]; const float* fcb  =(const float*)d_in[16];
  const float* Wa   =(const float*)d_in[17]; const float* acw  =(const float*)d_in[18];
  const float* dWih =(const float*)d_in[19]; const float* dbih =(const float*)d_in[20];
  const float* dUr  =(const float*)d_in[21]; const float* dUz  =(const float*)d_in[22];
  const float* dUn  =(const float*)d_in[23]; const float* dbn  =(const float*)d_in[24];
  const float* outw =(const float*)d_in[25];
  float* out = (float*)d_out;

  float *se,*te,*xp0,*l0,*xp1,*henc,*hw,*xpx,*hts,*uc0,*uc1,*dw,*wat,*est,*est2,*dst,*hfhb;
  unsigned* bc; __nv_bfloat16 *aw,*bw;
  cudaGetSymbolAddress((void**)&se,  g_src_emb);
  cudaGetSymbolAddress((void**)&te,  g_tgt_emb);
  cudaGetSymbolAddress((void**)&xp0, g_xp0);
  cudaGetSymbolAddress((void**)&l0,  g_l0);
  cudaGetSymbolAddress((void**)&xp1, g_xp1);
  cudaGetSymbolAddress((void**)&henc,g_henc);
  cudaGetSymbolAddress((void**)&hw,  g_hw);
  cudaGetSymbolAddress((void**)&xpx, g_xpx);
  cudaGetSymbolAddress((void**)&hts, g_hts);
  cudaGetSymbolAddress((void**)&uc0, g_uc0);
  cudaGetSymbolAddress((void**)&uc1, g_uc1);
  cudaGetSymbolAddress((void**)&dw,  g_dw);
  cudaGetSymbolAddress((void**)&wat, g_wat);
  cudaGetSymbolAddress((void**)&est, g_est);
  cudaGetSymbolAddress((void**)&est2,g_est2);
  cudaGetSymbolAddress((void**)&dst, g_dst);
  cudaGetSymbolAddress((void**)&hfhb,g_hfhb);
  cudaGetSymbolAddress((void**)&bc,  g_barc);
  cudaGetSymbolAddress((void**)&aw,  g_aw);
  cudaGetSymbolAddress((void**)&bw,  g_bw);

  cudaFuncSetAttribute(k_logits_mma, cudaFuncAttributeMaxDynamicSharedMemorySize,
                       LG_SMEM_TOTAL);
  cudaFuncSetAttribute(k_enc_scan, cudaFuncAttributeMaxDynamicSharedMemorySize,
                       ENC_SMEM);

  // launch order keeps enc1 at ncu slot -s 5
  k_gather<<<2*NTB, 128>>>(src, tgt, emb, se, te);
  k_prep<<<1792, 256>>>(e0Ur,e0Uz,e0Un, e1Ur,e1Uz,e1Un, dUr,dUz,dUn, dWih, Wa,
                        uc0, uc1, dw, wat);
  k_gemm_big<<<dim3(12,24), 256>>>(se, 512, e0Wih, 512, e0bih, xp0, 1536, 512, 1.f, 0);
  k_enc_scan<<<NBE, 256, ENC_SMEM>>>(xp0, uc0, e0bn, est, est2, l0, bc + 0);
  k_gemm_big<<<dim3(12,24), 256>>>(l0, 1024, e1Wih, 1024, e1bih, xp1, 1536, 1024, 1.f, 0);
  k_enc_scan<<<NBE, 256, ENC_SMEM>>>(xp1, uc1, e1bn, est, est2, henc, bc + 2);

  k_wsplit<<<64000, 256>>>(outw, bw);

  k_hfhb<<<256, 256>>>(est, hfhb);
  k_gemm_small<<<16, 256>>>(hfhb, 1024, fcw, 1024, fcb, dst + 64*512, 512, 1024, 1);

  k_gemm_big<<<dim3(4,24), 256>>>(henc, 1024, wat, 1024, (const float*)nullptr,
                                  hw, 512, 1024, 0.03125f, 0);
  k_gemm_big<<<dim3(12,24), 256>>>(te, 512, dWih, 1024, dbih, xpx, 1536, 512, 1.f, 0);

  k_dec_scan<<<NBLK, 256>>>(xpx, dw, dbn, dst, hw, henc, src, acw, hts, bc + 4);

  k_asplit<<<6144, 256>>>(hts, aw);
  k_logits_mma<<<dim3(250, 24), 256, LG_SMEM_TOTAL>>>(aw, bw, out);
}